// round 11
// baseline (speedup 1.0000x reference)
#include <cuda_runtime.h>
#include <cuda_bf16.h>
#include <math.h>
#include <stdint.h>

#define B_  2
#define S_  2048
#define D_  2048
#define H_  16
#define HD_ 128
#define M_  (B_*S_)   // 4096 rows

// ---------------- scratch (static device globals; allocation-free) ----------
__device__ __align__(128) float g_qkv[(size_t)M_*3*D_];   // [M][6144] q|k|v
__device__ __align__(128) float g_x2 [(size_t)M_*D_];
__device__ __align__(128) float g_r  [(size_t)M_*D_];
__device__ __align__(128) float g_h2 [(size_t)M_*D_];
__device__ __align__(128) float g_h3 [(size_t)M_*D_];
__device__ __align__(128) float g_pers[D_];

// bf16 hi/lo activation scratch
__device__ __align__(128) __nv_bfloat16 g_ah[(size_t)M_*D_];
__device__ __align__(128) __nv_bfloat16 g_al[(size_t)M_*D_];
__device__ __align__(128) __nv_bfloat16 g_th[(size_t)M_*4*D_];
__device__ __align__(128) __nv_bfloat16 g_tl[(size_t)M_*4*D_];

// attention scratch (bf16 splits only)
__device__ __align__(128) __nv_bfloat16 g_qsh[(size_t)M_*D_];
__device__ __align__(128) __nv_bfloat16 g_qsl[(size_t)M_*D_];
__device__ __align__(128) __nv_bfloat16 g_ksh[(size_t)M_*D_];
__device__ __align__(128) __nv_bfloat16 g_ksl[(size_t)M_*D_];
__device__ __align__(128) __nv_bfloat16 g_vth[(size_t)32*HD_*S_];   // [bh][128][2048]
__device__ __align__(128) __nv_bfloat16 g_vtl[(size_t)32*HD_*S_];

// bf16 hi/lo transposed weights, packed offsets into one pool: [N,K] row-major
#define OWQ  ((size_t)0)
#define OWK  ((size_t)4194304)
#define OWV  ((size_t)8388608)
#define OWO  ((size_t)12582912)
#define ORW1 ((size_t)16777216)
#define ORW2 ((size_t)25165824)
#define ODW  ((size_t)33554432)
#define OMW1 ((size_t)37748736)
#define OMW2 ((size_t)54525952)
#define WTOT ((size_t)71303168)
__device__ __align__(128) __nv_bfloat16 g_wh[WTOT];
__device__ __align__(128) __nv_bfloat16 g_wl[WTOT];

// ---------------- helpers ----------------------------------------------------
__device__ __forceinline__ void split2(float v, __nv_bfloat16& h, __nv_bfloat16& l) {
    h = __float2bfloat16(v);
    l = __float2bfloat16(v - __bfloat162float(h));
}
__device__ __forceinline__ uint32_t smem_u32(const void* p) {
    uint32_t a;
    asm("{ .reg .u64 t; cvta.to.shared.u64 t, %1; cvt.u32.u64 %0, t; }" : "=r"(a) : "l"(p));
    return a;
}
__device__ __forceinline__ uint32_t packbf2(float a, float b) {
    __nv_bfloat162 p;
    p.x = __float2bfloat16(a); p.y = __float2bfloat16(b);
    return *(uint32_t*)&p;
}

#define MMA16816(d, a, b) \
    asm volatile("mma.sync.aligned.m16n8k16.row.col.f32.bf16.bf16.f32 " \
        "{%0,%1,%2,%3}, {%4,%5,%6,%7}, {%8,%9}, {%0,%1,%2,%3};" \
        : "+f"((d)[0]), "+f"((d)[1]), "+f"((d)[2]), "+f"((d)[3]) \
        : "r"((a)[0]), "r"((a)[1]), "r"((a)[2]), "r"((a)[3]), "r"((b)[0]), "r"((b)[1]))

#define LDMX4(d, addr) \
    asm volatile("ldmatrix.sync.aligned.m8n8.x4.shared.b16 {%0,%1,%2,%3}, [%4];" \
        : "=r"((d)[0]), "=r"((d)[1]), "=r"((d)[2]), "=r"((d)[3]) : "r"(addr))

__device__ __forceinline__ void cp16(uint32_t dst, const void* src) {
    asm volatile("cp.async.cg.shared.global [%0], [%1], 16;" :: "r"(dst), "l"(src));
}
#define CP_COMMIT() asm volatile("cp.async.commit_group;" ::: "memory")
#define CP_WAIT1()  asm volatile("cp.async.wait_group 1;" ::: "memory")

__device__ __forceinline__ float gelu1(float v) {
    return 0.5f * v * (1.0f + erff(v * 0.70710678118654752f));
}

// ================= HMMA GEMM: 128x128 tile, KC=64, 3-buf / dist-2 pipeline ===
// Inner loop restructured pass-major: 16 INDEPENDENT MMAs per pass (hh|hl|lh)
// so no back-to-back RAW chains on the same accumulator.
#define LDE 72
#define MAT_E (128*LDE)
#define STAGE_B (4*MAT_E*2)
#define TG_SMEM (3*STAGE_B)            // 221184 bytes

template<bool GELU, bool BIAS, bool RES, bool OUT_BF16>
__global__ __launch_bounds__(256)
void tbgemm(const __nv_bfloat16* __restrict__ Ah, const __nv_bfloat16* __restrict__ Al,
            const __nv_bfloat16* __restrict__ Bh, const __nv_bfloat16* __restrict__ Bl,
            const float* __restrict__ bias, const float* __restrict__ res,
            float* __restrict__ Cf, __nv_bfloat16* __restrict__ Ch, __nv_bfloat16* __restrict__ Cl,
            int M, int N, int K)
{
    extern __shared__ __nv_bfloat16 sm[];
    const int tid  = threadIdx.x;
    const int lane = tid & 31;
    const int warp = tid >> 5;
    const int wm = warp & 3;
    const int wn = warp >> 2;
    const int m0 = blockIdx.y * 128;
    const int n0 = blockIdx.x * 128;
    const int g  = lane >> 2;
    const int t  = lane & 3;
    const uint32_t sbase = smem_u32(sm);
    const int jq = lane >> 3;
    const int jr = lane & 7;

    float acc[2][8][4];
    #pragma unroll
    for (int m = 0; m < 2; m++)
        #pragma unroll
        for (int n = 0; n < 8; n++)
            #pragma unroll
            for (int e = 0; e < 4; e++) acc[m][n][e] = 0.f;

    auto issue = [&](int c, int buf) {
        const int k0 = c << 6;
        const uint32_t b0 = sbase + (uint32_t)buf * STAGE_B;
        #pragma unroll
        for (int i = 0; i < 4; i++) {
            int v = i * 256 + tid;
            int r = v >> 3, q = v & 7;
            uint32_t so = (uint32_t)(r * LDE + q * 8) * 2;
            size_t ga = (size_t)(m0 + r) * K + k0 + q * 8;
            size_t gb = (size_t)(n0 + r) * K + k0 + q * 8;
            cp16(b0 + so,               Ah + ga);
            cp16(b0 + MAT_E*2 + so,     Al + ga);
            cp16(b0 + 2*MAT_E*2 + so,   Bh + gb);
            cp16(b0 + 3*MAT_E*2 + so,   Bl + gb);
        }
        CP_COMMIT();
    };

    const int nc = K >> 6;
    issue(0, 0);
    if (nc > 1) issue(1, 1); else CP_COMMIT();

    int buf = 0;
    for (int c = 0; c < nc; c++) {
        CP_WAIT1();
        __syncthreads();
        if (c + 2 < nc) {
            int nb = buf + 2; if (nb >= 3) nb -= 3;
            issue(c + 2, nb);
        } else {
            CP_COMMIT();
        }

        const uint32_t A_h = sbase + (uint32_t)buf * STAGE_B;
        const uint32_t A_l = A_h + MAT_E*2;
        const uint32_t B_h = A_h + 2*MAT_E*2;
        const uint32_t B_l = A_h + 3*MAT_E*2;

        #pragma unroll
        for (int kk = 0; kk < 64; kk += 16) {
            // ---- load all fragments for this k-step ----
            uint32_t ah[2][4], al[2][4];
            #pragma unroll
            for (int m = 0; m < 2; m++) {
                int row = wm * 32 + m * 16 + (jq & 1) * 8 + jr;
                uint32_t off = (uint32_t)(row * LDE + kk + (jq >> 1) * 8) * 2;
                LDMX4(ah[m], A_h + off);
                LDMX4(al[m], A_l + off);
            }
            uint32_t bh[4][4], bl[4][4];
            #pragma unroll
            for (int np = 0; np < 4; np++) {
                int nrow = wn * 64 + np * 16 + (jq >> 1) * 8 + jr;
                uint32_t boff = (uint32_t)(nrow * LDE + kk + (jq & 1) * 8) * 2;
                LDMX4(bh[np], B_h + boff);
                LDMX4(bl[np], B_l + boff);
            }
            // ---- pass 1: hh (16 independent MMAs) ----
            #pragma unroll
            for (int np = 0; np < 4; np++)
                #pragma unroll
                for (int m = 0; m < 2; m++) {
                    MMA16816(acc[m][2*np],   ah[m], &bh[np][0]);
                    MMA16816(acc[m][2*np+1], ah[m], &bh[np][2]);
                }
            // ---- pass 2: hl ----
            #pragma unroll
            for (int np = 0; np < 4; np++)
                #pragma unroll
                for (int m = 0; m < 2; m++) {
                    MMA16816(acc[m][2*np],   ah[m], &bl[np][0]);
                    MMA16816(acc[m][2*np+1], ah[m], &bl[np][2]);
                }
            // ---- pass 3: lh ----
            #pragma unroll
            for (int np = 0; np < 4; np++)
                #pragma unroll
                for (int m = 0; m < 2; m++) {
                    MMA16816(acc[m][2*np],   al[m], &bh[np][0]);
                    MMA16816(acc[m][2*np+1], al[m], &bh[np][2]);
                }
        }
        buf = buf + 1; if (buf >= 3) buf = 0;
    }

    #pragma unroll
    for (int m = 0; m < 2; m++) {
        #pragma unroll
        for (int n = 0; n < 8; n++) {
            int col = n0 + wn * 64 + n * 8 + t * 2;
            #pragma unroll
            for (int half = 0; half < 2; half++) {
                int row = m0 + wm * 32 + m * 16 + g + half * 8;
                float v0 = acc[m][n][half * 2 + 0];
                float v1 = acc[m][n][half * 2 + 1];
                if (BIAS) { v0 += bias[col]; v1 += bias[col + 1]; }
                if (GELU) { v0 = gelu1(v0); v1 = gelu1(v1); }
                size_t off = (size_t)row * N + col;
                if (RES) {
                    float2 r2 = *(const float2*)&res[off];
                    v0 += r2.x; v1 += r2.y;
                }
                if (OUT_BF16) {
                    __nv_bfloat16 h0, l0, h1, l1;
                    split2(v0, h0, l0); split2(v1, h1, l1);
                    __nv_bfloat162 hp, lp;
                    hp.x = h0; hp.y = h1; lp.x = l0; lp.y = l1;
                    *(__nv_bfloat162*)&Ch[off] = hp;
                    *(__nv_bfloat162*)&Cl[off] = lp;
                } else {
                    *(float2*)&Cf[off] = make_float2(v0, v1);
                }
            }
        }
    }
}

// ================= fused HMMA flash attention (unchanged from R10) ===========
#define LQ 136
#define LV 72
#define FQH 0
#define FQL (128*LQ)
#define FST0 (2*128*LQ)
#define FKH 0
#define FKL (64*LQ)
#define FVH (2*64*LQ)
#define FVL (FVH + 128*LV)
#define FSTG (FVL + 128*LV)
#define FA_SMEM ((FST0 + 2*FSTG)*2)    // 212992 bytes

__global__ __launch_bounds__(256)
void flash_attn(const __nv_bfloat16* __restrict__ Qh, const __nv_bfloat16* __restrict__ Ql,
                const __nv_bfloat16* __restrict__ Kh, const __nv_bfloat16* __restrict__ Kl,
                const __nv_bfloat16* __restrict__ Vth, const __nv_bfloat16* __restrict__ Vtl,
                const int* __restrict__ mask,
                __nv_bfloat16* __restrict__ Oh, __nv_bfloat16* __restrict__ Ol)
{
    extern __shared__ __nv_bfloat16 fsm[];
    const int tid  = threadIdx.x;
    const int lane = tid & 31;
    const int warp = tid >> 5;
    const int g  = lane >> 2;
    const int t  = lane & 3;
    const int jq = lane >> 3;
    const int jr = lane & 7;
    const uint32_t sb = smem_u32(fsm);
    const int z = blockIdx.y, b = z >> 4, h = z & 15;
    const int q0 = blockIdx.x * 128;
    const size_t qrow0 = (size_t)b * 2048 + q0;

    {
        #pragma unroll
        for (int i = 0; i < 8; i++) {
            int v = i * 256 + tid;
            int r = v >> 4, q = v & 15;
            uint32_t so = (uint32_t)(r * LQ + q * 8) * 2;
            size_t gq = (qrow0 + r) * 2048 + h * 128 + q * 8;
            cp16(sb + (FQH)*2 + so, Qh + gq);
            cp16(sb + (FQL)*2 + so, Ql + gq);
        }
        CP_COMMIT();
    }

    auto issue_kv = [&](int kt, int s) {
        const uint32_t b0 = sb + (uint32_t)(FST0 + s * FSTG) * 2;
        #pragma unroll
        for (int i = 0; i < 4; i++) {
            int v = i * 256 + tid;
            int r = v >> 4, q = v & 15;
            uint32_t so = (uint32_t)(r * LQ + q * 8) * 2;
            size_t gk = ((size_t)b * 2048 + kt * 64 + r) * 2048 + h * 128 + q * 8;
            cp16(b0 + (FKH)*2 + so, Kh + gk);
            cp16(b0 + (FKL)*2 + so, Kl + gk);
        }
        #pragma unroll
        for (int i = 0; i < 4; i++) {
            int v = i * 256 + tid;
            int d = v >> 3, q = v & 7;
            uint32_t so = (uint32_t)(d * LV + q * 8) * 2;
            size_t gv = ((size_t)z * 128 + d) * 2048 + kt * 64 + q * 8;
            cp16(b0 + (FVH)*2 + so, Vth + gv);
            cp16(b0 + (FVL)*2 + so, Vtl + gv);
        }
        CP_COMMIT();
    };

    issue_kv(0, 0);
    issue_kv(1, 1);

    const int q0w = warp * 16;
    float accO[16][4];
    #pragma unroll
    for (int n = 0; n < 16; n++)
        #pragma unroll
        for (int e = 0; e < 4; e++) accO[n][e] = 0.f;
    float m0v = -1e30f, m1v = -1e30f, l0v = 0.f, l1v = 0.f;

    for (int kt = 0; kt < 32; kt++) {
        CP_WAIT1();
        __syncthreads();
        const int s = kt & 1;
        const uint32_t K_h = sb + (uint32_t)(FST0 + s * FSTG + FKH) * 2;
        const uint32_t K_l = sb + (uint32_t)(FST0 + s * FSTG + FKL) * 2;
        const uint32_t V_h = sb + (uint32_t)(FST0 + s * FSTG + FVH) * 2;
        const uint32_t V_l = sb + (uint32_t)(FST0 + s * FSTG + FVL) * 2;

        float sc[8][4];
        #pragma unroll
        for (int n = 0; n < 8; n++)
            #pragma unroll
            for (int e = 0; e < 4; e++) sc[n][e] = 0.f;
        #pragma unroll
        for (int kc = 0; kc < 8; kc++) {
            int arow = q0w + (jq & 1) * 8 + jr;
            uint32_t aoff = (uint32_t)(arow * LQ + kc * 16 + (jq >> 1) * 8) * 2;
            uint32_t qh_[4], ql_[4];
            LDMX4(qh_, sb + FQH*2 + aoff);
            LDMX4(ql_, sb + FQL*2 + aoff);
            #pragma unroll
            for (int ng = 0; ng < 4; ng++) {
                int krow = ng * 16 + (jq >> 1) * 8 + jr;
                uint32_t boff = (uint32_t)(krow * LQ + kc * 16 + (jq & 1) * 8) * 2;
                uint32_t kh_[4], kl_[4];
                LDMX4(kh_, K_h + boff);
                LDMX4(kl_, K_l + boff);
                MMA16816(sc[2*ng],   qh_, &kh_[0]);
                MMA16816(sc[2*ng],   qh_, &kl_[0]);
                MMA16816(sc[2*ng],   ql_, &kh_[0]);
                MMA16816(sc[2*ng+1], qh_, &kh_[2]);
                MMA16816(sc[2*ng+1], qh_, &kl_[2]);
                MMA16816(sc[2*ng+1], ql_, &kh_[2]);
            }
        }

        const int kb = b * 2048 + kt * 64;
        #pragma unroll
        for (int j = 0; j < 8; j++) {
            if (mask[kb + 8*j + 2*t]     == 0) { sc[j][0] = -1e30f; sc[j][2] = -1e30f; }
            if (mask[kb + 8*j + 2*t + 1] == 0) { sc[j][1] = -1e30f; sc[j][3] = -1e30f; }
        }
        float rm0 = -1e30f, rm1 = -1e30f;
        #pragma unroll
        for (int j = 0; j < 8; j++) {
            rm0 = fmaxf(rm0, fmaxf(sc[j][0], sc[j][1]));
            rm1 = fmaxf(rm1, fmaxf(sc[j][2], sc[j][3]));
        }
        rm0 = fmaxf(rm0, __shfl_xor_sync(0xffffffffu, rm0, 1));
        rm0 = fmaxf(rm0, __shfl_xor_sync(0xffffffffu, rm0, 2));
        rm1 = fmaxf(rm1, __shfl_xor_sync(0xffffffffu, rm1, 1));
        rm1 = fmaxf(rm1, __shfl_xor_sync(0xffffffffu, rm1, 2));
        float mn0 = fmaxf(m0v, rm0), mn1 = fmaxf(m1v, rm1);
        float c0 = __expf(m0v - mn0), c1 = __expf(m1v - mn1);
        float p[8][4], rs0 = 0.f, rs1 = 0.f;
        #pragma unroll
        for (int j = 0; j < 8; j++) {
            p[j][0] = __expf(sc[j][0] - mn0);
            p[j][1] = __expf(sc[j][1] - mn0);
            p[j][2] = __expf(sc[j][2] - mn1);
            p[j][3] = __expf(sc[j][3] - mn1);
            rs0 += p[j][0] + p[j][1];
            rs1 += p[j][2] + p[j][3];
        }
        rs0 += __shfl_xor_sync(0xffffffffu, rs0, 1);
        rs0 += __shfl_xor_sync(0xffffffffu, rs0, 2);
        rs1 += __shfl_xor_sync(0xffffffffu, rs1, 1);
        rs1 += __shfl_xor_sync(0xffffffffu, rs1, 2);
        l0v = l0v * c0 + rs0;  m0v = mn0;
        l1v = l1v * c1 + rs1;  m1v = mn1;
        #pragma unroll
        for (int n = 0; n < 16; n++) {
            accO[n][0] *= c0; accO[n][1] *= c0;
            accO[n][2] *= c1; accO[n][3] *= c1;
        }

        #pragma unroll
        for (int kc = 0; kc < 4; kc++) {
            uint32_t a_h[4], a_l[4];
            #pragma unroll
            for (int q = 0; q < 2; q++) {
                float v0 = p[2*kc+q][0], v1 = p[2*kc+q][1];
                float v2 = p[2*kc+q][2], v3 = p[2*kc+q][3];
                uint32_t h01 = packbf2(v0, v1), h23 = packbf2(v2, v3);
                __nv_bfloat162 hb01 = *(__nv_bfloat162*)&h01;
                __nv_bfloat162 hb23 = *(__nv_bfloat162*)&h23;
                uint32_t l01 = packbf2(v0 - __bfloat162float(hb01.x),
                                       v1 - __bfloat162float(hb01.y));
                uint32_t l23 = packbf2(v2 - __bfloat162float(hb23.x),
                                       v3 - __bfloat162float(hb23.y));
                a_h[2*q+0] = h01; a_h[2*q+1] = h23;
                a_l[2*q+0] = l01; a_l[2*q+1] = l23;
            }
            #pragma unroll
            for (int ng = 0; ng < 8; ng++) {
                int drow = ng * 16 + (jq >> 1) * 8 + jr;
                uint32_t boff = (uint32_t)(drow * LV + kc * 16 + (jq & 1) * 8) * 2;
                uint32_t vh_[4], vl_[4];
                LDMX4(vh_, V_h + boff);
                LDMX4(vl_, V_l + boff);
                MMA16816(accO[2*ng],   a_h, &vh_[0]);
                MMA16816(accO[2*ng],   a_h, &vl_[0]);
                MMA16816(accO[2*ng],   a_l, &vh_[0]);
                MMA16816(accO[2*ng+1], a_h, &vh_[2]);
                MMA16816(accO[2*ng+1], a_h, &vl_[2]);
                MMA16816(accO[2*ng+1], a_l, &vh_[2]);
            }
        }

        __syncthreads();
        if (kt + 2 < 32) issue_kv(kt + 2, s); else CP_COMMIT();
    }

    float inv0 = 1.0f / l0v, inv1 = 1.0f / l1v;
    const size_t r0 = qrow0 + q0w + g;
    const size_t r1 = r0 + 8;
    #pragma unroll
    for (int n = 0; n < 16; n++) {
        int col = h * 128 + n * 8 + t * 2;
        float v0 = accO[n][0] * inv0, v1 = accO[n][1] * inv0;
        float v2 = accO[n][2] * inv1, v3 = accO[n][3] * inv1;
        __nv_bfloat16 h0,l0,h1,l1,h2,l2,h3,l3;
        split2(v0,h0,l0); split2(v1,h1,l1); split2(v2,h2,l2); split2(v3,h3,l3);
        __nv_bfloat162 hp0, lp0, hp1, lp1;
        hp0.x=h0; hp0.y=h1; lp0.x=l0; lp0.y=l1;
        hp1.x=h2; hp1.y=h3; lp1.x=l2; lp1.y=l3;
        *(__nv_bfloat162*)&Oh[r0*2048 + col] = hp0;
        *(__nv_bfloat162*)&Ol[r0*2048 + col] = lp0;
        *(__nv_bfloat162*)&Oh[r1*2048 + col] = hp1;
        *(__nv_bfloat162*)&Ol[r1*2048 + col] = lp1;
    }
}

// ---------------- transpose + bf16 split: W[K,N] -> Th/Tl[N,K] --------------
__global__ __launch_bounds__(256)
void transpose_split(const float* __restrict__ W, int K, int N,
                     __nv_bfloat16* __restrict__ Th, __nv_bfloat16* __restrict__ Tl)
{
    __shared__ float tile[32][33];
    const int tx = threadIdx.x, ty = threadIdx.y;
    const int n0 = blockIdx.x * 32, k0 = blockIdx.y * 32;
    #pragma unroll
    for (int i = 0; i < 4; i++)
        tile[ty + 8*i][tx] = W[(size_t)(k0 + ty + 8*i) * N + n0 + tx];
    __syncthreads();
    #pragma unroll
    for (int i = 0; i < 4; i++) {
        float v = tile[tx][ty + 8*i];
        __nv_bfloat16 h, l; split2(v, h, l);
        size_t o = (size_t)(n0 + ty + 8*i) * K + k0 + tx;
        Th[o] = h; Tl[o] = l;
    }
}

// ---------------- qk prep: qkv fp32 -> Q(scaled)/K bf16 splits --------------
__global__ __launch_bounds__(256)
void qk_prep(const float* __restrict__ qkv,
             __nv_bfloat16* __restrict__ qh, __nv_bfloat16* __restrict__ ql,
             __nv_bfloat16* __restrict__ kh, __nv_bfloat16* __restrict__ kl)
{
    const float scale = 0.088388347648318447f;
    size_t e = ((size_t)blockIdx.x * 256 + threadIdx.x) * 4;
    int row = (int)(e >> 12);
    int col = (int)(e & 4095);
    float4 v = *(const float4*)&qkv[(size_t)row * 6144 + col];
    __nv_bfloat16 hb[4], lb[4];
    if (col < 2048) {
        split2(v.x*scale, hb[0], lb[0]); split2(v.y*scale, hb[1], lb[1]);
        split2(v.z*scale, hb[2], lb[2]); split2(v.w*scale, hb[3], lb[3]);
        *(uint2*)&qh[(size_t)row*2048 + col] = *(uint2*)hb;
        *(uint2*)&ql[(size_t)row*2048 + col] = *(uint2*)lb;
    } else {
        split2(v.x, hb[0], lb[0]); split2(v.y, hb[1], lb[1]);
        split2(v.z, hb[2], lb[2]); split2(v.w, hb[3], lb[3]);
        *(uint2*)&kh[(size_t)row*2048 + col - 2048] = *(uint2*)hb;
        *(uint2*)&kl[(size_t)row*2048 + col - 2048] = *(uint2*)lb;
    }
}

// ---------------- v prep: transpose V per (b,h) -> [dim][keys] splits -------
__global__ __launch_bounds__(256)
void v_prep(const float* __restrict__ qkv,
            __nv_bfloat16* __restrict__ vth, __nv_bfloat16* __restrict__ vtl)
{
    __shared__ float tile[32][33];
    const int tx = threadIdx.x, ty = threadIdx.y;
    const int z = blockIdx.z, b = z >> 4, h = z & 15;
    const int key0 = blockIdx.x * 32, d0 = blockIdx.y * 32;
    #pragma unroll
    for (int i = 0; i < 4; i++) {
        int key = key0 + ty + 8*i;
        tile[ty + 8*i][tx] = qkv[(size_t)(b*2048 + key)*6144 + 4096 + h*128 + d0 + tx];
    }
    __syncthreads();
    #pragma unroll
    for (int i = 0; i < 4; i++) {
        int d = d0 + ty + 8*i;
        float v = tile[tx][ty + 8*i];
        __nv_bfloat16 hh, ll; split2(v, hh, ll);
        size_t o = ((size_t)z*128 + d)*2048 + key0 + tx;
        vth[o] = hh; vtl[o] = ll;
    }
}

// ---------------- LayerNorm: out = LN(A [+ Ad]) * g + b ; + bf16 split ------
__global__ __launch_bounds__(256)
void ln_kernel(const float* __restrict__ A, const float* __restrict__ Ad,
               const float* __restrict__ g, const float* __restrict__ bb,
               float* __restrict__ out, __nv_bfloat16* __restrict__ oh,
               __nv_bfloat16* __restrict__ ol)
{
    const int row = blockIdx.x, t = threadIdx.x;
    const float* a = A + (size_t)row * D_;
    float4 v[2];
    float s = 0.f, ss = 0.f;
    #pragma unroll
    for (int i = 0; i < 2; i++) {
        int idx = (i*256 + t) * 4;
        float4 x = *(const float4*)&a[idx];
        if (Ad) {
            float4 y = *(const float4*)&Ad[(size_t)row*D_ + idx];
            x.x += y.x; x.y += y.y; x.z += y.z; x.w += y.w;
        }
        v[i] = x;
        s  += x.x + x.y + x.z + x.w;
        ss += x.x*x.x + x.y*x.y + x.z*x.z + x.w*x.w;
    }
    #pragma unroll
    for (int off = 16; off; off >>= 1) {
        s  += __shfl_xor_sync(0xffffffffu, s,  off);
        ss += __shfl_xor_sync(0xffffffffu, ss, off);
    }
    __shared__ float sb[8], ssb[8];
    if ((t & 31) == 0) { sb[t>>5] = s; ssb[t>>5] = ss; }
    __syncthreads();
    float st = 0.f, sst = 0.f;
    #pragma unroll
    for (int i = 0; i < 8; i++) { st += sb[i]; sst += ssb[i]; }
    float mean = st * (1.f / D_);
    float var  = sst * (1.f / D_) - mean * mean;
    float rstd = rsqrtf(var + 1e-5f);
    #pragma unroll
    for (int i = 0; i < 2; i++) {
        int idx = (i*256 + t) * 4;
        float4 gg  = *(const float4*)&g[idx];
        float4 bbv = *(const float4*)&bb[idx];
        float4 x = v[i], o;
        o.x = (x.x - mean)*rstd*gg.x + bbv.x;
        o.y = (x.y - mean)*rstd*gg.y + bbv.y;
        o.z = (x.z - mean)*rstd*gg.z + bbv.z;
        o.w = (x.w - mean)*rstd*gg.w + bbv.w;
        if (out) *(float4*)&out[(size_t)row*D_ + idx] = o;
        __nv_bfloat16 hb[4], lb[4];
        split2(o.x, hb[0], lb[0]); split2(o.y, hb[1], lb[1]);
        split2(o.z, hb[2], lb[2]); split2(o.w, hb[3], lb[3]);
        *(uint2*)&oh[(size_t)row*D_ + idx] = *(uint2*)hb;
        *(uint2*)&ol[(size_t)row*D_ + idx] = *(uint2*)lb;
    }
}

// ---------------- persona vector: pers[j] = pemb[t]@dw[D:2D, j] + db[j] -----
__global__ __launch_bounds__(256)
void pers_kernel(const float* __restrict__ pemb, const int* __restrict__ trait,
                 const float* __restrict__ dw, const float* __restrict__ db,
                 float* __restrict__ out)
{
    int j = blockIdx.x * 256 + threadIdx.x;
    int t = trait[0];
    const float* pe = pemb + (size_t)t * D_;
    float acc = db[j];
    for (int i = 0; i < D_; ++i)
        acc = fmaf(pe[i], dw[(size_t)(D_ + i) * D_ + j], acc);
    out[j] = acc;
}

// ---------------- launch ----------------------------------------------------
extern "C" void kernel_launch(void* const* d_in, const int* in_sizes, int n_in,
                              void* d_out, int out_size)
{
    const float* x     = (const float*)d_in[0];
    const int*   mask  = (const int*)  d_in[1];
    const int*   trait = (const int*)  d_in[2];
    const float* wq    = (const float*)d_in[3];
    const float* wk    = (const float*)d_in[4];
    const float* wv    = (const float*)d_in[5];
    const float* wo    = (const float*)d_in[6];
    const float* g1    = (const float*)d_in[7];
    const float* b1    = (const float*)d_in[8];
    const float* g2    = (const float*)d_in[9];
    const float* b2    = (const float*)d_in[10];
    const float* rw1   = (const float*)d_in[11];
    const float* rb1   = (const float*)d_in[12];
    const float* rw2   = (const float*)d_in[13];
    const float* rb2   = (const float*)d_in[14];
    const float* rg    = (const float*)d_in[15];
    const float* rb    = (const float*)d_in[16];
    const float* pemb  = (const float*)d_in[17];
    const float* dw    = (const float*)d_in[18];
    const float* db    = (const float*)d_in[19];
    const float* wgam  = (const float*)d_in[20];
    const float* wbet  = (const float*)d_in[21];
    const float* mw1   = (const float*)d_in[22];
    const float* mb1   = (const float*)d_in[23];
    const float* mw2   = (const float*)d_in[24];
    const float* mb2   = (const float*)d_in[25];
    float* out = (float*)d_out;

    static float *pqkv=0,*px2=0,*pr=0,*ph2=0,*ph3=0,*ppers=0;
    static __nv_bfloat16 *pah=0,*pal=0,*pth=0,*ptl=0,*pwh=0,*pwl=0;
    static __nv_bfloat16 *pqsh=0,*pqsl=0,*pksh=0,*pksl=0,*pvth=0,*pvtl=0;
    static bool inited = false;
    if (!inited) {
        cudaGetSymbolAddress((void**)&pqkv, g_qkv);
        cudaGetSymbolAddress((void**)&px2, g_x2);
        cudaGetSymbolAddress((void**)&pr,  g_r);
        cudaGetSymbolAddress((void**)&ph2, g_h2);
        cudaGetSymbolAddress((void**)&ph3, g_h3);
        cudaGetSymbolAddress((void**)&ppers, g_pers);
        cudaGetSymbolAddress((void**)&pah, g_ah);
        cudaGetSymbolAddress((void**)&pal, g_al);
        cudaGetSymbolAddress((void**)&pth, g_th);
        cudaGetSymbolAddress((void**)&ptl, g_tl);
        cudaGetSymbolAddress((void**)&pwh, g_wh);
        cudaGetSymbolAddress((void**)&pwl, g_wl);
        cudaGetSymbolAddress((void**)&pqsh, g_qsh);
        cudaGetSymbolAddress((void**)&pqsl, g_qsl);
        cudaGetSymbolAddress((void**)&pksh, g_ksh);
        cudaGetSymbolAddress((void**)&pksl, g_ksl);
        cudaGetSymbolAddress((void**)&pvth, g_vth);
        cudaGetSymbolAddress((void**)&pvtl, g_vtl);
        cudaFuncSetAttribute(tbgemm<false,false,false,false>, cudaFuncAttributeMaxDynamicSharedMemorySize, TG_SMEM);
        cudaFuncSetAttribute(tbgemm<false,false,true,false>,  cudaFuncAttributeMaxDynamicSharedMemorySize, TG_SMEM);
        cudaFuncSetAttribute(tbgemm<true,true,false,true>,    cudaFuncAttributeMaxDynamicSharedMemorySize, TG_SMEM);
        cudaFuncSetAttribute(tbgemm<false,true,false,false>,  cudaFuncAttributeMaxDynamicSharedMemorySize, TG_SMEM);
        cudaFuncSetAttribute(tbgemm<false,true,true,false>,   cudaFuncAttributeMaxDynamicSharedMemorySize, TG_SMEM);
        cudaFuncSetAttribute(flash_attn, cudaFuncAttributeMaxDynamicSharedMemorySize, FA_SMEM);
        inited = true;
    }

    const dim3 blk(256);
    const dim3 tb(32, 8);

    // ---- weight prep ----
    transpose_split<<<dim3(64, 64),  tb>>>(wq,  2048, 2048, pwh+OWQ,  pwl+OWQ);
    transpose_split<<<dim3(64, 64),  tb>>>(wk,  2048, 2048, pwh+OWK,  pwl+OWK);
    transpose_split<<<dim3(64, 64),  tb>>>(wv,  2048, 2048, pwh+OWV,  pwl+OWV);
    transpose_split<<<dim3(64, 64),  tb>>>(wo,  2048, 2048, pwh+OWO,  pwl+OWO);
    transpose_split<<<dim3(128, 64), tb>>>(rw1, 2048, 4096, pwh+ORW1, pwl+ORW1);
    transpose_split<<<dim3(64, 128), tb>>>(rw2, 4096, 2048, pwh+ORW2, pwl+ORW2);
    transpose_split<<<dim3(64, 64),  tb>>>(dw,  2048, 2048, pwh+ODW,  pwl+ODW);
    transpose_split<<<dim3(256, 64), tb>>>(mw1, 2048, 8192, pwh+OMW1, pwl+OMW1);
    transpose_split<<<dim3(64, 256), tb>>>(mw2, 8192, 2048, pwh+OMW2, pwl+OMW2);
    pers_kernel<<<D_/256, blk>>>(pemb, trait, dw, db, ppers);

    // 1) h = LN1(x) -> bf16 split
    ln_kernel<<<M_, blk>>>(x, nullptr, g1, b1, nullptr, pah, pal);
    // 2) qkv = h @ [wq|wk|wv]
    tbgemm<false,false,false,false><<<dim3(48,32), blk, TG_SMEM>>>(
        pah,pal, pwh+OWQ,pwl+OWQ, nullptr,nullptr, pqkv,nullptr,nullptr, M_, 3*D_, D_);
    // 3) attention prep (bf16 splits)
    qk_prep<<<16384, blk>>>(pqkv, pqsh, pqsl, pksh, pksl);
    v_prep<<<dim3(64, 4, 32), tb>>>(pqkv, pvth, pvtl);
    // 4) fused flash attention -> pah/pal
    flash_attn<<<dim3(16, 32), blk, FA_SMEM>>>(
        pqsh, pqsl, pksh, pksl, pvth, pvtl, mask, pah, pal);
    // 5) x2 = x + attn_out @ wo
    tbgemm<false,false,true,false><<<dim3(16,32), blk, TG_SMEM>>>(
        pah,pal, pwh+OWO,pwl+OWO, nullptr,x, px2,nullptr,nullptr, M_, D_, D_);
    // 6) h2 = LN2(x2)
    ln_kernel<<<M_, blk>>>(px2, nullptr, g2, b2, ph2, pah, pal);
    // 7) t = gelu(h2 @ rw1 + rb1)
    tbgemm<true,true,false,true><<<dim3(32,32), blk, TG_SMEM>>>(
        pah,pal, pwh+ORW1,pwl+ORW1, rb1,nullptr, nullptr,pth,ptl, M_, 2*D_, D_);
    // 8) r = t @ rw2 + rb2
    tbgemm<false,true,false,false><<<dim3(16,32), blk, TG_SMEM>>>(
        pth,ptl, pwh+ORW2,pwl+ORW2, rb2,nullptr, pr,nullptr,nullptr, M_, D_, 2*D_);
    // 9) h3 = LN(h2 + r)
    ln_kernel<<<M_, blk>>>(ph2, pr, rg, rb, ph3, pah, pal);
    // 10) dec = h3 @ dw[:D] + pers
    tbgemm<false,true,false,false><<<dim3(16,32), blk, TG_SMEM>>>(
        pah,pal, pwh+ODW,pwl+ODW, ppers,nullptr, pqkv,nullptr,nullptr, M_, D_, D_);
    // 11) h4 = LN(h3 + dec)
    ln_kernel<<<M_, blk>>>(ph3, pqkv, wgam, wbet, nullptr, pah, pal);
    // 12) t = gelu(h4 @ mw1 + mb1)
    tbgemm<true,true,false,true><<<dim3(64,32), blk, TG_SMEM>>>(
        pah,pal, pwh+OMW1,pwl+OMW1, mb1,nullptr, nullptr,pth,ptl, M_, 4*D_, D_);
    // 13) out = x2 + t @ mw2 + mb2
    tbgemm<false,true,true,false><<<dim3(16,32), blk, TG_SMEM>>>(
        pth,ptl, pwh+OMW2,pwl+OMW2, mb2,px2, out,nullptr,nullptr, M_, D_, 4*D_);
}

// round 12
// speedup vs baseline: 1.0271x; 1.0271x over previous
#include <cuda_runtime.h>
#include <cuda_bf16.h>
#include <math.h>
#include <stdint.h>

#define B_  2
#define S_  2048
#define D_  2048
#define H_  16
#define HD_ 128
#define M_  (B_*S_)   // 4096 rows

// ---------------- scratch (static device globals; allocation-free) ----------
__device__ __align__(128) float g_qkv[(size_t)M_*3*D_];   // [M][6144] q|k|v
__device__ __align__(128) float g_x2 [(size_t)M_*D_];
__device__ __align__(128) float g_r  [(size_t)M_*D_];
__device__ __align__(128) float g_h2 [(size_t)M_*D_];
__device__ __align__(128) float g_h3 [(size_t)M_*D_];
__device__ __align__(128) float g_pers[D_];

// bf16 hi/lo activation scratch
__device__ __align__(128) __nv_bfloat16 g_ah[(size_t)M_*D_];
__device__ __align__(128) __nv_bfloat16 g_al[(size_t)M_*D_];
__device__ __align__(128) __nv_bfloat16 g_th[(size_t)M_*4*D_];
__device__ __align__(128) __nv_bfloat16 g_tl[(size_t)M_*4*D_];

// attention scratch (bf16 splits only)
__device__ __align__(128) __nv_bfloat16 g_qsh[(size_t)M_*D_];
__device__ __align__(128) __nv_bfloat16 g_qsl[(size_t)M_*D_];
__device__ __align__(128) __nv_bfloat16 g_ksh[(size_t)M_*D_];
__device__ __align__(128) __nv_bfloat16 g_ksl[(size_t)M_*D_];
__device__ __align__(128) __nv_bfloat16 g_vth[(size_t)32*HD_*S_];   // [bh][128][2048]
__device__ __align__(128) __nv_bfloat16 g_vtl[(size_t)32*HD_*S_];

// bf16 hi/lo transposed weights, packed offsets into one pool: [N,K] row-major
#define OWQ  ((size_t)0)
#define OWK  ((size_t)4194304)
#define OWV  ((size_t)8388608)
#define OWO  ((size_t)12582912)
#define ORW1 ((size_t)16777216)
#define ORW2 ((size_t)25165824)
#define ODW  ((size_t)33554432)
#define OMW1 ((size_t)37748736)
#define OMW2 ((size_t)54525952)
#define WTOT ((size_t)71303168)
__device__ __align__(128) __nv_bfloat16 g_wh[WTOT];
__device__ __align__(128) __nv_bfloat16 g_wl[WTOT];

// ---------------- helpers ----------------------------------------------------
__device__ __forceinline__ void split2(float v, __nv_bfloat16& h, __nv_bfloat16& l) {
    h = __float2bfloat16(v);
    l = __float2bfloat16(v - __bfloat162float(h));
}
__device__ __forceinline__ uint32_t smem_u32(const void* p) {
    uint32_t a;
    asm("{ .reg .u64 t; cvta.to.shared.u64 t, %1; cvt.u32.u64 %0, t; }" : "=r"(a) : "l"(p));
    return a;
}
__device__ __forceinline__ uint32_t packbf2(float a, float b) {
    __nv_bfloat162 p;
    p.x = __float2bfloat16(a); p.y = __float2bfloat16(b);
    return *(uint32_t*)&p;
}

#define MMA16816(d, a, b) \
    asm volatile("mma.sync.aligned.m16n8k16.row.col.f32.bf16.bf16.f32 " \
        "{%0,%1,%2,%3}, {%4,%5,%6,%7}, {%8,%9}, {%0,%1,%2,%3};" \
        : "+f"((d)[0]), "+f"((d)[1]), "+f"((d)[2]), "+f"((d)[3]) \
        : "r"((a)[0]), "r"((a)[1]), "r"((a)[2]), "r"((a)[3]), "r"((b)[0]), "r"((b)[1]))

#define LDMX4(d, addr) \
    asm volatile("ldmatrix.sync.aligned.m8n8.x4.shared.b16 {%0,%1,%2,%3}, [%4];" \
        : "=r"((d)[0]), "=r"((d)[1]), "=r"((d)[2]), "=r"((d)[3]) : "r"(addr))

__device__ __forceinline__ void cp16(uint32_t dst, const void* src) {
    asm volatile("cp.async.cg.shared.global [%0], [%1], 16;" :: "r"(dst), "l"(src));
}
#define CP_COMMIT() asm volatile("cp.async.commit_group;" ::: "memory")
#define CP_WAIT1()  asm volatile("cp.async.wait_group 1;" ::: "memory")

__device__ __forceinline__ float gelu1(float v) {
    return 0.5f * v * (1.0f + erff(v * 0.70710678118654752f));
}

// ================= HMMA GEMM: 128x128 tile, KC=32, 2-stage, 2 CTAs/SM ========
// stage = Ah|Al (128x40) + Bh|Bl (128x40) = 40960 B; 2 stages = 81920 B/CTA.
#define LDE 40
#define MAT_E (128*LDE)                // 5120 elems
#define STAGE_B (4*MAT_E*2)            // 40960 bytes
#define TG_SMEM (2*STAGE_B)            // 81920 bytes -> 2 CTAs/SM

template<bool GELU, bool BIAS, bool RES, bool OUT_BF16>
__global__ __launch_bounds__(256, 2)
void tbgemm(const __nv_bfloat16* __restrict__ Ah, const __nv_bfloat16* __restrict__ Al,
            const __nv_bfloat16* __restrict__ Bh, const __nv_bfloat16* __restrict__ Bl,
            const float* __restrict__ bias, const float* __restrict__ res,
            float* __restrict__ Cf, __nv_bfloat16* __restrict__ Ch, __nv_bfloat16* __restrict__ Cl,
            int M, int N, int K)
{
    extern __shared__ __nv_bfloat16 sm[];
    const int tid  = threadIdx.x;
    const int lane = tid & 31;
    const int warp = tid >> 5;
    const int wm = warp & 3;
    const int wn = warp >> 2;
    const int m0 = blockIdx.y * 128;
    const int n0 = blockIdx.x * 128;
    const int g  = lane >> 2;
    const int t  = lane & 3;
    const uint32_t sbase = smem_u32(sm);
    const int jq = lane >> 3;
    const int jr = lane & 7;

    float acc[2][8][4];
    #pragma unroll
    for (int m = 0; m < 2; m++)
        #pragma unroll
        for (int n = 0; n < 8; n++)
            #pragma unroll
            for (int e = 0; e < 4; e++) acc[m][n][e] = 0.f;

    auto issue = [&](int c, int buf) {
        const int k0 = c << 5;
        const uint32_t b0 = sbase + (uint32_t)buf * STAGE_B;
        #pragma unroll
        for (int i = 0; i < 2; i++) {
            int v = i * 256 + tid;
            int r = v >> 2, q = v & 3;
            uint32_t so = (uint32_t)(r * LDE + q * 8) * 2;
            size_t ga = (size_t)(m0 + r) * K + k0 + q * 8;
            size_t gb = (size_t)(n0 + r) * K + k0 + q * 8;
            cp16(b0 + so,               Ah + ga);
            cp16(b0 + MAT_E*2 + so,     Al + ga);
            cp16(b0 + 2*MAT_E*2 + so,   Bh + gb);
            cp16(b0 + 3*MAT_E*2 + so,   Bl + gb);
        }
        CP_COMMIT();
    };

    const int nc = K >> 5;
    issue(0, 0);
    if (nc > 1) issue(1, 1); else CP_COMMIT();

    for (int c = 0; c < nc; c++) {
        const int buf = c & 1;
        CP_WAIT1();
        __syncthreads();

        const uint32_t A_h = sbase + (uint32_t)buf * STAGE_B;
        const uint32_t A_l = A_h + MAT_E*2;
        const uint32_t B_h = A_h + 2*MAT_E*2;
        const uint32_t B_l = A_h + 3*MAT_E*2;

        #pragma unroll
        for (int kk = 0; kk < 32; kk += 16) {
            uint32_t ah[2][4], al[2][4];
            #pragma unroll
            for (int m = 0; m < 2; m++) {
                int row = wm * 32 + m * 16 + (jq & 1) * 8 + jr;
                uint32_t off = (uint32_t)(row * LDE + kk + (jq >> 1) * 8) * 2;
                LDMX4(ah[m], A_h + off);
                LDMX4(al[m], A_l + off);
            }
            #pragma unroll
            for (int np = 0; np < 4; np++) {
                int nrow = wn * 64 + np * 16 + (jq >> 1) * 8 + jr;
                uint32_t boff = (uint32_t)(nrow * LDE + kk + (jq & 1) * 8) * 2;
                uint32_t bh[4], bl[4];
                LDMX4(bh, B_h + boff);
                LDMX4(bl, B_l + boff);
                #pragma unroll
                for (int m = 0; m < 2; m++) {
                    MMA16816(acc[m][2*np],   ah[m], &bh[0]);
                    MMA16816(acc[m][2*np],   ah[m], &bl[0]);
                    MMA16816(acc[m][2*np],   al[m], &bh[0]);
                    MMA16816(acc[m][2*np+1], ah[m], &bh[2]);
                    MMA16816(acc[m][2*np+1], ah[m], &bl[2]);
                    MMA16816(acc[m][2*np+1], al[m], &bh[2]);
                }
            }
        }
        __syncthreads();
        if (c + 2 < nc) issue(c + 2, buf); else CP_COMMIT();
    }

    #pragma unroll
    for (int m = 0; m < 2; m++) {
        #pragma unroll
        for (int n = 0; n < 8; n++) {
            int col = n0 + wn * 64 + n * 8 + t * 2;
            #pragma unroll
            for (int half = 0; half < 2; half++) {
                int row = m0 + wm * 32 + m * 16 + g + half * 8;
                float v0 = acc[m][n][half * 2 + 0];
                float v1 = acc[m][n][half * 2 + 1];
                if (BIAS) { v0 += bias[col]; v1 += bias[col + 1]; }
                if (GELU) { v0 = gelu1(v0); v1 = gelu1(v1); }
                size_t off = (size_t)row * N + col;
                if (RES) {
                    float2 r2 = *(const float2*)&res[off];
                    v0 += r2.x; v1 += r2.y;
                }
                if (OUT_BF16) {
                    __nv_bfloat16 h0, l0, h1, l1;
                    split2(v0, h0, l0); split2(v1, h1, l1);
                    __nv_bfloat162 hp, lp;
                    hp.x = h0; hp.y = h1; lp.x = l0; lp.y = l1;
                    *(__nv_bfloat162*)&Ch[off] = hp;
                    *(__nv_bfloat162*)&Cl[off] = lp;
                } else {
                    *(float2*)&Cf[off] = make_float2(v0, v1);
                }
            }
        }
    }
}

// ================= fused HMMA flash attention (unchanged from R10) ===========
#define LQ 136
#define LV 72
#define FQH 0
#define FQL (128*LQ)
#define FST0 (2*128*LQ)
#define FKH 0
#define FKL (64*LQ)
#define FVH (2*64*LQ)
#define FVL (FVH + 128*LV)
#define FSTG (FVL + 128*LV)
#define FA_SMEM ((FST0 + 2*FSTG)*2)    // 212992 bytes

__global__ __launch_bounds__(256)
void flash_attn(const __nv_bfloat16* __restrict__ Qh, const __nv_bfloat16* __restrict__ Ql,
                const __nv_bfloat16* __restrict__ Kh, const __nv_bfloat16* __restrict__ Kl,
                const __nv_bfloat16* __restrict__ Vth, const __nv_bfloat16* __restrict__ Vtl,
                const int* __restrict__ mask,
                __nv_bfloat16* __restrict__ Oh, __nv_bfloat16* __restrict__ Ol)
{
    extern __shared__ __nv_bfloat16 fsm[];
    const int tid  = threadIdx.x;
    const int lane = tid & 31;
    const int warp = tid >> 5;
    const int g  = lane >> 2;
    const int t  = lane & 3;
    const int jq = lane >> 3;
    const int jr = lane & 7;
    const uint32_t sb = smem_u32(fsm);
    const int z = blockIdx.y, b = z >> 4, h = z & 15;
    const int q0 = blockIdx.x * 128;
    const size_t qrow0 = (size_t)b * 2048 + q0;

    {
        #pragma unroll
        for (int i = 0; i < 8; i++) {
            int v = i * 256 + tid;
            int r = v >> 4, q = v & 15;
            uint32_t so = (uint32_t)(r * LQ + q * 8) * 2;
            size_t gq = (qrow0 + r) * 2048 + h * 128 + q * 8;
            cp16(sb + (FQH)*2 + so, Qh + gq);
            cp16(sb + (FQL)*2 + so, Ql + gq);
        }
        CP_COMMIT();
    }

    auto issue_kv = [&](int kt, int s) {
        const uint32_t b0 = sb + (uint32_t)(FST0 + s * FSTG) * 2;
        #pragma unroll
        for (int i = 0; i < 4; i++) {
            int v = i * 256 + tid;
            int r = v >> 4, q = v & 15;
            uint32_t so = (uint32_t)(r * LQ + q * 8) * 2;
            size_t gk = ((size_t)b * 2048 + kt * 64 + r) * 2048 + h * 128 + q * 8;
            cp16(b0 + (FKH)*2 + so, Kh + gk);
            cp16(b0 + (FKL)*2 + so, Kl + gk);
        }
        #pragma unroll
        for (int i = 0; i < 4; i++) {
            int v = i * 256 + tid;
            int d = v >> 3, q = v & 7;
            uint32_t so = (uint32_t)(d * LV + q * 8) * 2;
            size_t gv = ((size_t)z * 128 + d) * 2048 + kt * 64 + q * 8;
            cp16(b0 + (FVH)*2 + so, Vth + gv);
            cp16(b0 + (FVL)*2 + so, Vtl + gv);
        }
        CP_COMMIT();
    };

    issue_kv(0, 0);
    issue_kv(1, 1);

    const int q0w = warp * 16;
    float accO[16][4];
    #pragma unroll
    for (int n = 0; n < 16; n++)
        #pragma unroll
        for (int e = 0; e < 4; e++) accO[n][e] = 0.f;
    float m0v = -1e30f, m1v = -1e30f, l0v = 0.f, l1v = 0.f;

    for (int kt = 0; kt < 32; kt++) {
        CP_WAIT1();
        __syncthreads();
        const int s = kt & 1;
        const uint32_t K_h = sb + (uint32_t)(FST0 + s * FSTG + FKH) * 2;
        const uint32_t K_l = sb + (uint32_t)(FST0 + s * FSTG + FKL) * 2;
        const uint32_t V_h = sb + (uint32_t)(FST0 + s * FSTG + FVH) * 2;
        const uint32_t V_l = sb + (uint32_t)(FST0 + s * FSTG + FVL) * 2;

        float sc[8][4];
        #pragma unroll
        for (int n = 0; n < 8; n++)
            #pragma unroll
            for (int e = 0; e < 4; e++) sc[n][e] = 0.f;
        #pragma unroll
        for (int kc = 0; kc < 8; kc++) {
            int arow = q0w + (jq & 1) * 8 + jr;
            uint32_t aoff = (uint32_t)(arow * LQ + kc * 16 + (jq >> 1) * 8) * 2;
            uint32_t qh_[4], ql_[4];
            LDMX4(qh_, sb + FQH*2 + aoff);
            LDMX4(ql_, sb + FQL*2 + aoff);
            #pragma unroll
            for (int ng = 0; ng < 4; ng++) {
                int krow = ng * 16 + (jq >> 1) * 8 + jr;
                uint32_t boff = (uint32_t)(krow * LQ + kc * 16 + (jq & 1) * 8) * 2;
                uint32_t kh_[4], kl_[4];
                LDMX4(kh_, K_h + boff);
                LDMX4(kl_, K_l + boff);
                MMA16816(sc[2*ng],   qh_, &kh_[0]);
                MMA16816(sc[2*ng],   qh_, &kl_[0]);
                MMA16816(sc[2*ng],   ql_, &kh_[0]);
                MMA16816(sc[2*ng+1], qh_, &kh_[2]);
                MMA16816(sc[2*ng+1], qh_, &kl_[2]);
                MMA16816(sc[2*ng+1], ql_, &kh_[2]);
            }
        }

        const int kb = b * 2048 + kt * 64;
        #pragma unroll
        for (int j = 0; j < 8; j++) {
            if (mask[kb + 8*j + 2*t]     == 0) { sc[j][0] = -1e30f; sc[j][2] = -1e30f; }
            if (mask[kb + 8*j + 2*t + 1] == 0) { sc[j][1] = -1e30f; sc[j][3] = -1e30f; }
        }
        float rm0 = -1e30f, rm1 = -1e30f;
        #pragma unroll
        for (int j = 0; j < 8; j++) {
            rm0 = fmaxf(rm0, fmaxf(sc[j][0], sc[j][1]));
            rm1 = fmaxf(rm1, fmaxf(sc[j][2], sc[j][3]));
        }
        rm0 = fmaxf(rm0, __shfl_xor_sync(0xffffffffu, rm0, 1));
        rm0 = fmaxf(rm0, __shfl_xor_sync(0xffffffffu, rm0, 2));
        rm1 = fmaxf(rm1, __shfl_xor_sync(0xffffffffu, rm1, 1));
        rm1 = fmaxf(rm1, __shfl_xor_sync(0xffffffffu, rm1, 2));
        float mn0 = fmaxf(m0v, rm0), mn1 = fmaxf(m1v, rm1);
        float c0 = __expf(m0v - mn0), c1 = __expf(m1v - mn1);
        float p[8][4], rs0 = 0.f, rs1 = 0.f;
        #pragma unroll
        for (int j = 0; j < 8; j++) {
            p[j][0] = __expf(sc[j][0] - mn0);
            p[j][1] = __expf(sc[j][1] - mn0);
            p[j][2] = __expf(sc[j][2] - mn1);
            p[j][3] = __expf(sc[j][3] - mn1);
            rs0 += p[j][0] + p[j][1];
            rs1 += p[j][2] + p[j][3];
        }
        rs0 += __shfl_xor_sync(0xffffffffu, rs0, 1);
        rs0 += __shfl_xor_sync(0xffffffffu, rs0, 2);
        rs1 += __shfl_xor_sync(0xffffffffu, rs1, 1);
        rs1 += __shfl_xor_sync(0xffffffffu, rs1, 2);
        l0v = l0v * c0 + rs0;  m0v = mn0;
        l1v = l1v * c1 + rs1;  m1v = mn1;
        #pragma unroll
        for (int n = 0; n < 16; n++) {
            accO[n][0] *= c0; accO[n][1] *= c0;
            accO[n][2] *= c1; accO[n][3] *= c1;
        }

        #pragma unroll
        for (int kc = 0; kc < 4; kc++) {
            uint32_t a_h[4], a_l[4];
            #pragma unroll
            for (int q = 0; q < 2; q++) {
                float v0 = p[2*kc+q][0], v1 = p[2*kc+q][1];
                float v2 = p[2*kc+q][2], v3 = p[2*kc+q][3];
                uint32_t h01 = packbf2(v0, v1), h23 = packbf2(v2, v3);
                __nv_bfloat162 hb01 = *(__nv_bfloat162*)&h01;
                __nv_bfloat162 hb23 = *(__nv_bfloat162*)&h23;
                uint32_t l01 = packbf2(v0 - __bfloat162float(hb01.x),
                                       v1 - __bfloat162float(hb01.y));
                uint32_t l23 = packbf2(v2 - __bfloat162float(hb23.x),
                                       v3 - __bfloat162float(hb23.y));
                a_h[2*q+0] = h01; a_h[2*q+1] = h23;
                a_l[2*q+0] = l01; a_l[2*q+1] = l23;
            }
            #pragma unroll
            for (int ng = 0; ng < 8; ng++) {
                int drow = ng * 16 + (jq >> 1) * 8 + jr;
                uint32_t boff = (uint32_t)(drow * LV + kc * 16 + (jq & 1) * 8) * 2;
                uint32_t vh_[4], vl_[4];
                LDMX4(vh_, V_h + boff);
                LDMX4(vl_, V_l + boff);
                MMA16816(accO[2*ng],   a_h, &vh_[0]);
                MMA16816(accO[2*ng],   a_h, &vl_[0]);
                MMA16816(accO[2*ng],   a_l, &vh_[0]);
                MMA16816(accO[2*ng+1], a_h, &vh_[2]);
                MMA16816(accO[2*ng+1], a_h, &vl_[2]);
                MMA16816(accO[2*ng+1], a_l, &vh_[2]);
            }
        }

        __syncthreads();
        if (kt + 2 < 32) issue_kv(kt + 2, s); else CP_COMMIT();
    }

    float inv0 = 1.0f / l0v, inv1 = 1.0f / l1v;
    const size_t r0 = qrow0 + q0w + g;
    const size_t r1 = r0 + 8;
    #pragma unroll
    for (int n = 0; n < 16; n++) {
        int col = h * 128 + n * 8 + t * 2;
        float v0 = accO[n][0] * inv0, v1 = accO[n][1] * inv0;
        float v2 = accO[n][2] * inv1, v3 = accO[n][3] * inv1;
        __nv_bfloat16 h0,l0,h1,l1,h2,l2,h3,l3;
        split2(v0,h0,l0); split2(v1,h1,l1); split2(v2,h2,l2); split2(v3,h3,l3);
        __nv_bfloat162 hp0, lp0, hp1, lp1;
        hp0.x=h0; hp0.y=h1; lp0.x=l0; lp0.y=l1;
        hp1.x=h2; hp1.y=h3; lp1.x=l2; lp1.y=l3;
        *(__nv_bfloat162*)&Oh[r0*2048 + col] = hp0;
        *(__nv_bfloat162*)&Ol[r0*2048 + col] = lp0;
        *(__nv_bfloat162*)&Oh[r1*2048 + col] = hp1;
        *(__nv_bfloat162*)&Ol[r1*2048 + col] = lp1;
    }
}

// ---------------- transpose + bf16 split: W[K,N] -> Th/Tl[N,K] --------------
__global__ __launch_bounds__(256)
void transpose_split(const float* __restrict__ W, int K, int N,
                     __nv_bfloat16* __restrict__ Th, __nv_bfloat16* __restrict__ Tl)
{
    __shared__ float tile[32][33];
    const int tx = threadIdx.x, ty = threadIdx.y;
    const int n0 = blockIdx.x * 32, k0 = blockIdx.y * 32;
    #pragma unroll
    for (int i = 0; i < 4; i++)
        tile[ty + 8*i][tx] = W[(size_t)(k0 + ty + 8*i) * N + n0 + tx];
    __syncthreads();
    #pragma unroll
    for (int i = 0; i < 4; i++) {
        float v = tile[tx][ty + 8*i];
        __nv_bfloat16 h, l; split2(v, h, l);
        size_t o = (size_t)(n0 + ty + 8*i) * K + k0 + tx;
        Th[o] = h; Tl[o] = l;
    }
}

// ---------------- qk prep: qkv fp32 -> Q(scaled)/K bf16 splits --------------
__global__ __launch_bounds__(256)
void qk_prep(const float* __restrict__ qkv,
             __nv_bfloat16* __restrict__ qh, __nv_bfloat16* __restrict__ ql,
             __nv_bfloat16* __restrict__ kh, __nv_bfloat16* __restrict__ kl)
{
    const float scale = 0.088388347648318447f;
    size_t e = ((size_t)blockIdx.x * 256 + threadIdx.x) * 4;
    int row = (int)(e >> 12);
    int col = (int)(e & 4095);
    float4 v = *(const float4*)&qkv[(size_t)row * 6144 + col];
    __nv_bfloat16 hb[4], lb[4];
    if (col < 2048) {
        split2(v.x*scale, hb[0], lb[0]); split2(v.y*scale, hb[1], lb[1]);
        split2(v.z*scale, hb[2], lb[2]); split2(v.w*scale, hb[3], lb[3]);
        *(uint2*)&qh[(size_t)row*2048 + col] = *(uint2*)hb;
        *(uint2*)&ql[(size_t)row*2048 + col] = *(uint2*)lb;
    } else {
        split2(v.x, hb[0], lb[0]); split2(v.y, hb[1], lb[1]);
        split2(v.z, hb[2], lb[2]); split2(v.w, hb[3], lb[3]);
        *(uint2*)&kh[(size_t)row*2048 + col - 2048] = *(uint2*)hb;
        *(uint2*)&kl[(size_t)row*2048 + col - 2048] = *(uint2*)lb;
    }
}

// ---------------- v prep: transpose V per (b,h) -> [dim][keys] splits -------
__global__ __launch_bounds__(256)
void v_prep(const float* __restrict__ qkv,
            __nv_bfloat16* __restrict__ vth, __nv_bfloat16* __restrict__ vtl)
{
    __shared__ float tile[32][33];
    const int tx = threadIdx.x, ty = threadIdx.y;
    const int z = blockIdx.z, b = z >> 4, h = z & 15;
    const int key0 = blockIdx.x * 32, d0 = blockIdx.y * 32;
    #pragma unroll
    for (int i = 0; i < 4; i++) {
        int key = key0 + ty + 8*i;
        tile[ty + 8*i][tx] = qkv[(size_t)(b*2048 + key)*6144 + 4096 + h*128 + d0 + tx];
    }
    __syncthreads();
    #pragma unroll
    for (int i = 0; i < 4; i++) {
        int d = d0 + ty + 8*i;
        float v = tile[tx][ty + 8*i];
        __nv_bfloat16 hh, ll; split2(v, hh, ll);
        size_t o = ((size_t)z*128 + d)*2048 + key0 + tx;
        vth[o] = hh; vtl[o] = ll;
    }
}

// ---------------- LayerNorm: out = LN(A [+ Ad]) * g + b ; + bf16 split ------
__global__ __launch_bounds__(256)
void ln_kernel(const float* __restrict__ A, const float* __restrict__ Ad,
               const float* __restrict__ g, const float* __restrict__ bb,
               float* __restrict__ out, __nv_bfloat16* __restrict__ oh,
               __nv_bfloat16* __restrict__ ol)
{
    const int row = blockIdx.x, t = threadIdx.x;
    const float* a = A + (size_t)row * D_;
    float4 v[2];
    float s = 0.f, ss = 0.f;
    #pragma unroll
    for (int i = 0; i < 2; i++) {
        int idx = (i*256 + t) * 4;
        float4 x = *(const float4*)&a[idx];
        if (Ad) {
            float4 y = *(const float4*)&Ad[(size_t)row*D_ + idx];
            x.x += y.x; x.y += y.y; x.z += y.z; x.w += y.w;
        }
        v[i] = x;
        s  += x.x + x.y + x.z + x.w;
        ss += x.x*x.x + x.y*x.y + x.z*x.z + x.w*x.w;
    }
    #pragma unroll
    for (int off = 16; off; off >>= 1) {
        s  += __shfl_xor_sync(0xffffffffu, s,  off);
        ss += __shfl_xor_sync(0xffffffffu, ss, off);
    }
    __shared__ float sb[8], ssb[8];
    if ((t & 31) == 0) { sb[t>>5] = s; ssb[t>>5] = ss; }
    __syncthreads();
    float st = 0.f, sst = 0.f;
    #pragma unroll
    for (int i = 0; i < 8; i++) { st += sb[i]; sst += ssb[i]; }
    float mean = st * (1.f / D_);
    float var  = sst * (1.f / D_) - mean * mean;
    float rstd = rsqrtf(var + 1e-5f);
    #pragma unroll
    for (int i = 0; i < 2; i++) {
        int idx = (i*256 + t) * 4;
        float4 gg  = *(const float4*)&g[idx];
        float4 bbv = *(const float4*)&bb[idx];
        float4 x = v[i], o;
        o.x = (x.x - mean)*rstd*gg.x + bbv.x;
        o.y = (x.y - mean)*rstd*gg.y + bbv.y;
        o.z = (x.z - mean)*rstd*gg.z + bbv.z;
        o.w = (x.w - mean)*rstd*gg.w + bbv.w;
        if (out) *(float4*)&out[(size_t)row*D_ + idx] = o;
        __nv_bfloat16 hb[4], lb[4];
        split2(o.x, hb[0], lb[0]); split2(o.y, hb[1], lb[1]);
        split2(o.z, hb[2], lb[2]); split2(o.w, hb[3], lb[3]);
        *(uint2*)&oh[(size_t)row*D_ + idx] = *(uint2*)hb;
        *(uint2*)&ol[(size_t)row*D_ + idx] = *(uint2*)lb;
    }
}

// ---------------- persona vector: pers[j] = pemb[t]@dw[D:2D, j] + db[j] -----
__global__ __launch_bounds__(256)
void pers_kernel(const float* __restrict__ pemb, const int* __restrict__ trait,
                 const float* __restrict__ dw, const float* __restrict__ db,
                 float* __restrict__ out)
{
    int j = blockIdx.x * 256 + threadIdx.x;
    int t = trait[0];
    const float* pe = pemb + (size_t)t * D_;
    float acc = db[j];
    for (int i = 0; i < D_; ++i)
        acc = fmaf(pe[i], dw[(size_t)(D_ + i) * D_ + j], acc);
    out[j] = acc;
}

// ---------------- launch ----------------------------------------------------
extern "C" void kernel_launch(void* const* d_in, const int* in_sizes, int n_in,
                              void* d_out, int out_size)
{
    const float* x     = (const float*)d_in[0];
    const int*   mask  = (const int*)  d_in[1];
    const int*   trait = (const int*)  d_in[2];
    const float* wq    = (const float*)d_in[3];
    const float* wk    = (const float*)d_in[4];
    const float* wv    = (const float*)d_in[5];
    const float* wo    = (const float*)d_in[6];
    const float* g1    = (const float*)d_in[7];
    const float* b1    = (const float*)d_in[8];
    const float* g2    = (const float*)d_in[9];
    const float* b2    = (const float*)d_in[10];
    const float* rw1   = (const float*)d_in[11];
    const float* rb1   = (const float*)d_in[12];
    const float* rw2   = (const float*)d_in[13];
    const float* rb2   = (const float*)d_in[14];
    const float* rg    = (const float*)d_in[15];
    const float* rb    = (const float*)d_in[16];
    const float* pemb  = (const float*)d_in[17];
    const float* dw    = (const float*)d_in[18];
    const float* db    = (const float*)d_in[19];
    const float* wgam  = (const float*)d_in[20];
    const float* wbet  = (const float*)d_in[21];
    const float* mw1   = (const float*)d_in[22];
    const float* mb1   = (const float*)d_in[23];
    const float* mw2   = (const float*)d_in[24];
    const float* mb2   = (const float*)d_in[25];
    float* out = (float*)d_out;

    static float *pqkv=0,*px2=0,*pr=0,*ph2=0,*ph3=0,*ppers=0;
    static __nv_bfloat16 *pah=0,*pal=0,*pth=0,*ptl=0,*pwh=0,*pwl=0;
    static __nv_bfloat16 *pqsh=0,*pqsl=0,*pksh=0,*pksl=0,*pvth=0,*pvtl=0;
    static bool inited = false;
    if (!inited) {
        cudaGetSymbolAddress((void**)&pqkv, g_qkv);
        cudaGetSymbolAddress((void**)&px2, g_x2);
        cudaGetSymbolAddress((void**)&pr,  g_r);
        cudaGetSymbolAddress((void**)&ph2, g_h2);
        cudaGetSymbolAddress((void**)&ph3, g_h3);
        cudaGetSymbolAddress((void**)&ppers, g_pers);
        cudaGetSymbolAddress((void**)&pah, g_ah);
        cudaGetSymbolAddress((void**)&pal, g_al);
        cudaGetSymbolAddress((void**)&pth, g_th);
        cudaGetSymbolAddress((void**)&ptl, g_tl);
        cudaGetSymbolAddress((void**)&pwh, g_wh);
        cudaGetSymbolAddress((void**)&pwl, g_wl);
        cudaGetSymbolAddress((void**)&pqsh, g_qsh);
        cudaGetSymbolAddress((void**)&pqsl, g_qsl);
        cudaGetSymbolAddress((void**)&pksh, g_ksh);
        cudaGetSymbolAddress((void**)&pksl, g_ksl);
        cudaGetSymbolAddress((void**)&pvth, g_vth);
        cudaGetSymbolAddress((void**)&pvtl, g_vtl);
        cudaFuncSetAttribute(tbgemm<false,false,false,false>, cudaFuncAttributeMaxDynamicSharedMemorySize, TG_SMEM);
        cudaFuncSetAttribute(tbgemm<false,false,true,false>,  cudaFuncAttributeMaxDynamicSharedMemorySize, TG_SMEM);
        cudaFuncSetAttribute(tbgemm<true,true,false,true>,    cudaFuncAttributeMaxDynamicSharedMemorySize, TG_SMEM);
        cudaFuncSetAttribute(tbgemm<false,true,false,false>,  cudaFuncAttributeMaxDynamicSharedMemorySize, TG_SMEM);
        cudaFuncSetAttribute(tbgemm<false,true,true,false>,   cudaFuncAttributeMaxDynamicSharedMemorySize, TG_SMEM);
        cudaFuncSetAttribute(flash_attn, cudaFuncAttributeMaxDynamicSharedMemorySize, FA_SMEM);
        inited = true;
    }

    const dim3 blk(256);
    const dim3 tb(32, 8);

    // ---- weight prep ----
    transpose_split<<<dim3(64, 64),  tb>>>(wq,  2048, 2048, pwh+OWQ,  pwl+OWQ);
    transpose_split<<<dim3(64, 64),  tb>>>(wk,  2048, 2048, pwh+OWK,  pwl+OWK);
    transpose_split<<<dim3(64, 64),  tb>>>(wv,  2048, 2048, pwh+OWV,  pwl+OWV);
    transpose_split<<<dim3(64, 64),  tb>>>(wo,  2048, 2048, pwh+OWO,  pwl+OWO);
    transpose_split<<<dim3(128, 64), tb>>>(rw1, 2048, 4096, pwh+ORW1, pwl+ORW1);
    transpose_split<<<dim3(64, 128), tb>>>(rw2, 4096, 2048, pwh+ORW2, pwl+ORW2);
    transpose_split<<<dim3(64, 64),  tb>>>(dw,  2048, 2048, pwh+ODW,  pwl+ODW);
    transpose_split<<<dim3(256, 64), tb>>>(mw1, 2048, 8192, pwh+OMW1, pwl+OMW1);
    transpose_split<<<dim3(64, 256), tb>>>(mw2, 8192, 2048, pwh+OMW2, pwl+OMW2);
    pers_kernel<<<D_/256, blk>>>(pemb, trait, dw, db, ppers);

    // 1) h = LN1(x) -> bf16 split
    ln_kernel<<<M_, blk>>>(x, nullptr, g1, b1, nullptr, pah, pal);
    // 2) qkv = h @ [wq|wk|wv]
    tbgemm<false,false,false,false><<<dim3(48,32), blk, TG_SMEM>>>(
        pah,pal, pwh+OWQ,pwl+OWQ, nullptr,nullptr, pqkv,nullptr,nullptr, M_, 3*D_, D_);
    // 3) attention prep (bf16 splits)
    qk_prep<<<16384, blk>>>(pqkv, pqsh, pqsl, pksh, pksl);
    v_prep<<<dim3(64, 4, 32), tb>>>(pqkv, pvth, pvtl);
    // 4) fused flash attention -> pah/pal
    flash_attn<<<dim3(16, 32), blk, FA_SMEM>>>(
        pqsh, pqsl, pksh, pksl, pvth, pvtl, mask, pah, pal);
    // 5) x2 = x + attn_out @ wo
    tbgemm<false,false,true,false><<<dim3(16,32), blk, TG_SMEM>>>(
        pah,pal, pwh+OWO,pwl+OWO, nullptr,x, px2,nullptr,nullptr, M_, D_, D_);
    // 6) h2 = LN2(x2)
    ln_kernel<<<M_, blk>>>(px2, nullptr, g2, b2, ph2, pah, pal);
    // 7) t = gelu(h2 @ rw1 + rb1)
    tbgemm<true,true,false,true><<<dim3(32,32), blk, TG_SMEM>>>(
        pah,pal, pwh+ORW1,pwl+ORW1, rb1,nullptr, nullptr,pth,ptl, M_, 2*D_, D_);
    // 8) r = t @ rw2 + rb2
    tbgemm<false,true,false,false><<<dim3(16,32), blk, TG_SMEM>>>(
        pth,ptl, pwh+ORW2,pwl+ORW2, rb2,nullptr, pr,nullptr,nullptr, M_, D_, 2*D_);
    // 9) h3 = LN(h2 + r)
    ln_kernel<<<M_, blk>>>(ph2, pr, rg, rb, ph3, pah, pal);
    // 10) dec = h3 @ dw[:D] + pers
    tbgemm<false,true,false,false><<<dim3(16,32), blk, TG_SMEM>>>(
        pah,pal, pwh+ODW,pwl+ODW, ppers,nullptr, pqkv,nullptr,nullptr, M_, D_, D_);
    // 11) h4 = LN(h3 + dec)
    ln_kernel<<<M_, blk>>>(ph3, pqkv, wgam, wbet, nullptr, pah, pal);
    // 12) t = gelu(h4 @ mw1 + mb1)
    tbgemm<true,true,false,true><<<dim3(64,32), blk, TG_SMEM>>>(
        pah,pal, pwh+OMW1,pwl+OMW1, mb1,nullptr, nullptr,pth,ptl, M_, 4*D_, D_);
    // 13) out = x2 + t @ mw2 + mb2
    tbgemm<false,true,true,false><<<dim3(16,32), blk, TG_SMEM>>>(
        pth,ptl, pwh+OMW2,pwl+OMW2, mb2,px2, out,nullptr,nullptr, M_, D_, 4*D_);
}

// round 13
// speedup vs baseline: 1.0897x; 1.0609x over previous
#include <cuda_runtime.h>
#include <cuda_bf16.h>
#include <math.h>
#include <stdint.h>

#define B_  2
#define S_  2048
#define D_  2048
#define H_  16
#define HD_ 128
#define M_  (B_*S_)   // 4096 rows

// ---------------- scratch (static device globals; allocation-free) ----------
__device__ __align__(128) float g_qkv[(size_t)M_*3*D_];   // [M][6144] q|k|v
__device__ __align__(128) float g_x2 [(size_t)M_*D_];
__device__ __align__(128) float g_r  [(size_t)M_*D_];
__device__ __align__(128) float g_h2 [(size_t)M_*D_];
__device__ __align__(128) float g_h3 [(size_t)M_*D_];
__device__ __align__(128) float g_pers[D_];
__device__ __align__(128) float g_ppart[32*D_];

// bf16 hi/lo activation scratch
__device__ __align__(128) __nv_bfloat16 g_ah[(size_t)M_*D_];
__device__ __align__(128) __nv_bfloat16 g_al[(size_t)M_*D_];
__device__ __align__(128) __nv_bfloat16 g_th[(size_t)M_*4*D_];
__device__ __align__(128) __nv_bfloat16 g_tl[(size_t)M_*4*D_];

// attention scratch (bf16 splits only)
__device__ __align__(128) __nv_bfloat16 g_qsh[(size_t)M_*D_];
__device__ __align__(128) __nv_bfloat16 g_qsl[(size_t)M_*D_];
__device__ __align__(128) __nv_bfloat16 g_ksh[(size_t)M_*D_];
__device__ __align__(128) __nv_bfloat16 g_ksl[(size_t)M_*D_];
__device__ __align__(128) __nv_bfloat16 g_vth[(size_t)32*HD_*S_];   // [bh][128][2048]
__device__ __align__(128) __nv_bfloat16 g_vtl[(size_t)32*HD_*S_];

// bf16 hi/lo transposed weights, packed offsets into one pool: [N,K] row-major
#define OWQ  ((size_t)0)
#define OWK  ((size_t)4194304)
#define OWV  ((size_t)8388608)
#define OWO  ((size_t)12582912)
#define ORW1 ((size_t)16777216)
#define ORW2 ((size_t)25165824)
#define ODW  ((size_t)33554432)
#define OMW1 ((size_t)37748736)
#define OMW2 ((size_t)54525952)
#define WTOT ((size_t)71303168)
__device__ __align__(128) __nv_bfloat16 g_wh[WTOT];
__device__ __align__(128) __nv_bfloat16 g_wl[WTOT];

// ---------------- helpers ----------------------------------------------------
__device__ __forceinline__ void split2(float v, __nv_bfloat16& h, __nv_bfloat16& l) {
    h = __float2bfloat16(v);
    l = __float2bfloat16(v - __bfloat162float(h));
}
__device__ __forceinline__ uint32_t smem_u32(const void* p) {
    uint32_t a;
    asm("{ .reg .u64 t; cvta.to.shared.u64 t, %1; cvt.u32.u64 %0, t; }" : "=r"(a) : "l"(p));
    return a;
}
__device__ __forceinline__ uint32_t packbf2(float a, float b) {
    __nv_bfloat162 p;
    p.x = __float2bfloat16(a); p.y = __float2bfloat16(b);
    return *(uint32_t*)&p;
}

#define MMA16816(d, a, b) \
    asm volatile("mma.sync.aligned.m16n8k16.row.col.f32.bf16.bf16.f32 " \
        "{%0,%1,%2,%3}, {%4,%5,%6,%7}, {%8,%9}, {%0,%1,%2,%3};" \
        : "+f"((d)[0]), "+f"((d)[1]), "+f"((d)[2]), "+f"((d)[3]) \
        : "r"((a)[0]), "r"((a)[1]), "r"((a)[2]), "r"((a)[3]), "r"((b)[0]), "r"((b)[1]))

#define LDMX4(d, addr) \
    asm volatile("ldmatrix.sync.aligned.m8n8.x4.shared.b16 {%0,%1,%2,%3}, [%4];" \
        : "=r"((d)[0]), "=r"((d)[1]), "=r"((d)[2]), "=r"((d)[3]) : "r"(addr))

__device__ __forceinline__ void cp16(uint32_t dst, const void* src) {
    asm volatile("cp.async.cg.shared.global [%0], [%1], 16;" :: "r"(dst), "l"(src));
}
#define CP_COMMIT() asm volatile("cp.async.commit_group;" ::: "memory")
#define CP_WAIT1()  asm volatile("cp.async.wait_group 1;" ::: "memory")

__device__ __forceinline__ float gelu1(float v) {
    return 0.5f * v * (1.0f + erff(v * 0.70710678118654752f));
}

// ================= HMMA GEMM: 128x256 tile, 512 thr, KC=64, 2-stage ==========
// warp tile 32x64 (acc 64 regs/thread). Traffic factor (1/128 + 1/256).
#define LDE 72
#define AME (128*LDE)                  // 9216 elems
#define BME (256*LDE)                  // 18432 elems
#define STAGE_B ((2*AME + 2*BME)*2)    // 110592 bytes
#define TG_SMEM (2*STAGE_B)            // 221184 bytes

template<bool GELU, bool BIAS, bool RES, bool OUT_BF16>
__global__ __launch_bounds__(512, 1)
void tbgemm(const __nv_bfloat16* __restrict__ Ah, const __nv_bfloat16* __restrict__ Al,
            const __nv_bfloat16* __restrict__ Bh, const __nv_bfloat16* __restrict__ Bl,
            const float* __restrict__ bias, const float* __restrict__ res,
            float* __restrict__ Cf, __nv_bfloat16* __restrict__ Ch, __nv_bfloat16* __restrict__ Cl,
            int M, int N, int K)
{
    extern __shared__ __nv_bfloat16 sm[];
    const int tid  = threadIdx.x;
    const int lane = tid & 31;
    const int warp = tid >> 5;         // 0..15
    const int wm = warp & 3;           // 4 m-warps, 32 rows each
    const int wn = warp >> 2;          // 4 n-warps, 64 cols each
    const int m0 = blockIdx.y * 128;
    const int n0 = blockIdx.x * 256;
    const int g  = lane >> 2;
    const int t  = lane & 3;
    const uint32_t sbase = smem_u32(sm);
    const int jq = lane >> 3;
    const int jr = lane & 7;

    float acc[2][8][4];
    #pragma unroll
    for (int m = 0; m < 2; m++)
        #pragma unroll
        for (int n = 0; n < 8; n++)
            #pragma unroll
            for (int e = 0; e < 4; e++) acc[m][n][e] = 0.f;

    auto issue = [&](int c, int buf) {
        const int k0 = c << 6;
        const uint32_t b0 = sbase + (uint32_t)buf * STAGE_B;
        #pragma unroll
        for (int i = 0; i < 2; i++) {          // A: 128 rows x 64, hi+lo
            int v = i * 512 + tid;
            int r = v >> 3, q = v & 7;
            uint32_t so = (uint32_t)(r * LDE + q * 8) * 2;
            size_t ga = (size_t)(m0 + r) * K + k0 + q * 8;
            cp16(b0 + so,          Ah + ga);
            cp16(b0 + AME*2 + so,  Al + ga);
        }
        #pragma unroll
        for (int i = 0; i < 4; i++) {          // B: 256 rows x 64, hi+lo
            int v = i * 512 + tid;
            int r = v >> 3, q = v & 7;
            uint32_t so = (uint32_t)(r * LDE + q * 8) * 2;
            size_t gb = (size_t)(n0 + r) * K + k0 + q * 8;
            cp16(b0 + 2*AME*2 + so,          Bh + gb);
            cp16(b0 + (2*AME + BME)*2 + so,  Bl + gb);
        }
        CP_COMMIT();
    };

    const int nc = K >> 6;
    issue(0, 0);
    if (nc > 1) issue(1, 1); else CP_COMMIT();

    for (int c = 0; c < nc; c++) {
        const int buf = c & 1;
        CP_WAIT1();
        __syncthreads();

        const uint32_t A_h = sbase + (uint32_t)buf * STAGE_B;
        const uint32_t A_l = A_h + AME*2;
        const uint32_t B_h = A_h + 2*AME*2;
        const uint32_t B_l = A_h + (2*AME + BME)*2;

        #pragma unroll
        for (int kk = 0; kk < 64; kk += 16) {
            uint32_t ah[2][4], al[2][4];
            #pragma unroll
            for (int m = 0; m < 2; m++) {
                int row = wm * 32 + m * 16 + (jq & 1) * 8 + jr;
                uint32_t off = (uint32_t)(row * LDE + kk + (jq >> 1) * 8) * 2;
                LDMX4(ah[m], A_h + off);
                LDMX4(al[m], A_l + off);
            }
            #pragma unroll
            for (int np = 0; np < 4; np++) {
                int nrow = wn * 64 + np * 16 + (jq >> 1) * 8 + jr;
                uint32_t boff = (uint32_t)(nrow * LDE + kk + (jq & 1) * 8) * 2;
                uint32_t bh[4], bl[4];
                LDMX4(bh, B_h + boff);
                LDMX4(bl, B_l + boff);
                #pragma unroll
                for (int m = 0; m < 2; m++) {
                    MMA16816(acc[m][2*np],   ah[m], &bh[0]);
                    MMA16816(acc[m][2*np],   ah[m], &bl[0]);
                    MMA16816(acc[m][2*np],   al[m], &bh[0]);
                    MMA16816(acc[m][2*np+1], ah[m], &bh[2]);
                    MMA16816(acc[m][2*np+1], ah[m], &bl[2]);
                    MMA16816(acc[m][2*np+1], al[m], &bh[2]);
                }
            }
        }
        __syncthreads();
        if (c + 2 < nc) issue(c + 2, buf); else CP_COMMIT();
    }

    #pragma unroll
    for (int m = 0; m < 2; m++) {
        #pragma unroll
        for (int n = 0; n < 8; n++) {
            int col = n0 + wn * 64 + n * 8 + t * 2;
            #pragma unroll
            for (int half = 0; half < 2; half++) {
                int row = m0 + wm * 32 + m * 16 + g + half * 8;
                float v0 = acc[m][n][half * 2 + 0];
                float v1 = acc[m][n][half * 2 + 1];
                if (BIAS) { v0 += bias[col]; v1 += bias[col + 1]; }
                if (GELU) { v0 = gelu1(v0); v1 = gelu1(v1); }
                size_t off = (size_t)row * N + col;
                if (RES) {
                    float2 r2 = *(const float2*)&res[off];
                    v0 += r2.x; v1 += r2.y;
                }
                if (OUT_BF16) {
                    __nv_bfloat16 h0, l0, h1, l1;
                    split2(v0, h0, l0); split2(v1, h1, l1);
                    __nv_bfloat162 hp, lp;
                    hp.x = h0; hp.y = h1; lp.x = l0; lp.y = l1;
                    *(__nv_bfloat162*)&Ch[off] = hp;
                    *(__nv_bfloat162*)&Cl[off] = lp;
                } else {
                    *(float2*)&Cf[off] = make_float2(v0, v1);
                }
            }
        }
    }
}

// ================= fused HMMA flash attention (unchanged) ====================
#define LQ 136
#define LV 72
#define FQH 0
#define FQL (128*LQ)
#define FST0 (2*128*LQ)
#define FKH 0
#define FKL (64*LQ)
#define FVH (2*64*LQ)
#define FVL (FVH + 128*LV)
#define FSTG (FVL + 128*LV)
#define FA_SMEM ((FST0 + 2*FSTG)*2)    // 212992 bytes

__global__ __launch_bounds__(256)
void flash_attn(const __nv_bfloat16* __restrict__ Qh, const __nv_bfloat16* __restrict__ Ql,
                const __nv_bfloat16* __restrict__ Kh, const __nv_bfloat16* __restrict__ Kl,
                const __nv_bfloat16* __restrict__ Vth, const __nv_bfloat16* __restrict__ Vtl,
                const int* __restrict__ mask,
                __nv_bfloat16* __restrict__ Oh, __nv_bfloat16* __restrict__ Ol)
{
    extern __shared__ __nv_bfloat16 fsm[];
    const int tid  = threadIdx.x;
    const int lane = tid & 31;
    const int warp = tid >> 5;
    const int g  = lane >> 2;
    const int t  = lane & 3;
    const int jq = lane >> 3;
    const int jr = lane & 7;
    const uint32_t sb = smem_u32(fsm);
    const int z = blockIdx.y, b = z >> 4, h = z & 15;
    const int q0 = blockIdx.x * 128;
    const size_t qrow0 = (size_t)b * 2048 + q0;

    {
        #pragma unroll
        for (int i = 0; i < 8; i++) {
            int v = i * 256 + tid;
            int r = v >> 4, q = v & 15;
            uint32_t so = (uint32_t)(r * LQ + q * 8) * 2;
            size_t gq = (qrow0 + r) * 2048 + h * 128 + q * 8;
            cp16(sb + (FQH)*2 + so, Qh + gq);
            cp16(sb + (FQL)*2 + so, Ql + gq);
        }
        CP_COMMIT();
    }

    auto issue_kv = [&](int kt, int s) {
        const uint32_t b0 = sb + (uint32_t)(FST0 + s * FSTG) * 2;
        #pragma unroll
        for (int i = 0; i < 4; i++) {
            int v = i * 256 + tid;
            int r = v >> 4, q = v & 15;
            uint32_t so = (uint32_t)(r * LQ + q * 8) * 2;
            size_t gk = ((size_t)b * 2048 + kt * 64 + r) * 2048 + h * 128 + q * 8;
            cp16(b0 + (FKH)*2 + so, Kh + gk);
            cp16(b0 + (FKL)*2 + so, Kl + gk);
        }
        #pragma unroll
        for (int i = 0; i < 4; i++) {
            int v = i * 256 + tid;
            int d = v >> 3, q = v & 7;
            uint32_t so = (uint32_t)(d * LV + q * 8) * 2;
            size_t gv = ((size_t)z * 128 + d) * 2048 + kt * 64 + q * 8;
            cp16(b0 + (FVH)*2 + so, Vth + gv);
            cp16(b0 + (FVL)*2 + so, Vtl + gv);
        }
        CP_COMMIT();
    };

    issue_kv(0, 0);
    issue_kv(1, 1);

    const int q0w = warp * 16;
    float accO[16][4];
    #pragma unroll
    for (int n = 0; n < 16; n++)
        #pragma unroll
        for (int e = 0; e < 4; e++) accO[n][e] = 0.f;
    float m0v = -1e30f, m1v = -1e30f, l0v = 0.f, l1v = 0.f;

    for (int kt = 0; kt < 32; kt++) {
        CP_WAIT1();
        __syncthreads();
        const int s = kt & 1;
        const uint32_t K_h = sb + (uint32_t)(FST0 + s * FSTG + FKH) * 2;
        const uint32_t K_l = sb + (uint32_t)(FST0 + s * FSTG + FKL) * 2;
        const uint32_t V_h = sb + (uint32_t)(FST0 + s * FSTG + FVH) * 2;
        const uint32_t V_l = sb + (uint32_t)(FST0 + s * FSTG + FVL) * 2;

        float sc[8][4];
        #pragma unroll
        for (int n = 0; n < 8; n++)
            #pragma unroll
            for (int e = 0; e < 4; e++) sc[n][e] = 0.f;
        #pragma unroll
        for (int kc = 0; kc < 8; kc++) {
            int arow = q0w + (jq & 1) * 8 + jr;
            uint32_t aoff = (uint32_t)(arow * LQ + kc * 16 + (jq >> 1) * 8) * 2;
            uint32_t qh_[4], ql_[4];
            LDMX4(qh_, sb + FQH*2 + aoff);
            LDMX4(ql_, sb + FQL*2 + aoff);
            #pragma unroll
            for (int ng = 0; ng < 4; ng++) {
                int krow = ng * 16 + (jq >> 1) * 8 + jr;
                uint32_t boff = (uint32_t)(krow * LQ + kc * 16 + (jq & 1) * 8) * 2;
                uint32_t kh_[4], kl_[4];
                LDMX4(kh_, K_h + boff);
                LDMX4(kl_, K_l + boff);
                MMA16816(sc[2*ng],   qh_, &kh_[0]);
                MMA16816(sc[2*ng],   qh_, &kl_[0]);
                MMA16816(sc[2*ng],   ql_, &kh_[0]);
                MMA16816(sc[2*ng+1], qh_, &kh_[2]);
                MMA16816(sc[2*ng+1], qh_, &kl_[2]);
                MMA16816(sc[2*ng+1], ql_, &kh_[2]);
            }
        }

        const int kb = b * 2048 + kt * 64;
        #pragma unroll
        for (int j = 0; j < 8; j++) {
            if (mask[kb + 8*j + 2*t]     == 0) { sc[j][0] = -1e30f; sc[j][2] = -1e30f; }
            if (mask[kb + 8*j + 2*t + 1] == 0) { sc[j][1] = -1e30f; sc[j][3] = -1e30f; }
        }
        float rm0 = -1e30f, rm1 = -1e30f;
        #pragma unroll
        for (int j = 0; j < 8; j++) {
            rm0 = fmaxf(rm0, fmaxf(sc[j][0], sc[j][1]));
            rm1 = fmaxf(rm1, fmaxf(sc[j][2], sc[j][3]));
        }
        rm0 = fmaxf(rm0, __shfl_xor_sync(0xffffffffu, rm0, 1));
        rm0 = fmaxf(rm0, __shfl_xor_sync(0xffffffffu, rm0, 2));
        rm1 = fmaxf(rm1, __shfl_xor_sync(0xffffffffu, rm1, 1));
        rm1 = fmaxf(rm1, __shfl_xor_sync(0xffffffffu, rm1, 2));
        float mn0 = fmaxf(m0v, rm0), mn1 = fmaxf(m1v, rm1);
        float c0 = __expf(m0v - mn0), c1 = __expf(m1v - mn1);
        float p[8][4], rs0 = 0.f, rs1 = 0.f;
        #pragma unroll
        for (int j = 0; j < 8; j++) {
            p[j][0] = __expf(sc[j][0] - mn0);
            p[j][1] = __expf(sc[j][1] - mn0);
            p[j][2] = __expf(sc[j][2] - mn1);
            p[j][3] = __expf(sc[j][3] - mn1);
            rs0 += p[j][0] + p[j][1];
            rs1 += p[j][2] + p[j][3];
        }
        rs0 += __shfl_xor_sync(0xffffffffu, rs0, 1);
        rs0 += __shfl_xor_sync(0xffffffffu, rs0, 2);
        rs1 += __shfl_xor_sync(0xffffffffu, rs1, 1);
        rs1 += __shfl_xor_sync(0xffffffffu, rs1, 2);
        l0v = l0v * c0 + rs0;  m0v = mn0;
        l1v = l1v * c1 + rs1;  m1v = mn1;
        #pragma unroll
        for (int n = 0; n < 16; n++) {
            accO[n][0] *= c0; accO[n][1] *= c0;
            accO[n][2] *= c1; accO[n][3] *= c1;
        }

        #pragma unroll
        for (int kc = 0; kc < 4; kc++) {
            uint32_t a_h[4], a_l[4];
            #pragma unroll
            for (int q = 0; q < 2; q++) {
                float v0 = p[2*kc+q][0], v1 = p[2*kc+q][1];
                float v2 = p[2*kc+q][2], v3 = p[2*kc+q][3];
                uint32_t h01 = packbf2(v0, v1), h23 = packbf2(v2, v3);
                __nv_bfloat162 hb01 = *(__nv_bfloat162*)&h01;
                __nv_bfloat162 hb23 = *(__nv_bfloat162*)&h23;
                uint32_t l01 = packbf2(v0 - __bfloat162float(hb01.x),
                                       v1 - __bfloat162float(hb01.y));
                uint32_t l23 = packbf2(v2 - __bfloat162float(hb23.x),
                                       v3 - __bfloat162float(hb23.y));
                a_h[2*q+0] = h01; a_h[2*q+1] = h23;
                a_l[2*q+0] = l01; a_l[2*q+1] = l23;
            }
            #pragma unroll
            for (int ng = 0; ng < 8; ng++) {
                int drow = ng * 16 + (jq >> 1) * 8 + jr;
                uint32_t boff = (uint32_t)(drow * LV + kc * 16 + (jq & 1) * 8) * 2;
                uint32_t vh_[4], vl_[4];
                LDMX4(vh_, V_h + boff);
                LDMX4(vl_, V_l + boff);
                MMA16816(accO[2*ng],   a_h, &vh_[0]);
                MMA16816(accO[2*ng],   a_h, &vl_[0]);
                MMA16816(accO[2*ng],   a_l, &vh_[0]);
                MMA16816(accO[2*ng+1], a_h, &vh_[2]);
                MMA16816(accO[2*ng+1], a_h, &vl_[2]);
                MMA16816(accO[2*ng+1], a_l, &vh_[2]);
            }
        }

        __syncthreads();
        if (kt + 2 < 32) issue_kv(kt + 2, s); else CP_COMMIT();
    }

    float inv0 = 1.0f / l0v, inv1 = 1.0f / l1v;
    const size_t r0 = qrow0 + q0w + g;
    const size_t r1 = r0 + 8;
    #pragma unroll
    for (int n = 0; n < 16; n++) {
        int col = h * 128 + n * 8 + t * 2;
        float v0 = accO[n][0] * inv0, v1 = accO[n][1] * inv0;
        float v2 = accO[n][2] * inv1, v3 = accO[n][3] * inv1;
        __nv_bfloat16 h0,l0,h1,l1,h2,l2,h3,l3;
        split2(v0,h0,l0); split2(v1,h1,l1); split2(v2,h2,l2); split2(v3,h3,l3);
        __nv_bfloat162 hp0, lp0, hp1, lp1;
        hp0.x=h0; hp0.y=h1; lp0.x=l0; lp0.y=l1;
        hp1.x=h2; hp1.y=h3; lp1.x=l2; lp1.y=l3;
        *(__nv_bfloat162*)&Oh[r0*2048 + col] = hp0;
        *(__nv_bfloat162*)&Ol[r0*2048 + col] = lp0;
        *(__nv_bfloat162*)&Oh[r1*2048 + col] = hp1;
        *(__nv_bfloat162*)&Ol[r1*2048 + col] = lp1;
    }
}

// ---------------- transpose + bf16 split: W[K,N] -> Th/Tl[N,K] --------------
__global__ __launch_bounds__(256)
void transpose_split(const float* __restrict__ W, int K, int N,
                     __nv_bfloat16* __restrict__ Th, __nv_bfloat16* __restrict__ Tl)
{
    __shared__ float tile[32][33];
    const int tx = threadIdx.x, ty = threadIdx.y;
    const int n0 = blockIdx.x * 32, k0 = blockIdx.y * 32;
    #pragma unroll
    for (int i = 0; i < 4; i++)
        tile[ty + 8*i][tx] = W[(size_t)(k0 + ty + 8*i) * N + n0 + tx];
    __syncthreads();
    #pragma unroll
    for (int i = 0; i < 4; i++) {
        float v = tile[tx][ty + 8*i];
        __nv_bfloat16 h, l; split2(v, h, l);
        size_t o = (size_t)(n0 + ty + 8*i) * K + k0 + tx;
        Th[o] = h; Tl[o] = l;
    }
}

// ---------------- qk prep: qkv fp32 -> Q(scaled)/K bf16 splits --------------
__global__ __launch_bounds__(256)
void qk_prep(const float* __restrict__ qkv,
             __nv_bfloat16* __restrict__ qh, __nv_bfloat16* __restrict__ ql,
             __nv_bfloat16* __restrict__ kh, __nv_bfloat16* __restrict__ kl)
{
    const float scale = 0.088388347648318447f;
    size_t e = ((size_t)blockIdx.x * 256 + threadIdx.x) * 4;
    int row = (int)(e >> 12);
    int col = (int)(e & 4095);
    float4 v = *(const float4*)&qkv[(size_t)row * 6144 + col];
    __nv_bfloat16 hb[4], lb[4];
    if (col < 2048) {
        split2(v.x*scale, hb[0], lb[0]); split2(v.y*scale, hb[1], lb[1]);
        split2(v.z*scale, hb[2], lb[2]); split2(v.w*scale, hb[3], lb[3]);
        *(uint2*)&qh[(size_t)row*2048 + col] = *(uint2*)hb;
        *(uint2*)&ql[(size_t)row*2048 + col] = *(uint2*)lb;
    } else {
        split2(v.x, hb[0], lb[0]); split2(v.y, hb[1], lb[1]);
        split2(v.z, hb[2], lb[2]); split2(v.w, hb[3], lb[3]);
        *(uint2*)&kh[(size_t)row*2048 + col - 2048] = *(uint2*)hb;
        *(uint2*)&kl[(size_t)row*2048 + col - 2048] = *(uint2*)lb;
    }
}

// ---------------- v prep: transpose V per (b,h) -> [dim][keys] splits -------
__global__ __launch_bounds__(256)
void v_prep(const float* __restrict__ qkv,
            __nv_bfloat16* __restrict__ vth, __nv_bfloat16* __restrict__ vtl)
{
    __shared__ float tile[32][33];
    const int tx = threadIdx.x, ty = threadIdx.y;
    const int z = blockIdx.z, b = z >> 4, h = z & 15;
    const int key0 = blockIdx.x * 32, d0 = blockIdx.y * 32;
    #pragma unroll
    for (int i = 0; i < 4; i++) {
        int key = key0 + ty + 8*i;
        tile[ty + 8*i][tx] = qkv[(size_t)(b*2048 + key)*6144 + 4096 + h*128 + d0 + tx];
    }
    __syncthreads();
    #pragma unroll
    for (int i = 0; i < 4; i++) {
        int d = d0 + ty + 8*i;
        float v = tile[tx][ty + 8*i];
        __nv_bfloat16 hh, ll; split2(v, hh, ll);
        size_t o = ((size_t)z*128 + d)*2048 + key0 + tx;
        vth[o] = hh; vtl[o] = ll;
    }
}

// ---------------- LayerNorm: out = LN(A [+ Ad]) * g + b ; + bf16 split ------
__global__ __launch_bounds__(256)
void ln_kernel(const float* __restrict__ A, const float* __restrict__ Ad,
               const float* __restrict__ g, const float* __restrict__ bb,
               float* __restrict__ out, __nv_bfloat16* __restrict__ oh,
               __nv_bfloat16* __restrict__ ol)
{
    const int row = blockIdx.x, t = threadIdx.x;
    const float* a = A + (size_t)row * D_;
    float4 v[2];
    float s = 0.f, ss = 0.f;
    #pragma unroll
    for (int i = 0; i < 2; i++) {
        int idx = (i*256 + t) * 4;
        float4 x = *(const float4*)&a[idx];
        if (Ad) {
            float4 y = *(const float4*)&Ad[(size_t)row*D_ + idx];
            x.x += y.x; x.y += y.y; x.z += y.z; x.w += y.w;
        }
        v[i] = x;
        s  += x.x + x.y + x.z + x.w;
        ss += x.x*x.x + x.y*x.y + x.z*x.z + x.w*x.w;
    }
    #pragma unroll
    for (int off = 16; off; off >>= 1) {
        s  += __shfl_xor_sync(0xffffffffu, s,  off);
        ss += __shfl_xor_sync(0xffffffffu, ss, off);
    }
    __shared__ float sb[8], ssb[8];
    if ((t & 31) == 0) { sb[t>>5] = s; ssb[t>>5] = ss; }
    __syncthreads();
    float st = 0.f, sst = 0.f;
    #pragma unroll
    for (int i = 0; i < 8; i++) { st += sb[i]; sst += ssb[i]; }
    float mean = st * (1.f / D_);
    float var  = sst * (1.f / D_) - mean * mean;
    float rstd = rsqrtf(var + 1e-5f);
    #pragma unroll
    for (int i = 0; i < 2; i++) {
        int idx = (i*256 + t) * 4;
        float4 gg  = *(const float4*)&g[idx];
        float4 bbv = *(const float4*)&bb[idx];
        float4 x = v[i], o;
        o.x = (x.x - mean)*rstd*gg.x + bbv.x;
        o.y = (x.y - mean)*rstd*gg.y + bbv.y;
        o.z = (x.z - mean)*rstd*gg.z + bbv.z;
        o.w = (x.w - mean)*rstd*gg.w + bbv.w;
        if (out) *(float4*)&out[(size_t)row*D_ + idx] = o;
        __nv_bfloat16 hb[4], lb[4];
        split2(o.x, hb[0], lb[0]); split2(o.y, hb[1], lb[1]);
        split2(o.z, hb[2], lb[2]); split2(o.w, hb[3], lb[3]);
        *(uint2*)&oh[(size_t)row*D_ + idx] = *(uint2*)hb;
        *(uint2*)&ol[(size_t)row*D_ + idx] = *(uint2*)lb;
    }
}

// ---------------- persona vector (2-stage, deterministic) -------------------
__global__ __launch_bounds__(256)
void pers_part(const float* __restrict__ pemb, const int* __restrict__ trait,
               const float* __restrict__ dw, float* __restrict__ part)
{
    int j = blockIdx.x * 256 + threadIdx.x;
    int seg = blockIdx.y;                       // 32 segments of 64 i's
    int tix = trait[0];
    const float* pe = pemb + (size_t)tix * D_;
    float acc = 0.f;
    int i0 = seg * 64;
    #pragma unroll 8
    for (int i = i0; i < i0 + 64; ++i)
        acc = fmaf(pe[i], dw[(size_t)(D_ + i) * D_ + j], acc);
    part[(size_t)seg * D_ + j] = acc;
}
__global__ __launch_bounds__(256)
void pers_reduce(const float* __restrict__ part, const float* __restrict__ db,
                 float* __restrict__ out)
{
    int j = blockIdx.x * 256 + threadIdx.x;
    float s = db[j];
    #pragma unroll
    for (int k = 0; k < 32; ++k) s += part[(size_t)k * D_ + j];
    out[j] = s;
}

// ---------------- launch ----------------------------------------------------
extern "C" void kernel_launch(void* const* d_in, const int* in_sizes, int n_in,
                              void* d_out, int out_size)
{
    const float* x     = (const float*)d_in[0];
    const int*   mask  = (const int*)  d_in[1];
    const int*   trait = (const int*)  d_in[2];
    const float* wq    = (const float*)d_in[3];
    const float* wk    = (const float*)d_in[4];
    const float* wv    = (const float*)d_in[5];
    const float* wo    = (const float*)d_in[6];
    const float* g1    = (const float*)d_in[7];
    const float* b1    = (const float*)d_in[8];
    const float* g2    = (const float*)d_in[9];
    const float* b2    = (const float*)d_in[10];
    const float* rw1   = (const float*)d_in[11];
    const float* rb1   = (const float*)d_in[12];
    const float* rw2   = (const float*)d_in[13];
    const float* rb2   = (const float*)d_in[14];
    const float* rg    = (const float*)d_in[15];
    const float* rb    = (const float*)d_in[16];
    const float* pemb  = (const float*)d_in[17];
    const float* dw    = (const float*)d_in[18];
    const float* db    = (const float*)d_in[19];
    const float* wgam  = (const float*)d_in[20];
    const float* wbet  = (const float*)d_in[21];
    const float* mw1   = (const float*)d_in[22];
    const float* mb1   = (const float*)d_in[23];
    const float* mw2   = (const float*)d_in[24];
    const float* mb2   = (const float*)d_in[25];
    float* out = (float*)d_out;

    static float *pqkv=0,*px2=0,*pr=0,*ph2=0,*ph3=0,*ppers=0,*pppart=0;
    static __nv_bfloat16 *pah=0,*pal=0,*pth=0,*ptl=0,*pwh=0,*pwl=0;
    static __nv_bfloat16 *pqsh=0,*pqsl=0,*pksh=0,*pksl=0,*pvth=0,*pvtl=0;
    static bool inited = false;
    if (!inited) {
        cudaGetSymbolAddress((void**)&pqkv, g_qkv);
        cudaGetSymbolAddress((void**)&px2, g_x2);
        cudaGetSymbolAddress((void**)&pr,  g_r);
        cudaGetSymbolAddress((void**)&ph2, g_h2);
        cudaGetSymbolAddress((void**)&ph3, g_h3);
        cudaGetSymbolAddress((void**)&ppers, g_pers);
        cudaGetSymbolAddress((void**)&pppart, g_ppart);
        cudaGetSymbolAddress((void**)&pah, g_ah);
        cudaGetSymbolAddress((void**)&pal, g_al);
        cudaGetSymbolAddress((void**)&pth, g_th);
        cudaGetSymbolAddress((void**)&ptl, g_tl);
        cudaGetSymbolAddress((void**)&pwh, g_wh);
        cudaGetSymbolAddress((void**)&pwl, g_wl);
        cudaGetSymbolAddress((void**)&pqsh, g_qsh);
        cudaGetSymbolAddress((void**)&pqsl, g_qsl);
        cudaGetSymbolAddress((void**)&pksh, g_ksh);
        cudaGetSymbolAddress((void**)&pksl, g_ksl);
        cudaGetSymbolAddress((void**)&pvth, g_vth);
        cudaGetSymbolAddress((void**)&pvtl, g_vtl);
        cudaFuncSetAttribute(tbgemm<false,false,false,false>, cudaFuncAttributeMaxDynamicSharedMemorySize, TG_SMEM);
        cudaFuncSetAttribute(tbgemm<false,false,true,false>,  cudaFuncAttributeMaxDynamicSharedMemorySize, TG_SMEM);
        cudaFuncSetAttribute(tbgemm<true,true,false,true>,    cudaFuncAttributeMaxDynamicSharedMemorySize, TG_SMEM);
        cudaFuncSetAttribute(tbgemm<false,true,false,false>,  cudaFuncAttributeMaxDynamicSharedMemorySize, TG_SMEM);
        cudaFuncSetAttribute(tbgemm<false,true,true,false>,   cudaFuncAttributeMaxDynamicSharedMemorySize, TG_SMEM);
        cudaFuncSetAttribute(flash_attn, cudaFuncAttributeMaxDynamicSharedMemorySize, FA_SMEM);
        inited = true;
    }

    const dim3 blk(256);
    const dim3 blk512(512);
    const dim3 tb(32, 8);

    // ---- weight prep ----
    transpose_split<<<dim3(64, 64),  tb>>>(wq,  2048, 2048, pwh+OWQ,  pwl+OWQ);
    transpose_split<<<dim3(64, 64),  tb>>>(wk,  2048, 2048, pwh+OWK,  pwl+OWK);
    transpose_split<<<dim3(64, 64),  tb>>>(wv,  2048, 2048, pwh+OWV,  pwl+OWV);
    transpose_split<<<dim3(64, 64),  tb>>>(wo,  2048, 2048, pwh+OWO,  pwl+OWO);
    transpose_split<<<dim3(128, 64), tb>>>(rw1, 2048, 4096, pwh+ORW1, pwl+ORW1);
    transpose_split<<<dim3(64, 128), tb>>>(rw2, 4096, 2048, pwh+ORW2, pwl+ORW2);
    transpose_split<<<dim3(64, 64),  tb>>>(dw,  2048, 2048, pwh+ODW,  pwl+ODW);
    transpose_split<<<dim3(256, 64), tb>>>(mw1, 2048, 8192, pwh+OMW1, pwl+OMW1);
    transpose_split<<<dim3(64, 256), tb>>>(mw2, 8192, 2048, pwh+OMW2, pwl+OMW2);
    pers_part<<<dim3(D_/256, 32), blk>>>(pemb, trait, dw, pppart);
    pers_reduce<<<D_/256, blk>>>(pppart, db, ppers);

    // 1) h = LN1(x) -> bf16 split
    ln_kernel<<<M_, blk>>>(x, nullptr, g1, b1, nullptr, pah, pal);
    // 2) qkv = h @ [wq|wk|wv]
    tbgemm<false,false,false,false><<<dim3(24,32), blk512, TG_SMEM>>>(
        pah,pal, pwh+OWQ,pwl+OWQ, nullptr,nullptr, pqkv,nullptr,nullptr, M_, 3*D_, D_);
    // 3) attention prep (bf16 splits)
    qk_prep<<<16384, blk>>>(pqkv, pqsh, pqsl, pksh, pksl);
    v_prep<<<dim3(64, 4, 32), tb>>>(pqkv, pvth, pvtl);
    // 4) fused flash attention -> pah/pal
    flash_attn<<<dim3(16, 32), blk, FA_SMEM>>>(
        pqsh, pqsl, pksh, pksl, pvth, pvtl, mask, pah, pal);
    // 5) x2 = x + attn_out @ wo
    tbgemm<false,false,true,false><<<dim3(8,32), blk512, TG_SMEM>>>(
        pah,pal, pwh+OWO,pwl+OWO, nullptr,x, px2,nullptr,nullptr, M_, D_, D_);
    // 6) h2 = LN2(x2)
    ln_kernel<<<M_, blk>>>(px2, nullptr, g2, b2, ph2, pah, pal);
    // 7) t = gelu(h2 @ rw1 + rb1)
    tbgemm<true,true,false,true><<<dim3(16,32), blk512, TG_SMEM>>>(
        pah,pal, pwh+ORW1,pwl+ORW1, rb1,nullptr, nullptr,pth,ptl, M_, 2*D_, D_);
    // 8) r = t @ rw2 + rb2
    tbgemm<false,true,false,false><<<dim3(8,32), blk512, TG_SMEM>>>(
        pth,ptl, pwh+ORW2,pwl+ORW2, rb2,nullptr, pr,nullptr,nullptr, M_, D_, 2*D_);
    // 9) h3 = LN(h2 + r)
    ln_kernel<<<M_, blk>>>(ph2, pr, rg, rb, ph3, pah, pal);
    // 10) dec = h3 @ dw[:D] + pers
    tbgemm<false,true,false,false><<<dim3(8,32), blk512, TG_SMEM>>>(
        pah,pal, pwh+ODW,pwl+ODW, ppers,nullptr, pqkv,nullptr,nullptr, M_, D_, D_);
    // 11) h4 = LN(h3 + dec)
    ln_kernel<<<M_, blk>>>(ph3, pqkv, wgam, wbet, nullptr, pah, pal);
    // 12) t = gelu(h4 @ mw1 + mb1)
    tbgemm<true,true,false,true><<<dim3(32,32), blk512, TG_SMEM>>>(
        pah,pal, pwh+OMW1,pwl+OMW1, mb1,nullptr, nullptr,pth,ptl, M_, 4*D_, D_);
    // 13) out = x2 + t @ mw2 + mb2
    tbgemm<false,true,true,false><<<dim3(8,32), blk512, TG_SMEM>>>(
        pth,ptl, pwh+OMW2,pwl+OMW2, mb2,px2, out,nullptr,nullptr, M_, D_, 4*D_);
}

// round 14
// speedup vs baseline: 1.5007x; 1.3771x over previous
#include <cuda_runtime.h>
#include <cuda_bf16.h>
#include <cuda_fp16.h>
#include <math.h>
#include <stdint.h>

#define B_  2
#define S_  2048
#define D_  2048
#define H_  16
#define HD_ 128
#define M_  (B_*S_)   // 4096 rows

// ---------------- scratch (static device globals; allocation-free) ----------
__device__ __align__(128) float g_qkv[(size_t)M_*3*D_];   // [M][6144] q|k|v
__device__ __align__(128) float g_x2 [(size_t)M_*D_];
__device__ __align__(128) float g_r  [(size_t)M_*D_];
__device__ __align__(128) float g_h2 [(size_t)M_*D_];
__device__ __align__(128) float g_h3 [(size_t)M_*D_];
__device__ __align__(128) float g_pers[D_];
__device__ __align__(128) float g_ppart[32*D_];

// fp16 hi/lo activation scratch (dense GEMM A-operands)
__device__ __align__(128) __half g_ah[(size_t)M_*D_];
__device__ __align__(128) __half g_al[(size_t)M_*D_];
__device__ __align__(128) __half g_th[(size_t)M_*4*D_];
__device__ __align__(128) __half g_tl[(size_t)M_*4*D_];

// attention scratch (bf16 splits, FA kernel unchanged)
__device__ __align__(128) __nv_bfloat16 g_qsh[(size_t)M_*D_];
__device__ __align__(128) __nv_bfloat16 g_qsl[(size_t)M_*D_];
__device__ __align__(128) __nv_bfloat16 g_ksh[(size_t)M_*D_];
__device__ __align__(128) __nv_bfloat16 g_ksl[(size_t)M_*D_];
__device__ __align__(128) __nv_bfloat16 g_vth[(size_t)32*HD_*S_];   // [bh][128][2048]
__device__ __align__(128) __nv_bfloat16 g_vtl[(size_t)32*HD_*S_];

// fp16 transposed weights (single precision level), packed pool: [N,K] row-major
#define OWQ  ((size_t)0)
#define OWK  ((size_t)4194304)
#define OWV  ((size_t)8388608)
#define OWO  ((size_t)12582912)
#define ORW1 ((size_t)16777216)
#define ORW2 ((size_t)25165824)
#define ODW  ((size_t)33554432)
#define OMW1 ((size_t)37748736)
#define OMW2 ((size_t)54525952)
#define WTOT ((size_t)71303168)
__device__ __align__(128) __half g_wh[WTOT];

// ---------------- helpers ----------------------------------------------------
__device__ __forceinline__ void split2h(float v, __half& h, __half& l) {
    h = __float2half(v);
    l = __float2half(v - __half2float(h));
}
__device__ __forceinline__ void split2b(float v, __nv_bfloat16& h, __nv_bfloat16& l) {
    h = __float2bfloat16(v);
    l = __float2bfloat16(v - __bfloat162float(h));
}
__device__ __forceinline__ uint32_t smem_u32(const void* p) {
    uint32_t a;
    asm("{ .reg .u64 t; cvta.to.shared.u64 t, %1; cvt.u32.u64 %0, t; }" : "=r"(a) : "l"(p));
    return a;
}
__device__ __forceinline__ uint32_t packbf2(float a, float b) {
    __nv_bfloat162 p;
    p.x = __float2bfloat16(a); p.y = __float2bfloat16(b);
    return *(uint32_t*)&p;
}

#define MMA16816B(d, a, b) \
    asm volatile("mma.sync.aligned.m16n8k16.row.col.f32.bf16.bf16.f32 " \
        "{%0,%1,%2,%3}, {%4,%5,%6,%7}, {%8,%9}, {%0,%1,%2,%3};" \
        : "+f"((d)[0]), "+f"((d)[1]), "+f"((d)[2]), "+f"((d)[3]) \
        : "r"((a)[0]), "r"((a)[1]), "r"((a)[2]), "r"((a)[3]), "r"((b)[0]), "r"((b)[1]))

#define MMA16816H(d, a, b) \
    asm volatile("mma.sync.aligned.m16n8k16.row.col.f32.f16.f16.f32 " \
        "{%0,%1,%2,%3}, {%4,%5,%6,%7}, {%8,%9}, {%0,%1,%2,%3};" \
        : "+f"((d)[0]), "+f"((d)[1]), "+f"((d)[2]), "+f"((d)[3]) \
        : "r"((a)[0]), "r"((a)[1]), "r"((a)[2]), "r"((a)[3]), "r"((b)[0]), "r"((b)[1]))

#define LDMX4(d, addr) \
    asm volatile("ldmatrix.sync.aligned.m8n8.x4.shared.b16 {%0,%1,%2,%3}, [%4];" \
        : "=r"((d)[0]), "=r"((d)[1]), "=r"((d)[2]), "=r"((d)[3]) : "r"(addr))

__device__ __forceinline__ void cp16(uint32_t dst, const void* src) {
    asm volatile("cp.async.cg.shared.global [%0], [%1], 16;" :: "r"(dst), "l"(src));
}
#define CP_COMMIT() asm volatile("cp.async.commit_group;" ::: "memory")
#define CP_WAIT1()  asm volatile("cp.async.wait_group 1;" ::: "memory")

__device__ __forceinline__ float gelu1(float v) {
    return 0.5f * v * (1.0f + erff(v * 0.70710678118654752f));
}

// ================= HMMA GEMM (fp16 2-pass): 128x256 tile, 512 thr, KC=64 =====
// C = (Ah+Al) @ Bh^T : passes hh + lh. Stage = Ah|Al (128x72) + Bh (256x72).
#define LDE 72
#define AME (128*LDE)                  // 9216 elems
#define BME (256*LDE)                  // 18432 elems
#define STAGE_B ((2*AME + BME)*2)      // 73728 bytes
#define TG_SMEM (2*STAGE_B)            // 147456 bytes

template<bool GELU, bool BIAS, bool RES, bool OUT_F16>
__global__ __launch_bounds__(512, 1)
void tbgemm(const __half* __restrict__ Ah, const __half* __restrict__ Al,
            const __half* __restrict__ Bh,
            const float* __restrict__ bias, const float* __restrict__ res,
            float* __restrict__ Cf, __half* __restrict__ Ch, __half* __restrict__ Cl,
            int M, int N, int K)
{
    extern __shared__ __half sm[];
    const int tid  = threadIdx.x;
    const int lane = tid & 31;
    const int warp = tid >> 5;         // 0..15
    const int wm = warp & 3;           // 4 m-warps, 32 rows each
    const int wn = warp >> 2;          // 4 n-warps, 64 cols each
    const int m0 = blockIdx.y * 128;
    const int n0 = blockIdx.x * 256;
    const int g  = lane >> 2;
    const int t  = lane & 3;
    const uint32_t sbase = smem_u32(sm);
    const int jq = lane >> 3;
    const int jr = lane & 7;

    float acc[2][8][4];
    #pragma unroll
    for (int m = 0; m < 2; m++)
        #pragma unroll
        for (int n = 0; n < 8; n++)
            #pragma unroll
            for (int e = 0; e < 4; e++) acc[m][n][e] = 0.f;

    auto issue = [&](int c, int buf) {
        const int k0 = c << 6;
        const uint32_t b0 = sbase + (uint32_t)buf * STAGE_B;
        #pragma unroll
        for (int i = 0; i < 2; i++) {          // A: 128 rows x 64, hi+lo
            int v = i * 512 + tid;
            int r = v >> 3, q = v & 7;
            uint32_t so = (uint32_t)(r * LDE + q * 8) * 2;
            size_t ga = (size_t)(m0 + r) * K + k0 + q * 8;
            cp16(b0 + so,          Ah + ga);
            cp16(b0 + AME*2 + so,  Al + ga);
        }
        #pragma unroll
        for (int i = 0; i < 4; i++) {          // B: 256 rows x 64, hi only
            int v = i * 512 + tid;
            int r = v >> 3, q = v & 7;
            uint32_t so = (uint32_t)(r * LDE + q * 8) * 2;
            size_t gb = (size_t)(n0 + r) * K + k0 + q * 8;
            cp16(b0 + 2*AME*2 + so, Bh + gb);
        }
        CP_COMMIT();
    };

    const int nc = K >> 6;
    issue(0, 0);
    if (nc > 1) issue(1, 1); else CP_COMMIT();

    for (int c = 0; c < nc; c++) {
        const int buf = c & 1;
        CP_WAIT1();
        __syncthreads();

        const uint32_t A_h = sbase + (uint32_t)buf * STAGE_B;
        const uint32_t A_l = A_h + AME*2;
        const uint32_t B_h = A_h + 2*AME*2;

        #pragma unroll
        for (int kk = 0; kk < 64; kk += 16) {
            uint32_t ah[2][4], al[2][4];
            #pragma unroll
            for (int m = 0; m < 2; m++) {
                int row = wm * 32 + m * 16 + (jq & 1) * 8 + jr;
                uint32_t off = (uint32_t)(row * LDE + kk + (jq >> 1) * 8) * 2;
                LDMX4(ah[m], A_h + off);
                LDMX4(al[m], A_l + off);
            }
            #pragma unroll
            for (int np = 0; np < 4; np++) {
                int nrow = wn * 64 + np * 16 + (jq >> 1) * 8 + jr;
                uint32_t boff = (uint32_t)(nrow * LDE + kk + (jq & 1) * 8) * 2;
                uint32_t bh[4];
                LDMX4(bh, B_h + boff);
                #pragma unroll
                for (int m = 0; m < 2; m++) {
                    MMA16816H(acc[m][2*np],   ah[m], &bh[0]);
                    MMA16816H(acc[m][2*np],   al[m], &bh[0]);
                    MMA16816H(acc[m][2*np+1], ah[m], &bh[2]);
                    MMA16816H(acc[m][2*np+1], al[m], &bh[2]);
                }
            }
        }
        __syncthreads();
        if (c + 2 < nc) issue(c + 2, buf); else CP_COMMIT();
    }

    #pragma unroll
    for (int m = 0; m < 2; m++) {
        #pragma unroll
        for (int n = 0; n < 8; n++) {
            int col = n0 + wn * 64 + n * 8 + t * 2;
            #pragma unroll
            for (int half = 0; half < 2; half++) {
                int row = m0 + wm * 32 + m * 16 + g + half * 8;
                float v0 = acc[m][n][half * 2 + 0];
                float v1 = acc[m][n][half * 2 + 1];
                if (BIAS) { v0 += bias[col]; v1 += bias[col + 1]; }
                if (GELU) { v0 = gelu1(v0); v1 = gelu1(v1); }
                size_t off = (size_t)row * N + col;
                if (RES) {
                    float2 r2 = *(const float2*)&res[off];
                    v0 += r2.x; v1 += r2.y;
                }
                if (OUT_F16) {
                    __half h0, l0, h1, l1;
                    split2h(v0, h0, l0); split2h(v1, h1, l1);
                    __half2 hp, lp;
                    hp.x = h0; hp.y = h1; lp.x = l0; lp.y = l1;
                    *(__half2*)&Ch[off] = hp;
                    *(__half2*)&Cl[off] = lp;
                } else {
                    *(float2*)&Cf[off] = make_float2(v0, v1);
                }
            }
        }
    }
}

// ================= fused HMMA flash attention (bf16 3-pass, fp16 output) =====
#define LQ 136
#define LV 72
#define FQH 0
#define FQL (128*LQ)
#define FST0 (2*128*LQ)
#define FKH 0
#define FKL (64*LQ)
#define FVH (2*64*LQ)
#define FVL (FVH + 128*LV)
#define FSTG (FVL + 128*LV)
#define FA_SMEM ((FST0 + 2*FSTG)*2)    // 212992 bytes

__global__ __launch_bounds__(256)
void flash_attn(const __nv_bfloat16* __restrict__ Qh, const __nv_bfloat16* __restrict__ Ql,
                const __nv_bfloat16* __restrict__ Kh, const __nv_bfloat16* __restrict__ Kl,
                const __nv_bfloat16* __restrict__ Vth, const __nv_bfloat16* __restrict__ Vtl,
                const int* __restrict__ mask,
                __half* __restrict__ Oh, __half* __restrict__ Ol)
{
    extern __shared__ __nv_bfloat16 fsm[];
    const int tid  = threadIdx.x;
    const int lane = tid & 31;
    const int warp = tid >> 5;
    const int g  = lane >> 2;
    const int t  = lane & 3;
    const int jq = lane >> 3;
    const int jr = lane & 7;
    const uint32_t sb = smem_u32(fsm);
    const int z = blockIdx.y, b = z >> 4, h = z & 15;
    const int q0 = blockIdx.x * 128;
    const size_t qrow0 = (size_t)b * 2048 + q0;

    {
        #pragma unroll
        for (int i = 0; i < 8; i++) {
            int v = i * 256 + tid;
            int r = v >> 4, q = v & 15;
            uint32_t so = (uint32_t)(r * LQ + q * 8) * 2;
            size_t gq = (qrow0 + r) * 2048 + h * 128 + q * 8;
            cp16(sb + (FQH)*2 + so, Qh + gq);
            cp16(sb + (FQL)*2 + so, Ql + gq);
        }
        CP_COMMIT();
    }

    auto issue_kv = [&](int kt, int s) {
        const uint32_t b0 = sb + (uint32_t)(FST0 + s * FSTG) * 2;
        #pragma unroll
        for (int i = 0; i < 4; i++) {
            int v = i * 256 + tid;
            int r = v >> 4, q = v & 15;
            uint32_t so = (uint32_t)(r * LQ + q * 8) * 2;
            size_t gk = ((size_t)b * 2048 + kt * 64 + r) * 2048 + h * 128 + q * 8;
            cp16(b0 + (FKH)*2 + so, Kh + gk);
            cp16(b0 + (FKL)*2 + so, Kl + gk);
        }
        #pragma unroll
        for (int i = 0; i < 4; i++) {
            int v = i * 256 + tid;
            int d = v >> 3, q = v & 7;
            uint32_t so = (uint32_t)(d * LV + q * 8) * 2;
            size_t gv = ((size_t)z * 128 + d) * 2048 + kt * 64 + q * 8;
            cp16(b0 + (FVH)*2 + so, Vth + gv);
            cp16(b0 + (FVL)*2 + so, Vtl + gv);
        }
        CP_COMMIT();
    };

    issue_kv(0, 0);
    issue_kv(1, 1);

    const int q0w = warp * 16;
    float accO[16][4];
    #pragma unroll
    for (int n = 0; n < 16; n++)
        #pragma unroll
        for (int e = 0; e < 4; e++) accO[n][e] = 0.f;
    float m0v = -1e30f, m1v = -1e30f, l0v = 0.f, l1v = 0.f;

    for (int kt = 0; kt < 32; kt++) {
        CP_WAIT1();
        __syncthreads();
        const int s = kt & 1;
        const uint32_t K_h = sb + (uint32_t)(FST0 + s * FSTG + FKH) * 2;
        const uint32_t K_l = sb + (uint32_t)(FST0 + s * FSTG + FKL) * 2;
        const uint32_t V_h = sb + (uint32_t)(FST0 + s * FSTG + FVH) * 2;
        const uint32_t V_l = sb + (uint32_t)(FST0 + s * FSTG + FVL) * 2;

        float sc[8][4];
        #pragma unroll
        for (int n = 0; n < 8; n++)
            #pragma unroll
            for (int e = 0; e < 4; e++) sc[n][e] = 0.f;
        #pragma unroll
        for (int kc = 0; kc < 8; kc++) {
            int arow = q0w + (jq & 1) * 8 + jr;
            uint32_t aoff = (uint32_t)(arow * LQ + kc * 16 + (jq >> 1) * 8) * 2;
            uint32_t qh_[4], ql_[4];
            LDMX4(qh_, sb + FQH*2 + aoff);
            LDMX4(ql_, sb + FQL*2 + aoff);
            #pragma unroll
            for (int ng = 0; ng < 4; ng++) {
                int krow = ng * 16 + (jq >> 1) * 8 + jr;
                uint32_t boff = (uint32_t)(krow * LQ + kc * 16 + (jq & 1) * 8) * 2;
                uint32_t kh_[4], kl_[4];
                LDMX4(kh_, K_h + boff);
                LDMX4(kl_, K_l + boff);
                MMA16816B(sc[2*ng],   qh_, &kh_[0]);
                MMA16816B(sc[2*ng],   qh_, &kl_[0]);
                MMA16816B(sc[2*ng],   ql_, &kh_[0]);
                MMA16816B(sc[2*ng+1], qh_, &kh_[2]);
                MMA16816B(sc[2*ng+1], qh_, &kl_[2]);
                MMA16816B(sc[2*ng+1], ql_, &kh_[2]);
            }
        }

        const int kb = b * 2048 + kt * 64;
        #pragma unroll
        for (int j = 0; j < 8; j++) {
            if (mask[kb + 8*j + 2*t]     == 0) { sc[j][0] = -1e30f; sc[j][2] = -1e30f; }
            if (mask[kb + 8*j + 2*t + 1] == 0) { sc[j][1] = -1e30f; sc[j][3] = -1e30f; }
        }
        float rm0 = -1e30f, rm1 = -1e30f;
        #pragma unroll
        for (int j = 0; j < 8; j++) {
            rm0 = fmaxf(rm0, fmaxf(sc[j][0], sc[j][1]));
            rm1 = fmaxf(rm1, fmaxf(sc[j][2], sc[j][3]));
        }
        rm0 = fmaxf(rm0, __shfl_xor_sync(0xffffffffu, rm0, 1));
        rm0 = fmaxf(rm0, __shfl_xor_sync(0xffffffffu, rm0, 2));
        rm1 = fmaxf(rm1, __shfl_xor_sync(0xffffffffu, rm1, 1));
        rm1 = fmaxf(rm1, __shfl_xor_sync(0xffffffffu, rm1, 2));
        float mn0 = fmaxf(m0v, rm0), mn1 = fmaxf(m1v, rm1);
        float c0 = __expf(m0v - mn0), c1 = __expf(m1v - mn1);
        float p[8][4], rs0 = 0.f, rs1 = 0.f;
        #pragma unroll
        for (int j = 0; j < 8; j++) {
            p[j][0] = __expf(sc[j][0] - mn0);
            p[j][1] = __expf(sc[j][1] - mn0);
            p[j][2] = __expf(sc[j][2] - mn1);
            p[j][3] = __expf(sc[j][3] - mn1);
            rs0 += p[j][0] + p[j][1];
            rs1 += p[j][2] + p[j][3];
        }
        rs0 += __shfl_xor_sync(0xffffffffu, rs0, 1);
        rs0 += __shfl_xor_sync(0xffffffffu, rs0, 2);
        rs1 += __shfl_xor_sync(0xffffffffu, rs1, 1);
        rs1 += __shfl_xor_sync(0xffffffffu, rs1, 2);
        l0v = l0v * c0 + rs0;  m0v = mn0;
        l1v = l1v * c1 + rs1;  m1v = mn1;
        #pragma unroll
        for (int n = 0; n < 16; n++) {
            accO[n][0] *= c0; accO[n][1] *= c0;
            accO[n][2] *= c1; accO[n][3] *= c1;
        }

        #pragma unroll
        for (int kc = 0; kc < 4; kc++) {
            uint32_t a_h[4], a_l[4];
            #pragma unroll
            for (int q = 0; q < 2; q++) {
                float v0 = p[2*kc+q][0], v1 = p[2*kc+q][1];
                float v2 = p[2*kc+q][2], v3 = p[2*kc+q][3];
                uint32_t h01 = packbf2(v0, v1), h23 = packbf2(v2, v3);
                __nv_bfloat162 hb01 = *(__nv_bfloat162*)&h01;
                __nv_bfloat162 hb23 = *(__nv_bfloat162*)&h23;
                uint32_t l01 = packbf2(v0 - __bfloat162float(hb01.x),
                                       v1 - __bfloat162float(hb01.y));
                uint32_t l23 = packbf2(v2 - __bfloat162float(hb23.x),
                                       v3 - __bfloat162float(hb23.y));
                a_h[2*q+0] = h01; a_h[2*q+1] = h23;
                a_l[2*q+0] = l01; a_l[2*q+1] = l23;
            }
            #pragma unroll
            for (int ng = 0; ng < 8; ng++) {
                int drow = ng * 16 + (jq >> 1) * 8 + jr;
                uint32_t boff = (uint32_t)(drow * LV + kc * 16 + (jq & 1) * 8) * 2;
                uint32_t vh_[4], vl_[4];
                LDMX4(vh_, V_h + boff);
                LDMX4(vl_, V_l + boff);
                MMA16816B(accO[2*ng],   a_h, &vh_[0]);
                MMA16816B(accO[2*ng],   a_h, &vl_[0]);
                MMA16816B(accO[2*ng],   a_l, &vh_[0]);
                MMA16816B(accO[2*ng+1], a_h, &vh_[2]);
                MMA16816B(accO[2*ng+1], a_h, &vl_[2]);
                MMA16816B(accO[2*ng+1], a_l, &vh_[2]);
            }
        }

        __syncthreads();
        if (kt + 2 < 32) issue_kv(kt + 2, s); else CP_COMMIT();
    }

    float inv0 = 1.0f / l0v, inv1 = 1.0f / l1v;
    const size_t r0 = qrow0 + q0w + g;
    const size_t r1 = r0 + 8;
    #pragma unroll
    for (int n = 0; n < 16; n++) {
        int col = h * 128 + n * 8 + t * 2;
        float v0 = accO[n][0] * inv0, v1 = accO[n][1] * inv0;
        float v2 = accO[n][2] * inv1, v3 = accO[n][3] * inv1;
        __half h0,l0,h1,l1,h2,l2,h3,l3;
        split2h(v0,h0,l0); split2h(v1,h1,l1); split2h(v2,h2,l2); split2h(v3,h3,l3);
        __half2 hp0, lp0, hp1, lp1;
        hp0.x=h0; hp0.y=h1; lp0.x=l0; lp0.y=l1;
        hp1.x=h2; hp1.y=h3; lp1.x=l2; lp1.y=l3;
        *(__half2*)&Oh[r0*2048 + col] = hp0;
        *(__half2*)&Ol[r0*2048 + col] = lp0;
        *(__half2*)&Oh[r1*2048 + col] = hp1;
        *(__half2*)&Ol[r1*2048 + col] = lp1;
    }
}

// ---------------- transpose + fp16 cast: W[K,N] -> Th[N,K] ------------------
__global__ __launch_bounds__(256)
void transpose_half(const float* __restrict__ W, int K, int N,
                    __half* __restrict__ Th)
{
    __shared__ float tile[32][33];
    const int tx = threadIdx.x, ty = threadIdx.y;
    const int n0 = blockIdx.x * 32, k0 = blockIdx.y * 32;
    #pragma unroll
    for (int i = 0; i < 4; i++)
        tile[ty + 8*i][tx] = W[(size_t)(k0 + ty + 8*i) * N + n0 + tx];
    __syncthreads();
    #pragma unroll
    for (int i = 0; i < 4; i++) {
        float v = tile[tx][ty + 8*i];
        Th[(size_t)(n0 + ty + 8*i) * K + k0 + tx] = __float2half(v);
    }
}

// ---------------- qk prep: qkv fp32 -> Q(scaled)/K bf16 splits --------------
__global__ __launch_bounds__(256)
void qk_prep(const float* __restrict__ qkv,
             __nv_bfloat16* __restrict__ qh, __nv_bfloat16* __restrict__ ql,
             __nv_bfloat16* __restrict__ kh, __nv_bfloat16* __restrict__ kl)
{
    const float scale = 0.088388347648318447f;
    size_t e = ((size_t)blockIdx.x * 256 + threadIdx.x) * 4;
    int row = (int)(e >> 12);
    int col = (int)(e & 4095);
    float4 v = *(const float4*)&qkv[(size_t)row * 6144 + col];
    __nv_bfloat16 hb[4], lb[4];
    if (col < 2048) {
        split2b(v.x*scale, hb[0], lb[0]); split2b(v.y*scale, hb[1], lb[1]);
        split2b(v.z*scale, hb[2], lb[2]); split2b(v.w*scale, hb[3], lb[3]);
        *(uint2*)&qh[(size_t)row*2048 + col] = *(uint2*)hb;
        *(uint2*)&ql[(size_t)row*2048 + col] = *(uint2*)lb;
    } else {
        split2b(v.x, hb[0], lb[0]); split2b(v.y, hb[1], lb[1]);
        split2b(v.z, hb[2], lb[2]); split2b(v.w, hb[3], lb[3]);
        *(uint2*)&kh[(size_t)row*2048 + col - 2048] = *(uint2*)hb;
        *(uint2*)&kl[(size_t)row*2048 + col - 2048] = *(uint2*)lb;
    }
}

// ---------------- v prep: transpose V per (b,h) -> [dim][keys] splits -------
__global__ __launch_bounds__(256)
void v_prep(const float* __restrict__ qkv,
            __nv_bfloat16* __restrict__ vth, __nv_bfloat16* __restrict__ vtl)
{
    __shared__ float tile[32][33];
    const int tx = threadIdx.x, ty = threadIdx.y;
    const int z = blockIdx.z, b = z >> 4, h = z & 15;
    const int key0 = blockIdx.x * 32, d0 = blockIdx.y * 32;
    #pragma unroll
    for (int i = 0; i < 4; i++) {
        int key = key0 + ty + 8*i;
        tile[ty + 8*i][tx] = qkv[(size_t)(b*2048 + key)*6144 + 4096 + h*128 + d0 + tx];
    }
    __syncthreads();
    #pragma unroll
    for (int i = 0; i < 4; i++) {
        int d = d0 + ty + 8*i;
        float v = tile[tx][ty + 8*i];
        __nv_bfloat16 hh, ll; split2b(v, hh, ll);
        size_t o = ((size_t)z*128 + d)*2048 + key0 + tx;
        vth[o] = hh; vtl[o] = ll;
    }
}

// ---------------- LayerNorm: out = LN(A [+ Ad]) * g + b ; + fp16 split ------
__global__ __launch_bounds__(256)
void ln_kernel(const float* __restrict__ A, const float* __restrict__ Ad,
               const float* __restrict__ g, const float* __restrict__ bb,
               float* __restrict__ out, __half* __restrict__ oh,
               __half* __restrict__ ol)
{
    const int row = blockIdx.x, t = threadIdx.x;
    const float* a = A + (size_t)row * D_;
    float4 v[2];
    float s = 0.f, ss = 0.f;
    #pragma unroll
    for (int i = 0; i < 2; i++) {
        int idx = (i*256 + t) * 4;
        float4 x = *(const float4*)&a[idx];
        if (Ad) {
            float4 y = *(const float4*)&Ad[(size_t)row*D_ + idx];
            x.x += y.x; x.y += y.y; x.z += y.z; x.w += y.w;
        }
        v[i] = x;
        s  += x.x + x.y + x.z + x.w;
        ss += x.x*x.x + x.y*x.y + x.z*x.z + x.w*x.w;
    }
    #pragma unroll
    for (int off = 16; off; off >>= 1) {
        s  += __shfl_xor_sync(0xffffffffu, s,  off);
        ss += __shfl_xor_sync(0xffffffffu, ss, off);
    }
    __shared__ float sb[8], ssb[8];
    if ((t & 31) == 0) { sb[t>>5] = s; ssb[t>>5] = ss; }
    __syncthreads();
    float st = 0.f, sst = 0.f;
    #pragma unroll
    for (int i = 0; i < 8; i++) { st += sb[i]; sst += ssb[i]; }
    float mean = st * (1.f / D_);
    float var  = sst * (1.f / D_) - mean * mean;
    float rstd = rsqrtf(var + 1e-5f);
    #pragma unroll
    for (int i = 0; i < 2; i++) {
        int idx = (i*256 + t) * 4;
        float4 gg  = *(const float4*)&g[idx];
        float4 bbv = *(const float4*)&bb[idx];
        float4 x = v[i], o;
        o.x = (x.x - mean)*rstd*gg.x + bbv.x;
        o.y = (x.y - mean)*rstd*gg.y + bbv.y;
        o.z = (x.z - mean)*rstd*gg.z + bbv.z;
        o.w = (x.w - mean)*rstd*gg.w + bbv.w;
        if (out) *(float4*)&out[(size_t)row*D_ + idx] = o;
        __half hb[4], lb[4];
        split2h(o.x, hb[0], lb[0]); split2h(o.y, hb[1], lb[1]);
        split2h(o.z, hb[2], lb[2]); split2h(o.w, hb[3], lb[3]);
        *(uint2*)&oh[(size_t)row*D_ + idx] = *(uint2*)hb;
        *(uint2*)&ol[(size_t)row*D_ + idx] = *(uint2*)lb;
    }
}

// ---------------- persona vector (2-stage, deterministic) -------------------
__global__ __launch_bounds__(256)
void pers_part(const float* __restrict__ pemb, const int* __restrict__ trait,
               const float* __restrict__ dw, float* __restrict__ part)
{
    int j = blockIdx.x * 256 + threadIdx.x;
    int seg = blockIdx.y;
    int tix = trait[0];
    const float* pe = pemb + (size_t)tix * D_;
    float acc = 0.f;
    int i0 = seg * 64;
    #pragma unroll 8
    for (int i = i0; i < i0 + 64; ++i)
        acc = fmaf(pe[i], dw[(size_t)(D_ + i) * D_ + j], acc);
    part[(size_t)seg * D_ + j] = acc;
}
__global__ __launch_bounds__(256)
void pers_reduce(const float* __restrict__ part, const float* __restrict__ db,
                 float* __restrict__ out)
{
    int j = blockIdx.x * 256 + threadIdx.x;
    float s = db[j];
    #pragma unroll
    for (int k = 0; k < 32; ++k) s += part[(size_t)k * D_ + j];
    out[j] = s;
}

// ---------------- launch ----------------------------------------------------
extern "C" void kernel_launch(void* const* d_in, const int* in_sizes, int n_in,
                              void* d_out, int out_size)
{
    const float* x     = (const float*)d_in[0];
    const int*   mask  = (const int*)  d_in[1];
    const int*   trait = (const int*)  d_in[2];
    const float* wq    = (const float*)d_in[3];
    const float* wk    = (const float*)d_in[4];
    const float* wv    = (const float*)d_in[5];
    const float* wo    = (const float*)d_in[6];
    const float* g1    = (const float*)d_in[7];
    const float* b1    = (const float*)d_in[8];
    const float* g2    = (const float*)d_in[9];
    const float* b2    = (const float*)d_in[10];
    const float* rw1   = (const float*)d_in[11];
    const float* rb1   = (const float*)d_in[12];
    const float* rw2   = (const float*)d_in[13];
    const float* rb2   = (const float*)d_in[14];
    const float* rg    = (const float*)d_in[15];
    const float* rb    = (const float*)d_in[16];
    const float* pemb  = (const float*)d_in[17];
    const float* dw    = (const float*)d_in[18];
    const float* db    = (const float*)d_in[19];
    const float* wgam  = (const float*)d_in[20];
    const float* wbet  = (const float*)d_in[21];
    const float* mw1   = (const float*)d_in[22];
    const float* mb1   = (const float*)d_in[23];
    const float* mw2   = (const float*)d_in[24];
    const float* mb2   = (const float*)d_in[25];
    float* out = (float*)d_out;

    static float *pqkv=0,*px2=0,*pr=0,*ph2=0,*ph3=0,*ppers=0,*pppart=0;
    static __half *pah=0,*pal=0,*pth=0,*ptl=0,*pwh=0;
    static __nv_bfloat16 *pqsh=0,*pqsl=0,*pksh=0,*pksl=0,*pvth=0,*pvtl=0;
    static bool inited = false;
    if (!inited) {
        cudaGetSymbolAddress((void**)&pqkv, g_qkv);
        cudaGetSymbolAddress((void**)&px2, g_x2);
        cudaGetSymbolAddress((void**)&pr,  g_r);
        cudaGetSymbolAddress((void**)&ph2, g_h2);
        cudaGetSymbolAddress((void**)&ph3, g_h3);
        cudaGetSymbolAddress((void**)&ppers, g_pers);
        cudaGetSymbolAddress((void**)&pppart, g_ppart);
        cudaGetSymbolAddress((void**)&pah, g_ah);
        cudaGetSymbolAddress((void**)&pal, g_al);
        cudaGetSymbolAddress((void**)&pth, g_th);
        cudaGetSymbolAddress((void**)&ptl, g_tl);
        cudaGetSymbolAddress((void**)&pwh, g_wh);
        cudaGetSymbolAddress((void**)&pqsh, g_qsh);
        cudaGetSymbolAddress((void**)&pqsl, g_qsl);
        cudaGetSymbolAddress((void**)&pksh, g_ksh);
        cudaGetSymbolAddress((void**)&pksl, g_ksl);
        cudaGetSymbolAddress((void**)&pvth, g_vth);
        cudaGetSymbolAddress((void**)&pvtl, g_vtl);
        cudaFuncSetAttribute(tbgemm<false,false,false,false>, cudaFuncAttributeMaxDynamicSharedMemorySize, TG_SMEM);
        cudaFuncSetAttribute(tbgemm<false,false,true,false>,  cudaFuncAttributeMaxDynamicSharedMemorySize, TG_SMEM);
        cudaFuncSetAttribute(tbgemm<true,true,false,true>,    cudaFuncAttributeMaxDynamicSharedMemorySize, TG_SMEM);
        cudaFuncSetAttribute(tbgemm<false,true,false,false>,  cudaFuncAttributeMaxDynamicSharedMemorySize, TG_SMEM);
        cudaFuncSetAttribute(tbgemm<false,true,true,false>,   cudaFuncAttributeMaxDynamicSharedMemorySize, TG_SMEM);
        cudaFuncSetAttribute(flash_attn, cudaFuncAttributeMaxDynamicSharedMemorySize, FA_SMEM);
        inited = true;
    }

    const dim3 blk(256);
    const dim3 blk512(512);
    const dim3 tb(32, 8);

    // ---- weight prep (fp16 single-level) ----
    transpose_half<<<dim3(64, 64),  tb>>>(wq,  2048, 2048, pwh+OWQ);
    transpose_half<<<dim3(64, 64),  tb>>>(wk,  2048, 2048, pwh+OWK);
    transpose_half<<<dim3(64, 64),  tb>>>(wv,  2048, 2048, pwh+OWV);
    transpose_half<<<dim3(64, 64),  tb>>>(wo,  2048, 2048, pwh+OWO);
    transpose_half<<<dim3(128, 64), tb>>>(rw1, 2048, 4096, pwh+ORW1);
    transpose_half<<<dim3(64, 128), tb>>>(rw2, 4096, 2048, pwh+ORW2);
    transpose_half<<<dim3(64, 64),  tb>>>(dw,  2048, 2048, pwh+ODW);
    transpose_half<<<dim3(256, 64), tb>>>(mw1, 2048, 8192, pwh+OMW1);
    transpose_half<<<dim3(64, 256), tb>>>(mw2, 8192, 2048, pwh+OMW2);
    pers_part<<<dim3(D_/256, 32), blk>>>(pemb, trait, dw, pppart);
    pers_reduce<<<D_/256, blk>>>(pppart, db, ppers);

    // 1) h = LN1(x) -> fp16 split
    ln_kernel<<<M_, blk>>>(x, nullptr, g1, b1, nullptr, pah, pal);
    // 2) qkv = h @ [wq|wk|wv]
    tbgemm<false,false,false,false><<<dim3(24,32), blk512, TG_SMEM>>>(
        pah,pal, pwh+OWQ, nullptr,nullptr, pqkv,nullptr,nullptr, M_, 3*D_, D_);
    // 3) attention prep (bf16 splits)
    qk_prep<<<16384, blk>>>(pqkv, pqsh, pqsl, pksh, pksl);
    v_prep<<<dim3(64, 4, 32), tb>>>(pqkv, pvth, pvtl);
    // 4) fused flash attention -> pah/pal (fp16 split)
    flash_attn<<<dim3(16, 32), blk, FA_SMEM>>>(
        pqsh, pqsl, pksh, pksl, pvth, pvtl, mask, pah, pal);
    // 5) x2 = x + attn_out @ wo
    tbgemm<false,false,true,false><<<dim3(8,32), blk512, TG_SMEM>>>(
        pah,pal, pwh+OWO, nullptr,x, px2,nullptr,nullptr, M_, D_, D_);
    // 6) h2 = LN2(x2)
    ln_kernel<<<M_, blk>>>(px2, nullptr, g2, b2, ph2, pah, pal);
    // 7) t = gelu(h2 @ rw1 + rb1)
    tbgemm<true,true,false,true><<<dim3(16,32), blk512, TG_SMEM>>>(
        pah,pal, pwh+ORW1, rb1,nullptr, nullptr,pth,ptl, M_, 2*D_, D_);
    // 8) r = t @ rw2 + rb2
    tbgemm<false,true,false,false><<<dim3(8,32), blk512, TG_SMEM>>>(
        pth,ptl, pwh+ORW2, rb2,nullptr, pr,nullptr,nullptr, M_, D_, 2*D_);
    // 9) h3 = LN(h2 + r)
    ln_kernel<<<M_, blk>>>(ph2, pr, rg, rb, ph3, pah, pal);
    // 10) dec = h3 @ dw[:D] + pers
    tbgemm<false,true,false,false><<<dim3(8,32), blk512, TG_SMEM>>>(
        pah,pal, pwh+ODW, ppers,nullptr, pqkv,nullptr,nullptr, M_, D_, D_);
    // 11) h4 = LN(h3 + dec)
    ln_kernel<<<M_, blk>>>(ph3, pqkv, wgam, wbet, nullptr, pah, pal);
    // 12) t = gelu(h4 @ mw1 + mb1)
    tbgemm<true,true,false,true><<<dim3(32,32), blk512, TG_SMEM>>>(
        pah,pal, pwh+OMW1, mb1,nullptr, nullptr,pth,ptl, M_, 4*D_, D_);
    // 13) out = x2 + t @ mw2 + mb2
    tbgemm<false,true,true,false><<<dim3(8,32), blk512, TG_SMEM>>>(
        pth,ptl, pwh+OMW2, mb2,px2, out,nullptr,nullptr, M_, D_, 4*D_);
}

// round 15
// speedup vs baseline: 1.5707x; 1.0467x over previous
#include <cuda_runtime.h>
#include <cuda_fp16.h>
#include <math.h>
#include <stdint.h>

#define B_  2
#define S_  2048
#define D_  2048
#define H_  16
#define HD_ 128
#define M_  (B_*S_)   // 4096 rows

// ---------------- scratch (static device globals; allocation-free) ----------
__device__ __align__(128) float g_qkv[(size_t)M_*3*D_];   // [M][6144] q|k|v
__device__ __align__(128) float g_x2 [(size_t)M_*D_];
__device__ __align__(128) float g_r  [(size_t)M_*D_];
__device__ __align__(128) float g_h2 [(size_t)M_*D_];
__device__ __align__(128) float g_h3 [(size_t)M_*D_];
__device__ __align__(128) float g_pers[D_];
__device__ __align__(128) float g_ppart[32*D_];

// fp16 hi/lo activation scratch (dense GEMM A-operands)
__device__ __align__(128) __half g_ah[(size_t)M_*D_];
__device__ __align__(128) __half g_al[(size_t)M_*D_];
__device__ __align__(128) __half g_th[(size_t)M_*4*D_];
__device__ __align__(128) __half g_tl[(size_t)M_*4*D_];

// attention scratch (fp16: Q hi/lo, K single, V^T single)
__device__ __align__(128) __half g_qsh[(size_t)M_*D_];
__device__ __align__(128) __half g_qsl[(size_t)M_*D_];
__device__ __align__(128) __half g_ksh[(size_t)M_*D_];
__device__ __align__(128) __half g_vth[(size_t)32*HD_*S_];   // [bh][128][2048]

// fp16 transposed weights (single level), packed pool: [N,K] row-major
#define OWQ  ((size_t)0)
#define OWK  ((size_t)4194304)
#define OWV  ((size_t)8388608)
#define OWO  ((size_t)12582912)
#define ORW1 ((size_t)16777216)
#define ORW2 ((size_t)25165824)
#define ODW  ((size_t)33554432)
#define OMW1 ((size_t)37748736)
#define OMW2 ((size_t)54525952)
#define WTOT ((size_t)71303168)
__device__ __align__(128) __half g_wh[WTOT];

// ---------------- helpers ----------------------------------------------------
__device__ __forceinline__ void split2h(float v, __half& h, __half& l) {
    h = __float2half(v);
    l = __float2half(v - __half2float(h));
}
__device__ __forceinline__ uint32_t smem_u32(const void* p) {
    uint32_t a;
    asm("{ .reg .u64 t; cvta.to.shared.u64 t, %1; cvt.u32.u64 %0, t; }" : "=r"(a) : "l"(p));
    return a;
}
__device__ __forceinline__ uint32_t packh2(float a, float b) {
    __half2 p;
    p.x = __float2half(a); p.y = __float2half(b);
    return *(uint32_t*)&p;
}

#define MMA16816H(d, a, b) \
    asm volatile("mma.sync.aligned.m16n8k16.row.col.f32.f16.f16.f32 " \
        "{%0,%1,%2,%3}, {%4,%5,%6,%7}, {%8,%9}, {%0,%1,%2,%3};" \
        : "+f"((d)[0]), "+f"((d)[1]), "+f"((d)[2]), "+f"((d)[3]) \
        : "r"((a)[0]), "r"((a)[1]), "r"((a)[2]), "r"((a)[3]), "r"((b)[0]), "r"((b)[1]))

#define LDMX4(d, addr) \
    asm volatile("ldmatrix.sync.aligned.m8n8.x4.shared.b16 {%0,%1,%2,%3}, [%4];" \
        : "=r"((d)[0]), "=r"((d)[1]), "=r"((d)[2]), "=r"((d)[3]) : "r"(addr))

__device__ __forceinline__ void cp16(uint32_t dst, const void* src) {
    asm volatile("cp.async.cg.shared.global [%0], [%1], 16;" :: "r"(dst), "l"(src));
}
#define CP_COMMIT() asm volatile("cp.async.commit_group;" ::: "memory")
#define CP_WAIT1()  asm volatile("cp.async.wait_group 1;" ::: "memory")

__device__ __forceinline__ float gelu1(float v) {
    return 0.5f * v * (1.0f + erff(v * 0.70710678118654752f));
}

// ================= HMMA GEMM (fp16 2-pass): 128x256 tile, 512 thr, KC=64 =====
#define LDE 72
#define AME (128*LDE)                  // 9216 elems
#define BME (256*LDE)                  // 18432 elems
#define STAGE_B ((2*AME + BME)*2)      // 73728 bytes
#define TG_SMEM (2*STAGE_B)            // 147456 bytes

template<bool GELU, bool BIAS, bool RES, bool OUT_F16>
__global__ __launch_bounds__(512, 1)
void tbgemm(const __half* __restrict__ Ah, const __half* __restrict__ Al,
            const __half* __restrict__ Bh,
            const float* __restrict__ bias, const float* __restrict__ res,
            float* __restrict__ Cf, __half* __restrict__ Ch, __half* __restrict__ Cl,
            int M, int N, int K)
{
    extern __shared__ __half sm[];
    const int tid  = threadIdx.x;
    const int lane = tid & 31;
    const int warp = tid >> 5;
    const int wm = warp & 3;
    const int wn = warp >> 2;
    const int m0 = blockIdx.y * 128;
    const int n0 = blockIdx.x * 256;
    const int g  = lane >> 2;
    const int t  = lane & 3;
    const uint32_t sbase = smem_u32(sm);
    const int jq = lane >> 3;
    const int jr = lane & 7;

    float acc[2][8][4];
    #pragma unroll
    for (int m = 0; m < 2; m++)
        #pragma unroll
        for (int n = 0; n < 8; n++)
            #pragma unroll
            for (int e = 0; e < 4; e++) acc[m][n][e] = 0.f;

    auto issue = [&](int c, int buf) {
        const int k0 = c << 6;
        const uint32_t b0 = sbase + (uint32_t)buf * STAGE_B;
        #pragma unroll
        for (int i = 0; i < 2; i++) {
            int v = i * 512 + tid;
            int r = v >> 3, q = v & 7;
            uint32_t so = (uint32_t)(r * LDE + q * 8) * 2;
            size_t ga = (size_t)(m0 + r) * K + k0 + q * 8;
            cp16(b0 + so,          Ah + ga);
            cp16(b0 + AME*2 + so,  Al + ga);
        }
        #pragma unroll
        for (int i = 0; i < 4; i++) {
            int v = i * 512 + tid;
            int r = v >> 3, q = v & 7;
            uint32_t so = (uint32_t)(r * LDE + q * 8) * 2;
            size_t gb = (size_t)(n0 + r) * K + k0 + q * 8;
            cp16(b0 + 2*AME*2 + so, Bh + gb);
        }
        CP_COMMIT();
    };

    const int nc = K >> 6;
    issue(0, 0);
    if (nc > 1) issue(1, 1); else CP_COMMIT();

    for (int c = 0; c < nc; c++) {
        const int buf = c & 1;
        CP_WAIT1();
        __syncthreads();

        const uint32_t A_h = sbase + (uint32_t)buf * STAGE_B;
        const uint32_t A_l = A_h + AME*2;
        const uint32_t B_h = A_h + 2*AME*2;

        #pragma unroll
        for (int kk = 0; kk < 64; kk += 16) {
            uint32_t ah[2][4], al[2][4];
            #pragma unroll
            for (int m = 0; m < 2; m++) {
                int row = wm * 32 + m * 16 + (jq & 1) * 8 + jr;
                uint32_t off = (uint32_t)(row * LDE + kk + (jq >> 1) * 8) * 2;
                LDMX4(ah[m], A_h + off);
                LDMX4(al[m], A_l + off);
            }
            #pragma unroll
            for (int np = 0; np < 4; np++) {
                int nrow = wn * 64 + np * 16 + (jq >> 1) * 8 + jr;
                uint32_t boff = (uint32_t)(nrow * LDE + kk + (jq & 1) * 8) * 2;
                uint32_t bh[4];
                LDMX4(bh, B_h + boff);
                #pragma unroll
                for (int m = 0; m < 2; m++) {
                    MMA16816H(acc[m][2*np],   ah[m], &bh[0]);
                    MMA16816H(acc[m][2*np],   al[m], &bh[0]);
                    MMA16816H(acc[m][2*np+1], ah[m], &bh[2]);
                    MMA16816H(acc[m][2*np+1], al[m], &bh[2]);
                }
            }
        }
        __syncthreads();
        if (c + 2 < nc) issue(c + 2, buf); else CP_COMMIT();
    }

    #pragma unroll
    for (int m = 0; m < 2; m++) {
        #pragma unroll
        for (int n = 0; n < 8; n++) {
            int col = n0 + wn * 64 + n * 8 + t * 2;
            #pragma unroll
            for (int half = 0; half < 2; half++) {
                int row = m0 + wm * 32 + m * 16 + g + half * 8;
                float v0 = acc[m][n][half * 2 + 0];
                float v1 = acc[m][n][half * 2 + 1];
                if (BIAS) { v0 += bias[col]; v1 += bias[col + 1]; }
                if (GELU) { v0 = gelu1(v0); v1 = gelu1(v1); }
                size_t off = (size_t)row * N + col;
                if (RES) {
                    float2 r2 = *(const float2*)&res[off];
                    v0 += r2.x; v1 += r2.y;
                }
                if (OUT_F16) {
                    __half h0, l0, h1, l1;
                    split2h(v0, h0, l0); split2h(v1, h1, l1);
                    __half2 hp, lp;
                    hp.x = h0; hp.y = h1; lp.x = l0; lp.y = l1;
                    *(__half2*)&Ch[off] = hp;
                    *(__half2*)&Cl[off] = lp;
                } else {
                    *(float2*)&Cf[off] = make_float2(v0, v1);
                }
            }
        }
    }
}

// ================= fused HMMA flash attention (fp16 2-pass) ==================
// Q = Qh+Ql (scaled), K single, V single. S: 4 MMAs/ng; PV: 4 MMAs/ng.
#define LQ 136                         // Q/K smem row pad (128 d + 8)
#define LV 72                          // V^T smem row pad (64 keys + 8)
#define FQH 0
#define FQL (128*LQ)                   // 17408
#define FST0 (2*128*LQ)                // 34816
#define FKH 0
#define FVH (64*LQ)                    // 8704
#define FSTG (FVH + 128*LV)            // 17920 elems per stage
#define FA_SMEM ((FST0 + 2*FSTG)*2)    // 141312 bytes

__global__ __launch_bounds__(256)
void flash_attn(const __half* __restrict__ Qh, const __half* __restrict__ Ql,
                const __half* __restrict__ Kh, const __half* __restrict__ Vth,
                const int* __restrict__ mask,
                __half* __restrict__ Oh, __half* __restrict__ Ol)
{
    extern __shared__ __half fsm[];
    const int tid  = threadIdx.x;
    const int lane = tid & 31;
    const int warp = tid >> 5;
    const int g  = lane >> 2;
    const int t  = lane & 3;
    const int jq = lane >> 3;
    const int jr = lane & 7;
    const uint32_t sb = smem_u32(fsm);
    const int z = blockIdx.y, b = z >> 4, h = z & 15;
    const int q0 = blockIdx.x * 128;
    const size_t qrow0 = (size_t)b * 2048 + q0;

    {
        #pragma unroll
        for (int i = 0; i < 8; i++) {
            int v = i * 256 + tid;
            int r = v >> 4, q = v & 15;
            uint32_t so = (uint32_t)(r * LQ + q * 8) * 2;
            size_t gq = (qrow0 + r) * 2048 + h * 128 + q * 8;
            cp16(sb + (FQH)*2 + so, Qh + gq);
            cp16(sb + (FQL)*2 + so, Ql + gq);
        }
        CP_COMMIT();
    }

    auto issue_kv = [&](int kt, int s) {
        const uint32_t b0 = sb + (uint32_t)(FST0 + s * FSTG) * 2;
        #pragma unroll
        for (int i = 0; i < 4; i++) {           // K: 64 keys x 128 d (single)
            int v = i * 256 + tid;
            int r = v >> 4, q = v & 15;
            uint32_t so = (uint32_t)(r * LQ + q * 8) * 2;
            size_t gk = ((size_t)b * 2048 + kt * 64 + r) * 2048 + h * 128 + q * 8;
            cp16(b0 + (FKH)*2 + so, Kh + gk);
        }
        #pragma unroll
        for (int i = 0; i < 4; i++) {           // V^T: 128 d x 64 keys (single)
            int v = i * 256 + tid;
            int d = v >> 3, q = v & 7;
            uint32_t so = (uint32_t)(d * LV + q * 8) * 2;
            size_t gv = ((size_t)z * 128 + d) * 2048 + kt * 64 + q * 8;
            cp16(b0 + (FVH)*2 + so, Vth + gv);
        }
        CP_COMMIT();
    };

    issue_kv(0, 0);
    issue_kv(1, 1);

    const int q0w = warp * 16;
    float accO[16][4];
    #pragma unroll
    for (int n = 0; n < 16; n++)
        #pragma unroll
        for (int e = 0; e < 4; e++) accO[n][e] = 0.f;
    float m0v = -1e30f, m1v = -1e30f, l0v = 0.f, l1v = 0.f;

    for (int kt = 0; kt < 32; kt++) {
        CP_WAIT1();
        __syncthreads();
        const int s = kt & 1;
        const uint32_t K_h = sb + (uint32_t)(FST0 + s * FSTG + FKH) * 2;
        const uint32_t V_h = sb + (uint32_t)(FST0 + s * FSTG + FVH) * 2;

        // ---- S = (Qh+Ql) @ K^T ----
        float sc[8][4];
        #pragma unroll
        for (int n = 0; n < 8; n++)
            #pragma unroll
            for (int e = 0; e < 4; e++) sc[n][e] = 0.f;
        #pragma unroll
        for (int kc = 0; kc < 8; kc++) {
            int arow = q0w + (jq & 1) * 8 + jr;
            uint32_t aoff = (uint32_t)(arow * LQ + kc * 16 + (jq >> 1) * 8) * 2;
            uint32_t qh_[4], ql_[4];
            LDMX4(qh_, sb + FQH*2 + aoff);
            LDMX4(ql_, sb + FQL*2 + aoff);
            #pragma unroll
            for (int ng = 0; ng < 4; ng++) {
                int krow = ng * 16 + (jq >> 1) * 8 + jr;
                uint32_t boff = (uint32_t)(krow * LQ + kc * 16 + (jq & 1) * 8) * 2;
                uint32_t kh_[4];
                LDMX4(kh_, K_h + boff);
                MMA16816H(sc[2*ng],   qh_, &kh_[0]);
                MMA16816H(sc[2*ng],   ql_, &kh_[0]);
                MMA16816H(sc[2*ng+1], qh_, &kh_[2]);
                MMA16816H(sc[2*ng+1], ql_, &kh_[2]);
            }
        }

        // ---- mask + online softmax ----
        const int kb = b * 2048 + kt * 64;
        #pragma unroll
        for (int j = 0; j < 8; j++) {
            if (mask[kb + 8*j + 2*t]     == 0) { sc[j][0] = -1e30f; sc[j][2] = -1e30f; }
            if (mask[kb + 8*j + 2*t + 1] == 0) { sc[j][1] = -1e30f; sc[j][3] = -1e30f; }
        }
        float rm0 = -1e30f, rm1 = -1e30f;
        #pragma unroll
        for (int j = 0; j < 8; j++) {
            rm0 = fmaxf(rm0, fmaxf(sc[j][0], sc[j][1]));
            rm1 = fmaxf(rm1, fmaxf(sc[j][2], sc[j][3]));
        }
        rm0 = fmaxf(rm0, __shfl_xor_sync(0xffffffffu, rm0, 1));
        rm0 = fmaxf(rm0, __shfl_xor_sync(0xffffffffu, rm0, 2));
        rm1 = fmaxf(rm1, __shfl_xor_sync(0xffffffffu, rm1, 1));
        rm1 = fmaxf(rm1, __shfl_xor_sync(0xffffffffu, rm1, 2));
        float mn0 = fmaxf(m0v, rm0), mn1 = fmaxf(m1v, rm1);
        float c0 = __expf(m0v - mn0), c1 = __expf(m1v - mn1);
        float p[8][4], rs0 = 0.f, rs1 = 0.f;
        #pragma unroll
        for (int j = 0; j < 8; j++) {
            p[j][0] = __expf(sc[j][0] - mn0);
            p[j][1] = __expf(sc[j][1] - mn0);
            p[j][2] = __expf(sc[j][2] - mn1);
            p[j][3] = __expf(sc[j][3] - mn1);
            rs0 += p[j][0] + p[j][1];
            rs1 += p[j][2] + p[j][3];
        }
        rs0 += __shfl_xor_sync(0xffffffffu, rs0, 1);
        rs0 += __shfl_xor_sync(0xffffffffu, rs0, 2);
        rs1 += __shfl_xor_sync(0xffffffffu, rs1, 1);
        rs1 += __shfl_xor_sync(0xffffffffu, rs1, 2);
        l0v = l0v * c0 + rs0;  m0v = mn0;
        l1v = l1v * c1 + rs1;  m1v = mn1;
        #pragma unroll
        for (int n = 0; n < 16; n++) {
            accO[n][0] *= c0; accO[n][1] *= c0;
            accO[n][2] *= c1; accO[n][3] *= c1;
        }

        // ---- O += (Ph+Pl) @ V^T ----
        #pragma unroll
        for (int kc = 0; kc < 4; kc++) {
            uint32_t a_h[4], a_l[4];
            #pragma unroll
            for (int q = 0; q < 2; q++) {
                float v0 = p[2*kc+q][0], v1 = p[2*kc+q][1];
                float v2 = p[2*kc+q][2], v3 = p[2*kc+q][3];
                uint32_t h01 = packh2(v0, v1), h23 = packh2(v2, v3);
                __half2 hb01 = *(__half2*)&h01;
                __half2 hb23 = *(__half2*)&h23;
                uint32_t l01 = packh2(v0 - __half2float(hb01.x),
                                      v1 - __half2float(hb01.y));
                uint32_t l23 = packh2(v2 - __half2float(hb23.x),
                                      v3 - __half2float(hb23.y));
                a_h[2*q+0] = h01; a_h[2*q+1] = h23;
                a_l[2*q+0] = l01; a_l[2*q+1] = l23;
            }
            #pragma unroll
            for (int ng = 0; ng < 8; ng++) {
                int drow = ng * 16 + (jq >> 1) * 8 + jr;
                uint32_t boff = (uint32_t)(drow * LV + kc * 16 + (jq & 1) * 8) * 2;
                uint32_t vh_[4];
                LDMX4(vh_, V_h + boff);
                MMA16816H(accO[2*ng],   a_h, &vh_[0]);
                MMA16816H(accO[2*ng],   a_l, &vh_[0]);
                MMA16816H(accO[2*ng+1], a_h, &vh_[2]);
                MMA16816H(accO[2*ng+1], a_l, &vh_[2]);
            }
        }

        __syncthreads();
        if (kt + 2 < 32) issue_kv(kt + 2, s); else CP_COMMIT();
    }

    float inv0 = 1.0f / l0v, inv1 = 1.0f / l1v;
    const size_t r0 = qrow0 + q0w + g;
    const size_t r1 = r0 + 8;
    #pragma unroll
    for (int n = 0; n < 16; n++) {
        int col = h * 128 + n * 8 + t * 2;
        float v0 = accO[n][0] * inv0, v1 = accO[n][1] * inv0;
        float v2 = accO[n][2] * inv1, v3 = accO[n][3] * inv1;
        __half h0,l0,h1,l1,h2,l2,h3,l3;
        split2h(v0,h0,l0); split2h(v1,h1,l1); split2h(v2,h2,l2); split2h(v3,h3,l3);
        __half2 hp0, lp0, hp1, lp1;
        hp0.x=h0; hp0.y=h1; lp0.x=l0; lp0.y=l1;
        hp1.x=h2; hp1.y=h3; lp1.x=l2; lp1.y=l3;
        *(__half2*)&Oh[r0*2048 + col] = hp0;
        *(__half2*)&Ol[r0*2048 + col] = lp0;
        *(__half2*)&Oh[r1*2048 + col] = hp1;
        *(__half2*)&Ol[r1*2048 + col] = lp1;
    }
}

// ---------------- transpose + fp16 cast: W[K,N] -> Th[N,K] ------------------
__global__ __launch_bounds__(256)
void transpose_half(const float* __restrict__ W, int K, int N,
                    __half* __restrict__ Th)
{
    __shared__ float tile[32][33];
    const int tx = threadIdx.x, ty = threadIdx.y;
    const int n0 = blockIdx.x * 32, k0 = blockIdx.y * 32;
    #pragma unroll
    for (int i = 0; i < 4; i++)
        tile[ty + 8*i][tx] = W[(size_t)(k0 + ty + 8*i) * N + n0 + tx];
    __syncthreads();
    #pragma unroll
    for (int i = 0; i < 4; i++) {
        float v = tile[tx][ty + 8*i];
        Th[(size_t)(n0 + ty + 8*i) * K + k0 + tx] = __float2half(v);
    }
}

// ---------------- qk prep: qkv fp32 -> Q(scaled) hi/lo, K single fp16 -------
__global__ __launch_bounds__(256)
void qk_prep(const float* __restrict__ qkv,
             __half* __restrict__ qh, __half* __restrict__ ql,
             __half* __restrict__ kh)
{
    const float scale = 0.088388347648318447f;
    size_t e = ((size_t)blockIdx.x * 256 + threadIdx.x) * 4;
    int row = (int)(e >> 12);
    int col = (int)(e & 4095);
    float4 v = *(const float4*)&qkv[(size_t)row * 6144 + col];
    if (col < 2048) {
        __half hb[4], lb[4];
        split2h(v.x*scale, hb[0], lb[0]); split2h(v.y*scale, hb[1], lb[1]);
        split2h(v.z*scale, hb[2], lb[2]); split2h(v.w*scale, hb[3], lb[3]);
        *(uint2*)&qh[(size_t)row*2048 + col] = *(uint2*)hb;
        *(uint2*)&ql[(size_t)row*2048 + col] = *(uint2*)lb;
    } else {
        __half hb[4];
        hb[0] = __float2half(v.x); hb[1] = __float2half(v.y);
        hb[2] = __float2half(v.z); hb[3] = __float2half(v.w);
        *(uint2*)&kh[(size_t)row*2048 + col - 2048] = *(uint2*)hb;
    }
}

// ---------------- v prep: transpose V per (b,h) -> [dim][keys] fp16 ---------
__global__ __launch_bounds__(256)
void v_prep(const float* __restrict__ qkv, __half* __restrict__ vth)
{
    __shared__ float tile[32][33];
    const int tx = threadIdx.x, ty = threadIdx.y;
    const int z = blockIdx.z, b = z >> 4, h = z & 15;
    const int key0 = blockIdx.x * 32, d0 = blockIdx.y * 32;
    #pragma unroll
    for (int i = 0; i < 4; i++) {
        int key = key0 + ty + 8*i;
        tile[ty + 8*i][tx] = qkv[(size_t)(b*2048 + key)*6144 + 4096 + h*128 + d0 + tx];
    }
    __syncthreads();
    #pragma unroll
    for (int i = 0; i < 4; i++) {
        int d = d0 + ty + 8*i;
        float v = tile[tx][ty + 8*i];
        vth[((size_t)z*128 + d)*2048 + key0 + tx] = __float2half(v);
    }
}

// ---------------- LayerNorm: out = LN(A [+ Ad]) * g + b ; + fp16 split ------
__global__ __launch_bounds__(256)
void ln_kernel(const float* __restrict__ A, const float* __restrict__ Ad,
               const float* __restrict__ g, const float* __restrict__ bb,
               float* __restrict__ out, __half* __restrict__ oh,
               __half* __restrict__ ol)
{
    const int row = blockIdx.x, t = threadIdx.x;
    const float* a = A + (size_t)row * D_;
    float4 v[2];
    float s = 0.f, ss = 0.f;
    #pragma unroll
    for (int i = 0; i < 2; i++) {
        int idx = (i*256 + t) * 4;
        float4 x = *(const float4*)&a[idx];
        if (Ad) {
            float4 y = *(const float4*)&Ad[(size_t)row*D_ + idx];
            x.x += y.x; x.y += y.y; x.z += y.z; x.w += y.w;
        }
        v[i] = x;
        s  += x.x + x.y + x.z + x.w;
        ss += x.x*x.x + x.y*x.y + x.z*x.z + x.w*x.w;
    }
    #pragma unroll
    for (int off = 16; off; off >>= 1) {
        s  += __shfl_xor_sync(0xffffffffu, s,  off);
        ss += __shfl_xor_sync(0xffffffffu, ss, off);
    }
    __shared__ float sb[8], ssb[8];
    if ((t & 31) == 0) { sb[t>>5] = s; ssb[t>>5] = ss; }
    __syncthreads();
    float st = 0.f, sst = 0.f;
    #pragma unroll
    for (int i = 0; i < 8; i++) { st += sb[i]; sst += ssb[i]; }
    float mean = st * (1.f / D_);
    float var  = sst * (1.f / D_) - mean * mean;
    float rstd = rsqrtf(var + 1e-5f);
    #pragma unroll
    for (int i = 0; i < 2; i++) {
        int idx = (i*256 + t) * 4;
        float4 gg  = *(const float4*)&g[idx];
        float4 bbv = *(const float4*)&bb[idx];
        float4 x = v[i], o;
        o.x = (x.x - mean)*rstd*gg.x + bbv.x;
        o.y = (x.y - mean)*rstd*gg.y + bbv.y;
        o.z = (x.z - mean)*rstd*gg.z + bbv.z;
        o.w = (x.w - mean)*rstd*gg.w + bbv.w;
        if (out) *(float4*)&out[(size_t)row*D_ + idx] = o;
        __half hb[4], lb[4];
        split2h(o.x, hb[0], lb[0]); split2h(o.y, hb[1], lb[1]);
        split2h(o.z, hb[2], lb[2]); split2h(o.w, hb[3], lb[3]);
        *(uint2*)&oh[(size_t)row*D_ + idx] = *(uint2*)hb;
        *(uint2*)&ol[(size_t)row*D_ + idx] = *(uint2*)lb;
    }
}

// ---------------- persona vector (2-stage, deterministic) -------------------
__global__ __launch_bounds__(256)
void pers_part(const float* __restrict__ pemb, const int* __restrict__ trait,
               const float* __restrict__ dw, float* __restrict__ part)
{
    int j = blockIdx.x * 256 + threadIdx.x;
    int seg = blockIdx.y;
    int tix = trait[0];
    const float* pe = pemb + (size_t)tix * D_;
    float acc = 0.f;
    int i0 = seg * 64;
    #pragma unroll 8
    for (int i = i0; i < i0 + 64; ++i)
        acc = fmaf(pe[i], dw[(size_t)(D_ + i) * D_ + j], acc);
    part[(size_t)seg * D_ + j] = acc;
}
__global__ __launch_bounds__(256)
void pers_reduce(const float* __restrict__ part, const float* __restrict__ db,
                 float* __restrict__ out)
{
    int j = blockIdx.x * 256 + threadIdx.x;
    float s = db[j];
    #pragma unroll
    for (int k = 0; k < 32; ++k) s += part[(size_t)k * D_ + j];
    out[j] = s;
}

// ---------------- launch ----------------------------------------------------
extern "C" void kernel_launch(void* const* d_in, const int* in_sizes, int n_in,
                              void* d_out, int out_size)
{
    const float* x     = (const float*)d_in[0];
    const int*   mask  = (const int*)  d_in[1];
    const int*   trait = (const int*)  d_in[2];
    const float* wq    = (const float*)d_in[3];
    const float* wk    = (const float*)d_in[4];
    const float* wv    = (const float*)d_in[5];
    const float* wo    = (const float*)d_in[6];
    const float* g1    = (const float*)d_in[7];
    const float* b1    = (const float*)d_in[8];
    const float* g2    = (const float*)d_in[9];
    const float* b2    = (const float*)d_in[10];
    const float* rw1   = (const float*)d_in[11];
    const float* rb1   = (const float*)d_in[12];
    const float* rw2   = (const float*)d_in[13];
    const float* rb2   = (const float*)d_in[14];
    const float* rg    = (const float*)d_in[15];
    const float* rb    = (const float*)d_in[16];
    const float* pemb  = (const float*)d_in[17];
    const float* dw    = (const float*)d_in[18];
    const float* db    = (const float*)d_in[19];
    const float* wgam  = (const float*)d_in[20];
    const float* wbet  = (const float*)d_in[21];
    const float* mw1   = (const float*)d_in[22];
    const float* mb1   = (const float*)d_in[23];
    const float* mw2   = (const float*)d_in[24];
    const float* mb2   = (const float*)d_in[25];
    float* out = (float*)d_out;

    static float *pqkv=0,*px2=0,*pr=0,*ph2=0,*ph3=0,*ppers=0,*pppart=0;
    static __half *pah=0,*pal=0,*pth=0,*ptl=0,*pwh=0;
    static __half *pqsh=0,*pqsl=0,*pksh=0,*pvth=0;
    static bool inited = false;
    if (!inited) {
        cudaGetSymbolAddress((void**)&pqkv, g_qkv);
        cudaGetSymbolAddress((void**)&px2, g_x2);
        cudaGetSymbolAddress((void**)&pr,  g_r);
        cudaGetSymbolAddress((void**)&ph2, g_h2);
        cudaGetSymbolAddress((void**)&ph3, g_h3);
        cudaGetSymbolAddress((void**)&ppers, g_pers);
        cudaGetSymbolAddress((void**)&pppart, g_ppart);
        cudaGetSymbolAddress((void**)&pah, g_ah);
        cudaGetSymbolAddress((void**)&pal, g_al);
        cudaGetSymbolAddress((void**)&pth, g_th);
        cudaGetSymbolAddress((void**)&ptl, g_tl);
        cudaGetSymbolAddress((void**)&pwh, g_wh);
        cudaGetSymbolAddress((void**)&pqsh, g_qsh);
        cudaGetSymbolAddress((void**)&pqsl, g_qsl);
        cudaGetSymbolAddress((void**)&pksh, g_ksh);
        cudaGetSymbolAddress((void**)&pvth, g_vth);
        cudaFuncSetAttribute(tbgemm<false,false,false,false>, cudaFuncAttributeMaxDynamicSharedMemorySize, TG_SMEM);
        cudaFuncSetAttribute(tbgemm<false,false,true,false>,  cudaFuncAttributeMaxDynamicSharedMemorySize, TG_SMEM);
        cudaFuncSetAttribute(tbgemm<true,true,false,true>,    cudaFuncAttributeMaxDynamicSharedMemorySize, TG_SMEM);
        cudaFuncSetAttribute(tbgemm<false,true,false,false>,  cudaFuncAttributeMaxDynamicSharedMemorySize, TG_SMEM);
        cudaFuncSetAttribute(tbgemm<false,true,true,false>,   cudaFuncAttributeMaxDynamicSharedMemorySize, TG_SMEM);
        cudaFuncSetAttribute(flash_attn, cudaFuncAttributeMaxDynamicSharedMemorySize, FA_SMEM);
        inited = true;
    }

    const dim3 blk(256);
    const dim3 blk512(512);
    const dim3 tb(32, 8);

    // ---- weight prep (fp16 single-level) ----
    transpose_half<<<dim3(64, 64),  tb>>>(wq,  2048, 2048, pwh+OWQ);
    transpose_half<<<dim3(64, 64),  tb>>>(wk,  2048, 2048, pwh+OWK);
    transpose_half<<<dim3(64, 64),  tb>>>(wv,  2048, 2048, pwh+OWV);
    transpose_half<<<dim3(64, 64),  tb>>>(wo,  2048, 2048, pwh+OWO);
    transpose_half<<<dim3(128, 64), tb>>>(rw1, 2048, 4096, pwh+ORW1);
    transpose_half<<<dim3(64, 128), tb>>>(rw2, 4096, 2048, pwh+ORW2);
    transpose_half<<<dim3(64, 64),  tb>>>(dw,  2048, 2048, pwh+ODW);
    transpose_half<<<dim3(256, 64), tb>>>(mw1, 2048, 8192, pwh+OMW1);
    transpose_half<<<dim3(64, 256), tb>>>(mw2, 8192, 2048, pwh+OMW2);
    pers_part<<<dim3(D_/256, 32), blk>>>(pemb, trait, dw, pppart);
    pers_reduce<<<D_/256, blk>>>(pppart, db, ppers);

    // 1) h = LN1(x) -> fp16 split
    ln_kernel<<<M_, blk>>>(x, nullptr, g1, b1, nullptr, pah, pal);
    // 2) qkv = h @ [wq|wk|wv]
    tbgemm<false,false,false,false><<<dim3(24,32), blk512, TG_SMEM>>>(
        pah,pal, pwh+OWQ, nullptr,nullptr, pqkv,nullptr,nullptr, M_, 3*D_, D_);
    // 3) attention prep (fp16)
    qk_prep<<<16384, blk>>>(pqkv, pqsh, pqsl, pksh);
    v_prep<<<dim3(64, 4, 32), tb>>>(pqkv, pvth);
    // 4) fused flash attention -> pah/pal (fp16 split)
    flash_attn<<<dim3(16, 32), blk, FA_SMEM>>>(
        pqsh, pqsl, pksh, pvth, mask, pah, pal);
    // 5) x2 = x + attn_out @ wo
    tbgemm<false,false,true,false><<<dim3(8,32), blk512, TG_SMEM>>>(
        pah,pal, pwh+OWO, nullptr,x, px2,nullptr,nullptr, M_, D_, D_);
    // 6) h2 = LN2(x2)
    ln_kernel<<<M_, blk>>>(px2, nullptr, g2, b2, ph2, pah, pal);
    // 7) t = gelu(h2 @ rw1 + rb1)
    tbgemm<true,true,false,true><<<dim3(16,32), blk512, TG_SMEM>>>(
        pah,pal, pwh+ORW1, rb1,nullptr, nullptr,pth,ptl, M_, 2*D_, D_);
    // 8) r = t @ rw2 + rb2
    tbgemm<false,true,false,false><<<dim3(8,32), blk512, TG_SMEM>>>(
        pth,ptl, pwh+ORW2, rb2,nullptr, pr,nullptr,nullptr, M_, D_, 2*D_);
    // 9) h3 = LN(h2 + r)
    ln_kernel<<<M_, blk>>>(ph2, pr, rg, rb, ph3, pah, pal);
    // 10) dec = h3 @ dw[:D] + pers
    tbgemm<false,true,false,false><<<dim3(8,32), blk512, TG_SMEM>>>(
        pah,pal, pwh+ODW, ppers,nullptr, pqkv,nullptr,nullptr, M_, D_, D_);
    // 11) h4 = LN(h3 + dec)
    ln_kernel<<<M_, blk>>>(ph3, pqkv, wgam, wbet, nullptr, pah, pal);
    // 12) t = gelu(h4 @ mw1 + mb1)
    tbgemm<true,true,false,true><<<dim3(32,32), blk512, TG_SMEM>>>(
        pah,pal, pwh+OMW1, mb1,nullptr, nullptr,pth,ptl, M_, 4*D_, D_);
    // 13) out = x2 + t @ mw2 + mb2
    tbgemm<false,true,true,false><<<dim3(8,32), blk512, TG_SMEM>>>(
        pth,ptl, pwh+OMW2, mb2,px2, out,nullptr,nullptr, M_, D_, 4*D_);
}

// round 16
// speedup vs baseline: 2.4015x; 1.5289x over previous
#include <cuda_runtime.h>
#include <cuda_fp16.h>
#include <math.h>
#include <stdint.h>

#define B_  2
#define S_  2048
#define D_  2048
#define H_  16
#define HD_ 128
#define M_  (B_*S_)   // 4096 rows

// ---------------- scratch (static device globals; allocation-free) ----------
__device__ __align__(128) float g_qkv[(size_t)M_*3*D_];   // [M][6144] q|k|v
__device__ __align__(128) float g_x2 [(size_t)M_*D_];
__device__ __align__(128) float g_r  [(size_t)M_*D_];
__device__ __align__(128) float g_h2 [(size_t)M_*D_];
__device__ __align__(128) float g_h3 [(size_t)M_*D_];
__device__ __align__(128) float g_pers[D_];
__device__ __align__(128) float g_ppart[32*D_];

// fp16 activation scratch (single precision level)
__device__ __align__(128) __half g_ah[(size_t)M_*D_];
__device__ __align__(128) __half g_th[(size_t)M_*4*D_];

// attention scratch (fp16: Q hi/lo, K single, V^T single)
__device__ __align__(128) __half g_qsh[(size_t)M_*D_];
__device__ __align__(128) __half g_qsl[(size_t)M_*D_];
__device__ __align__(128) __half g_ksh[(size_t)M_*D_];
__device__ __align__(128) __half g_vth[(size_t)32*HD_*S_];   // [bh][128][2048]

// fp16 transposed weights (single level), packed pool: [N,K] row-major
#define OWQ  ((size_t)0)
#define OWK  ((size_t)4194304)
#define OWV  ((size_t)8388608)
#define OWO  ((size_t)12582912)
#define ORW1 ((size_t)16777216)
#define ORW2 ((size_t)25165824)
#define ODW  ((size_t)33554432)
#define OMW1 ((size_t)37748736)
#define OMW2 ((size_t)54525952)
#define WTOT ((size_t)71303168)
__device__ __align__(128) __half g_wh[WTOT];

// ---------------- helpers ----------------------------------------------------
__device__ __forceinline__ void split2h(float v, __half& h, __half& l) {
    h = __float2half(v);
    l = __float2half(v - __half2float(h));
}
__device__ __forceinline__ uint32_t smem_u32(const void* p) {
    uint32_t a;
    asm("{ .reg .u64 t; cvta.to.shared.u64 t, %1; cvt.u32.u64 %0, t; }" : "=r"(a) : "l"(p));
    return a;
}
__device__ __forceinline__ uint32_t packh2(float a, float b) {
    __half2 p;
    p.x = __float2half(a); p.y = __float2half(b);
    return *(uint32_t*)&p;
}

#define MMA16816H(d, a, b) \
    asm volatile("mma.sync.aligned.m16n8k16.row.col.f32.f16.f16.f32 " \
        "{%0,%1,%2,%3}, {%4,%5,%6,%7}, {%8,%9}, {%0,%1,%2,%3};" \
        : "+f"((d)[0]), "+f"((d)[1]), "+f"((d)[2]), "+f"((d)[3]) \
        : "r"((a)[0]), "r"((a)[1]), "r"((a)[2]), "r"((a)[3]), "r"((b)[0]), "r"((b)[1]))

#define LDMX4(d, addr) \
    asm volatile("ldmatrix.sync.aligned.m8n8.x4.shared.b16 {%0,%1,%2,%3}, [%4];" \
        : "=r"((d)[0]), "=r"((d)[1]), "=r"((d)[2]), "=r"((d)[3]) : "r"(addr))

__device__ __forceinline__ void cp16(uint32_t dst, const void* src) {
    asm volatile("cp.async.cg.shared.global [%0], [%1], 16;" :: "r"(dst), "l"(src));
}
#define CP_COMMIT() asm volatile("cp.async.commit_group;" ::: "memory")
#define CP_WAIT1()  asm volatile("cp.async.wait_group 1;" ::: "memory")

__device__ __forceinline__ float gelu1(float v) {
    return 0.5f * v * (1.0f + erff(v * 0.70710678118654752f));
}

// ================= HMMA GEMM (fp16 1-pass): 128x256 tile, 512 thr, KC=64 =====
// C = A @ B^T, single fp16 both sides, fp32 accumulate.
#define LDE 72
#define AME (128*LDE)                  // 9216 elems
#define BME (256*LDE)                  // 18432 elems
#define STAGE_B ((AME + BME)*2)        // 55296 bytes
#define TG_SMEM (2*STAGE_B)            // 110592 bytes

template<bool GELU, bool BIAS, bool RES, bool OUT_F16>
__global__ __launch_bounds__(512, 1)
void tbgemm(const __half* __restrict__ Ah, const __half* __restrict__ Bh,
            const float* __restrict__ bias, const float* __restrict__ res,
            float* __restrict__ Cf, __half* __restrict__ Ch,
            int M, int N, int K)
{
    extern __shared__ __half sm[];
    const int tid  = threadIdx.x;
    const int lane = tid & 31;
    const int warp = tid >> 5;
    const int wm = warp & 3;
    const int wn = warp >> 2;
    const int m0 = blockIdx.y * 128;
    const int n0 = blockIdx.x * 256;
    const int g  = lane >> 2;
    const int t  = lane & 3;
    const uint32_t sbase = smem_u32(sm);
    const int jq = lane >> 3;
    const int jr = lane & 7;

    float acc[2][8][4];
    #pragma unroll
    for (int m = 0; m < 2; m++)
        #pragma unroll
        for (int n = 0; n < 8; n++)
            #pragma unroll
            for (int e = 0; e < 4; e++) acc[m][n][e] = 0.f;

    auto issue = [&](int c, int buf) {
        const int k0 = c << 6;
        const uint32_t b0 = sbase + (uint32_t)buf * STAGE_B;
        #pragma unroll
        for (int i = 0; i < 2; i++) {          // A: 128 rows x 64
            int v = i * 512 + tid;
            int r = v >> 3, q = v & 7;
            uint32_t so = (uint32_t)(r * LDE + q * 8) * 2;
            size_t ga = (size_t)(m0 + r) * K + k0 + q * 8;
            cp16(b0 + so, Ah + ga);
        }
        #pragma unroll
        for (int i = 0; i < 4; i++) {          // B: 256 rows x 64
            int v = i * 512 + tid;
            int r = v >> 3, q = v & 7;
            uint32_t so = (uint32_t)(r * LDE + q * 8) * 2;
            size_t gb = (size_t)(n0 + r) * K + k0 + q * 8;
            cp16(b0 + AME*2 + so, Bh + gb);
        }
        CP_COMMIT();
    };

    const int nc = K >> 6;
    issue(0, 0);
    if (nc > 1) issue(1, 1); else CP_COMMIT();

    for (int c = 0; c < nc; c++) {
        const int buf = c & 1;
        CP_WAIT1();
        __syncthreads();

        const uint32_t A_h = sbase + (uint32_t)buf * STAGE_B;
        const uint32_t B_h = A_h + AME*2;

        #pragma unroll
        for (int kk = 0; kk < 64; kk += 16) {
            uint32_t ah[2][4];
            #pragma unroll
            for (int m = 0; m < 2; m++) {
                int row = wm * 32 + m * 16 + (jq & 1) * 8 + jr;
                uint32_t off = (uint32_t)(row * LDE + kk + (jq >> 1) * 8) * 2;
                LDMX4(ah[m], A_h + off);
            }
            #pragma unroll
            for (int np = 0; np < 4; np++) {
                int nrow = wn * 64 + np * 16 + (jq >> 1) * 8 + jr;
                uint32_t boff = (uint32_t)(nrow * LDE + kk + (jq & 1) * 8) * 2;
                uint32_t bh[4];
                LDMX4(bh, B_h + boff);
                #pragma unroll
                for (int m = 0; m < 2; m++) {
                    MMA16816H(acc[m][2*np],   ah[m], &bh[0]);
                    MMA16816H(acc[m][2*np+1], ah[m], &bh[2]);
                }
            }
        }
        __syncthreads();
        if (c + 2 < nc) issue(c + 2, buf); else CP_COMMIT();
    }

    #pragma unroll
    for (int m = 0; m < 2; m++) {
        #pragma unroll
        for (int n = 0; n < 8; n++) {
            int col = n0 + wn * 64 + n * 8 + t * 2;
            #pragma unroll
            for (int half = 0; half < 2; half++) {
                int row = m0 + wm * 32 + m * 16 + g + half * 8;
                float v0 = acc[m][n][half * 2 + 0];
                float v1 = acc[m][n][half * 2 + 1];
                if (BIAS) { v0 += bias[col]; v1 += bias[col + 1]; }
                if (GELU) { v0 = gelu1(v0); v1 = gelu1(v1); }
                size_t off = (size_t)row * N + col;
                if (RES) {
                    float2 r2 = *(const float2*)&res[off];
                    v0 += r2.x; v1 += r2.y;
                }
                if (OUT_F16) {
                    __half2 hp;
                    hp.x = __float2half(v0); hp.y = __float2half(v1);
                    *(__half2*)&Ch[off] = hp;
                } else {
                    *(float2*)&Cf[off] = make_float2(v0, v1);
                }
            }
        }
    }
}

// ================= fused HMMA flash attention (fp16, Q 2-pass) ===============
#define LQ 136                         // Q/K smem row pad (128 d + 8)
#define LV 72                          // V^T smem row pad (64 keys + 8)
#define FQH 0
#define FQL (128*LQ)                   // 17408
#define FST0 (2*128*LQ)                // 34816
#define FKH 0
#define FVH (64*LQ)                    // 8704
#define FSTG (FVH + 128*LV)            // 17920 elems per stage
#define FA_SMEM ((FST0 + 2*FSTG)*2)    // 141312 bytes

__global__ __launch_bounds__(256)
void flash_attn(const __half* __restrict__ Qh, const __half* __restrict__ Ql,
                const __half* __restrict__ Kh, const __half* __restrict__ Vth,
                const int* __restrict__ mask,
                __half* __restrict__ Oh)
{
    extern __shared__ __half fsm[];
    const int tid  = threadIdx.x;
    const int lane = tid & 31;
    const int warp = tid >> 5;
    const int g  = lane >> 2;
    const int t  = lane & 3;
    const int jq = lane >> 3;
    const int jr = lane & 7;
    const uint32_t sb = smem_u32(fsm);
    const int z = blockIdx.y, b = z >> 4, h = z & 15;
    const int q0 = blockIdx.x * 128;
    const size_t qrow0 = (size_t)b * 2048 + q0;

    {
        #pragma unroll
        for (int i = 0; i < 8; i++) {
            int v = i * 256 + tid;
            int r = v >> 4, q = v & 15;
            uint32_t so = (uint32_t)(r * LQ + q * 8) * 2;
            size_t gq = (qrow0 + r) * 2048 + h * 128 + q * 8;
            cp16(sb + (FQH)*2 + so, Qh + gq);
            cp16(sb + (FQL)*2 + so, Ql + gq);
        }
        CP_COMMIT();
    }

    auto issue_kv = [&](int kt, int s) {
        const uint32_t b0 = sb + (uint32_t)(FST0 + s * FSTG) * 2;
        #pragma unroll
        for (int i = 0; i < 4; i++) {
            int v = i * 256 + tid;
            int r = v >> 4, q = v & 15;
            uint32_t so = (uint32_t)(r * LQ + q * 8) * 2;
            size_t gk = ((size_t)b * 2048 + kt * 64 + r) * 2048 + h * 128 + q * 8;
            cp16(b0 + (FKH)*2 + so, Kh + gk);
        }
        #pragma unroll
        for (int i = 0; i < 4; i++) {
            int v = i * 256 + tid;
            int d = v >> 3, q = v & 7;
            uint32_t so = (uint32_t)(d * LV + q * 8) * 2;
            size_t gv = ((size_t)z * 128 + d) * 2048 + kt * 64 + q * 8;
            cp16(b0 + (FVH)*2 + so, Vth + gv);
        }
        CP_COMMIT();
    };

    issue_kv(0, 0);
    issue_kv(1, 1);

    const int q0w = warp * 16;
    float accO[16][4];
    #pragma unroll
    for (int n = 0; n < 16; n++)
        #pragma unroll
        for (int e = 0; e < 4; e++) accO[n][e] = 0.f;
    float m0v = -1e30f, m1v = -1e30f, l0v = 0.f, l1v = 0.f;

    for (int kt = 0; kt < 32; kt++) {
        CP_WAIT1();
        __syncthreads();
        const int s = kt & 1;
        const uint32_t K_h = sb + (uint32_t)(FST0 + s * FSTG + FKH) * 2;
        const uint32_t V_h = sb + (uint32_t)(FST0 + s * FSTG + FVH) * 2;

        // ---- S = (Qh+Ql) @ K^T ----
        float sc[8][4];
        #pragma unroll
        for (int n = 0; n < 8; n++)
            #pragma unroll
            for (int e = 0; e < 4; e++) sc[n][e] = 0.f;
        #pragma unroll
        for (int kc = 0; kc < 8; kc++) {
            int arow = q0w + (jq & 1) * 8 + jr;
            uint32_t aoff = (uint32_t)(arow * LQ + kc * 16 + (jq >> 1) * 8) * 2;
            uint32_t qh_[4], ql_[4];
            LDMX4(qh_, sb + FQH*2 + aoff);
            LDMX4(ql_, sb + FQL*2 + aoff);
            #pragma unroll
            for (int ng = 0; ng < 4; ng++) {
                int krow = ng * 16 + (jq >> 1) * 8 + jr;
                uint32_t boff = (uint32_t)(krow * LQ + kc * 16 + (jq & 1) * 8) * 2;
                uint32_t kh_[4];
                LDMX4(kh_, K_h + boff);
                MMA16816H(sc[2*ng],   qh_, &kh_[0]);
                MMA16816H(sc[2*ng],   ql_, &kh_[0]);
                MMA16816H(sc[2*ng+1], qh_, &kh_[2]);
                MMA16816H(sc[2*ng+1], ql_, &kh_[2]);
            }
        }

        // ---- mask + online softmax ----
        const int kb = b * 2048 + kt * 64;
        #pragma unroll
        for (int j = 0; j < 8; j++) {
            if (mask[kb + 8*j + 2*t]     == 0) { sc[j][0] = -1e30f; sc[j][2] = -1e30f; }
            if (mask[kb + 8*j + 2*t + 1] == 0) { sc[j][1] = -1e30f; sc[j][3] = -1e30f; }
        }
        float rm0 = -1e30f, rm1 = -1e30f;
        #pragma unroll
        for (int j = 0; j < 8; j++) {
            rm0 = fmaxf(rm0, fmaxf(sc[j][0], sc[j][1]));
            rm1 = fmaxf(rm1, fmaxf(sc[j][2], sc[j][3]));
        }
        rm0 = fmaxf(rm0, __shfl_xor_sync(0xffffffffu, rm0, 1));
        rm0 = fmaxf(rm0, __shfl_xor_sync(0xffffffffu, rm0, 2));
        rm1 = fmaxf(rm1, __shfl_xor_sync(0xffffffffu, rm1, 1));
        rm1 = fmaxf(rm1, __shfl_xor_sync(0xffffffffu, rm1, 2));
        float mn0 = fmaxf(m0v, rm0), mn1 = fmaxf(m1v, rm1);
        float c0 = __expf(m0v - mn0), c1 = __expf(m1v - mn1);
        float p[8][4], rs0 = 0.f, rs1 = 0.f;
        #pragma unroll
        for (int j = 0; j < 8; j++) {
            p[j][0] = __expf(sc[j][0] - mn0);
            p[j][1] = __expf(sc[j][1] - mn0);
            p[j][2] = __expf(sc[j][2] - mn1);
            p[j][3] = __expf(sc[j][3] - mn1);
            rs0 += p[j][0] + p[j][1];
            rs1 += p[j][2] + p[j][3];
        }
        rs0 += __shfl_xor_sync(0xffffffffu, rs0, 1);
        rs0 += __shfl_xor_sync(0xffffffffu, rs0, 2);
        rs1 += __shfl_xor_sync(0xffffffffu, rs1, 1);
        rs1 += __shfl_xor_sync(0xffffffffu, rs1, 2);
        l0v = l0v * c0 + rs0;  m0v = mn0;
        l1v = l1v * c1 + rs1;  m1v = mn1;
        #pragma unroll
        for (int n = 0; n < 16; n++) {
            accO[n][0] *= c0; accO[n][1] *= c0;
            accO[n][2] *= c1; accO[n][3] *= c1;
        }

        // ---- O += (Ph+Pl) @ V^T ----
        #pragma unroll
        for (int kc = 0; kc < 4; kc++) {
            uint32_t a_h[4], a_l[4];
            #pragma unroll
            for (int q = 0; q < 2; q++) {
                float v0 = p[2*kc+q][0], v1 = p[2*kc+q][1];
                float v2 = p[2*kc+q][2], v3 = p[2*kc+q][3];
                uint32_t h01 = packh2(v0, v1), h23 = packh2(v2, v3);
                __half2 hb01 = *(__half2*)&h01;
                __half2 hb23 = *(__half2*)&h23;
                uint32_t l01 = packh2(v0 - __half2float(hb01.x),
                                      v1 - __half2float(hb01.y));
                uint32_t l23 = packh2(v2 - __half2float(hb23.x),
                                      v3 - __half2float(hb23.y));
                a_h[2*q+0] = h01; a_h[2*q+1] = h23;
                a_l[2*q+0] = l01; a_l[2*q+1] = l23;
            }
            #pragma unroll
            for (int ng = 0; ng < 8; ng++) {
                int drow = ng * 16 + (jq >> 1) * 8 + jr;
                uint32_t boff = (uint32_t)(drow * LV + kc * 16 + (jq & 1) * 8) * 2;
                uint32_t vh_[4];
                LDMX4(vh_, V_h + boff);
                MMA16816H(accO[2*ng],   a_h, &vh_[0]);
                MMA16816H(accO[2*ng],   a_l, &vh_[0]);
                MMA16816H(accO[2*ng+1], a_h, &vh_[2]);
                MMA16816H(accO[2*ng+1], a_l, &vh_[2]);
            }
        }

        __syncthreads();
        if (kt + 2 < 32) issue_kv(kt + 2, s); else CP_COMMIT();
    }

    float inv0 = 1.0f / l0v, inv1 = 1.0f / l1v;
    const size_t r0 = qrow0 + q0w + g;
    const size_t r1 = r0 + 8;
    #pragma unroll
    for (int n = 0; n < 16; n++) {
        int col = h * 128 + n * 8 + t * 2;
        __half2 hp0, hp1;
        hp0.x = __float2half(accO[n][0] * inv0);
        hp0.y = __float2half(accO[n][1] * inv0);
        hp1.x = __float2half(accO[n][2] * inv1);
        hp1.y = __float2half(accO[n][3] * inv1);
        *(__half2*)&Oh[r0*2048 + col] = hp0;
        *(__half2*)&Oh[r1*2048 + col] = hp1;
    }
}

// ---------------- transpose + fp16 cast: W[K,N] -> Th[N,K] ------------------
__global__ __launch_bounds__(256)
void transpose_half(const float* __restrict__ W, int K, int N,
                    __half* __restrict__ Th)
{
    __shared__ float tile[32][33];
    const int tx = threadIdx.x, ty = threadIdx.y;
    const int n0 = blockIdx.x * 32, k0 = blockIdx.y * 32;
    #pragma unroll
    for (int i = 0; i < 4; i++)
        tile[ty + 8*i][tx] = W[(size_t)(k0 + ty + 8*i) * N + n0 + tx];
    __syncthreads();
    #pragma unroll
    for (int i = 0; i < 4; i++) {
        float v = tile[tx][ty + 8*i];
        Th[(size_t)(n0 + ty + 8*i) * K + k0 + tx] = __float2half(v);
    }
}

// ---------------- qk prep: qkv fp32 -> Q(scaled) hi/lo, K single fp16 -------
__global__ __launch_bounds__(256)
void qk_prep(const float* __restrict__ qkv,
             __half* __restrict__ qh, __half* __restrict__ ql,
             __half* __restrict__ kh)
{
    const float scale = 0.088388347648318447f;
    size_t e = ((size_t)blockIdx.x * 256 + threadIdx.x) * 4;
    int row = (int)(e >> 12);
    int col = (int)(e & 4095);
    float4 v = *(const float4*)&qkv[(size_t)row * 6144 + col];
    if (col < 2048) {
        __half hb[4], lb[4];
        split2h(v.x*scale, hb[0], lb[0]); split2h(v.y*scale, hb[1], lb[1]);
        split2h(v.z*scale, hb[2], lb[2]); split2h(v.w*scale, hb[3], lb[3]);
        *(uint2*)&qh[(size_t)row*2048 + col] = *(uint2*)hb;
        *(uint2*)&ql[(size_t)row*2048 + col] = *(uint2*)lb;
    } else {
        __half hb[4];
        hb[0] = __float2half(v.x); hb[1] = __float2half(v.y);
        hb[2] = __float2half(v.z); hb[3] = __float2half(v.w);
        *(uint2*)&kh[(size_t)row*2048 + col - 2048] = *(uint2*)hb;
    }
}

// ---------------- v prep: transpose V per (b,h) -> [dim][keys] fp16 ---------
__global__ __launch_bounds__(256)
void v_prep(const float* __restrict__ qkv, __half* __restrict__ vth)
{
    __shared__ float tile[32][33];
    const int tx = threadIdx.x, ty = threadIdx.y;
    const int z = blockIdx.z, b = z >> 4, h = z & 15;
    const int key0 = blockIdx.x * 32, d0 = blockIdx.y * 32;
    #pragma unroll
    for (int i = 0; i < 4; i++) {
        int key = key0 + ty + 8*i;
        tile[ty + 8*i][tx] = qkv[(size_t)(b*2048 + key)*6144 + 4096 + h*128 + d0 + tx];
    }
    __syncthreads();
    #pragma unroll
    for (int i = 0; i < 4; i++) {
        int d = d0 + ty + 8*i;
        float v = tile[tx][ty + 8*i];
        vth[((size_t)z*128 + d)*2048 + key0 + tx] = __float2half(v);
    }
}

// ---------------- LayerNorm: out = LN(A [+ Ad]) * g + b ; + fp16 cast -------
__global__ __launch_bounds__(256)
void ln_kernel(const float* __restrict__ A, const float* __restrict__ Ad,
               const float* __restrict__ g, const float* __restrict__ bb,
               float* __restrict__ out, __half* __restrict__ oh)
{
    const int row = blockIdx.x, t = threadIdx.x;
    const float* a = A + (size_t)row * D_;
    float4 v[2];
    float s = 0.f, ss = 0.f;
    #pragma unroll
    for (int i = 0; i < 2; i++) {
        int idx = (i*256 + t) * 4;
        float4 x = *(const float4*)&a[idx];
        if (Ad) {
            float4 y = *(const float4*)&Ad[(size_t)row*D_ + idx];
            x.x += y.x; x.y += y.y; x.z += y.z; x.w += y.w;
        }
        v[i] = x;
        s  += x.x + x.y + x.z + x.w;
        ss += x.x*x.x + x.y*x.y + x.z*x.z + x.w*x.w;
    }
    #pragma unroll
    for (int off = 16; off; off >>= 1) {
        s  += __shfl_xor_sync(0xffffffffu, s,  off);
        ss += __shfl_xor_sync(0xffffffffu, ss, off);
    }
    __shared__ float sb[8], ssb[8];
    if ((t & 31) == 0) { sb[t>>5] = s; ssb[t>>5] = ss; }
    __syncthreads();
    float st = 0.f, sst = 0.f;
    #pragma unroll
    for (int i = 0; i < 8; i++) { st += sb[i]; sst += ssb[i]; }
    float mean = st * (1.f / D_);
    float var  = sst * (1.f / D_) - mean * mean;
    float rstd = rsqrtf(var + 1e-5f);
    #pragma unroll
    for (int i = 0; i < 2; i++) {
        int idx = (i*256 + t) * 4;
        float4 gg  = *(const float4*)&g[idx];
        float4 bbv = *(const float4*)&bb[idx];
        float4 x = v[i], o;
        o.x = (x.x - mean)*rstd*gg.x + bbv.x;
        o.y = (x.y - mean)*rstd*gg.y + bbv.y;
        o.z = (x.z - mean)*rstd*gg.z + bbv.z;
        o.w = (x.w - mean)*rstd*gg.w + bbv.w;
        if (out) *(float4*)&out[(size_t)row*D_ + idx] = o;
        __half hb[4];
        hb[0] = __float2half(o.x); hb[1] = __float2half(o.y);
        hb[2] = __float2half(o.z); hb[3] = __float2half(o.w);
        *(uint2*)&oh[(size_t)row*D_ + idx] = *(uint2*)hb;
    }
}

// ---------------- persona vector (2-stage, deterministic) -------------------
__global__ __launch_bounds__(256)
void pers_part(const float* __restrict__ pemb, const int* __restrict__ trait,
               const float* __restrict__ dw, float* __restrict__ part)
{
    int j = blockIdx.x * 256 + threadIdx.x;
    int seg = blockIdx.y;
    int tix = trait[0];
    const float* pe = pemb + (size_t)tix * D_;
    float acc = 0.f;
    int i0 = seg * 64;
    #pragma unroll 8
    for (int i = i0; i < i0 + 64; ++i)
        acc = fmaf(pe[i], dw[(size_t)(D_ + i) * D_ + j], acc);
    part[(size_t)seg * D_ + j] = acc;
}
__global__ __launch_bounds__(256)
void pers_reduce(const float* __restrict__ part, const float* __restrict__ db,
                 float* __restrict__ out)
{
    int j = blockIdx.x * 256 + threadIdx.x;
    float s = db[j];
    #pragma unroll
    for (int k = 0; k < 32; ++k) s += part[(size_t)k * D_ + j];
    out[j] = s;
}

// ---------------- launch ----------------------------------------------------
extern "C" void kernel_launch(void* const* d_in, const int* in_sizes, int n_in,
                              void* d_out, int out_size)
{
    const float* x     = (const float*)d_in[0];
    const int*   mask  = (const int*)  d_in[1];
    const int*   trait = (const int*)  d_in[2];
    const float* wq    = (const float*)d_in[3];
    const float* wk    = (const float*)d_in[4];
    const float* wv    = (const float*)d_in[5];
    const float* wo    = (const float*)d_in[6];
    const float* g1    = (const float*)d_in[7];
    const float* b1    = (const float*)d_in[8];
    const float* g2    = (const float*)d_in[9];
    const float* b2    = (const float*)d_in[10];
    const float* rw1   = (const float*)d_in[11];
    const float* rb1   = (const float*)d_in[12];
    const float* rw2   = (const float*)d_in[13];
    const float* rb2   = (const float*)d_in[14];
    const float* rg    = (const float*)d_in[15];
    const float* rb    = (const float*)d_in[16];
    const float* pemb  = (const float*)d_in[17];
    const float* dw    = (const float*)d_in[18];
    const float* db    = (const float*)d_in[19];
    const float* wgam  = (const float*)d_in[20];
    const float* wbet  = (const float*)d_in[21];
    const float* mw1   = (const float*)d_in[22];
    const float* mb1   = (const float*)d_in[23];
    const float* mw2   = (const float*)d_in[24];
    const float* mb2   = (const float*)d_in[25];
    float* out = (float*)d_out;

    static float *pqkv=0,*px2=0,*pr=0,*ph2=0,*ph3=0,*ppers=0,*pppart=0;
    static __half *pah=0,*pth=0,*pwh=0;
    static __half *pqsh=0,*pqsl=0,*pksh=0,*pvth=0;
    static bool inited = false;
    if (!inited) {
        cudaGetSymbolAddress((void**)&pqkv, g_qkv);
        cudaGetSymbolAddress((void**)&px2, g_x2);
        cudaGetSymbolAddress((void**)&pr,  g_r);
        cudaGetSymbolAddress((void**)&ph2, g_h2);
        cudaGetSymbolAddress((void**)&ph3, g_h3);
        cudaGetSymbolAddress((void**)&ppers, g_pers);
        cudaGetSymbolAddress((void**)&pppart, g_ppart);
        cudaGetSymbolAddress((void**)&pah, g_ah);
        cudaGetSymbolAddress((void**)&pth, g_th);
        cudaGetSymbolAddress((void**)&pwh, g_wh);
        cudaGetSymbolAddress((void**)&pqsh, g_qsh);
        cudaGetSymbolAddress((void**)&pqsl, g_qsl);
        cudaGetSymbolAddress((void**)&pksh, g_ksh);
        cudaGetSymbolAddress((void**)&pvth, g_vth);
        cudaFuncSetAttribute(tbgemm<false,false,false,false>, cudaFuncAttributeMaxDynamicSharedMemorySize, TG_SMEM);
        cudaFuncSetAttribute(tbgemm<false,false,true,false>,  cudaFuncAttributeMaxDynamicSharedMemorySize, TG_SMEM);
        cudaFuncSetAttribute(tbgemm<true,true,false,true>,    cudaFuncAttributeMaxDynamicSharedMemorySize, TG_SMEM);
        cudaFuncSetAttribute(tbgemm<false,true,false,false>,  cudaFuncAttributeMaxDynamicSharedMemorySize, TG_SMEM);
        cudaFuncSetAttribute(tbgemm<false,true,true,false>,   cudaFuncAttributeMaxDynamicSharedMemorySize, TG_SMEM);
        cudaFuncSetAttribute(flash_attn, cudaFuncAttributeMaxDynamicSharedMemorySize, FA_SMEM);
        inited = true;
    }

    const dim3 blk(256);
    const dim3 blk512(512);
    const dim3 tb(32, 8);

    // ---- weight prep (fp16 single-level) ----
    transpose_half<<<dim3(64, 64),  tb>>>(wq,  2048, 2048, pwh+OWQ);
    transpose_half<<<dim3(64, 64),  tb>>>(wk,  2048, 2048, pwh+OWK);
    transpose_half<<<dim3(64, 64),  tb>>>(wv,  2048, 2048, pwh+OWV);
    transpose_half<<<dim3(64, 64),  tb>>>(wo,  2048, 2048, pwh+OWO);
    transpose_half<<<dim3(128, 64), tb>>>(rw1, 2048, 4096, pwh+ORW1);
    transpose_half<<<dim3(64, 128), tb>>>(rw2, 4096, 2048, pwh+ORW2);
    transpose_half<<<dim3(64, 64),  tb>>>(dw,  2048, 2048, pwh+ODW);
    transpose_half<<<dim3(256, 64), tb>>>(mw1, 2048, 8192, pwh+OMW1);
    transpose_half<<<dim3(64, 256), tb>>>(mw2, 8192, 2048, pwh+OMW2);
    pers_part<<<dim3(D_/256, 32), blk>>>(pemb, trait, dw, pppart);
    pers_reduce<<<D_/256, blk>>>(pppart, db, ppers);

    // 1) h = LN1(x) -> fp16
    ln_kernel<<<M_, blk>>>(x, nullptr, g1, b1, nullptr, pah);
    // 2) qkv = h @ [wq|wk|wv]
    tbgemm<false,false,false,false><<<dim3(24,32), blk512, TG_SMEM>>>(
        pah, pwh+OWQ, nullptr,nullptr, pqkv,nullptr, M_, 3*D_, D_);
    // 3) attention prep (fp16)
    qk_prep<<<16384, blk>>>(pqkv, pqsh, pqsl, pksh);
    v_prep<<<dim3(64, 4, 32), tb>>>(pqkv, pvth);
    // 4) fused flash attention -> pah (fp16)
    flash_attn<<<dim3(16, 32), blk, FA_SMEM>>>(
        pqsh, pqsl, pksh, pvth, mask, pah);
    // 5) x2 = x + attn_out @ wo
    tbgemm<false,false,true,false><<<dim3(8,32), blk512, TG_SMEM>>>(
        pah, pwh+OWO, nullptr,x, px2,nullptr, M_, D_, D_);
    // 6) h2 = LN2(x2)
    ln_kernel<<<M_, blk>>>(px2, nullptr, g2, b2, ph2, pah);
    // 7) t = gelu(h2 @ rw1 + rb1)
    tbgemm<true,true,false,true><<<dim3(16,32), blk512, TG_SMEM>>>(
        pah, pwh+ORW1, rb1,nullptr, nullptr,pth, M_, 2*D_, D_);
    // 8) r = t @ rw2 + rb2
    tbgemm<false,true,false,false><<<dim3(8,32), blk512, TG_SMEM>>>(
        pth, pwh+ORW2, rb2,nullptr, pr,nullptr, M_, D_, 2*D_);
    // 9) h3 = LN(h2 + r)
    ln_kernel<<<M_, blk>>>(ph2, pr, rg, rb, ph3, pah);
    // 10) dec = h3 @ dw[:D] + pers
    tbgemm<false,true,false,false><<<dim3(8,32), blk512, TG_SMEM>>>(
        pah, pwh+ODW, ppers,nullptr, pqkv,nullptr, M_, D_, D_);
    // 11) h4 = LN(h3 + dec)
    ln_kernel<<<M_, blk>>>(ph3, pqkv, wgam, wbet, nullptr, pah);
    // 12) t = gelu(h4 @ mw1 + mb1)
    tbgemm<true,true,false,true><<<dim3(32,32), blk512, TG_SMEM>>>(
        pah, pwh+OMW1, mb1,nullptr, nullptr,pth, M_, 4*D_, D_);
    // 13) out = x2 + t @ mw2 + mb2
    tbgemm<false,true,true,false><<<dim3(8,32), blk512, TG_SMEM>>>(
        pth, pwh+OMW2, mb2,px2, out,nullptr, M_, D_, 4*D_);
}

// round 17
// speedup vs baseline: 2.5555x; 1.0641x over previous
#include <cuda_runtime.h>
#include <cuda_fp16.h>
#include <math.h>
#include <stdint.h>

#define B_  2
#define S_  2048
#define D_  2048
#define H_  16
#define HD_ 128
#define M_  (B_*S_)   // 4096 rows

// ---------------- scratch (static device globals; allocation-free) ----------
__device__ __align__(128) float g_qkv[(size_t)M_*3*D_];   // [M][6144] q|k|v
__device__ __align__(128) float g_x2 [(size_t)M_*D_];
__device__ __align__(128) float g_r  [(size_t)M_*D_];
__device__ __align__(128) float g_h2 [(size_t)M_*D_];
__device__ __align__(128) float g_h3 [(size_t)M_*D_];
__device__ __align__(128) float g_pers[D_];
__device__ __align__(128) float g_ppart[32*D_];

// fp16 activation scratch (single precision level)
__device__ __align__(128) __half g_ah[(size_t)M_*D_];
__device__ __align__(128) __half g_th[(size_t)M_*4*D_];

// attention scratch (fp16 single: Q scaled, K, V^T)
__device__ __align__(128) __half g_qsh[(size_t)M_*D_];
__device__ __align__(128) __half g_ksh[(size_t)M_*D_];
__device__ __align__(128) __half g_vth[(size_t)32*HD_*S_];   // [bh][128][2048]

// fp16 transposed weights (single level), packed pool: [N,K] row-major
#define OWQ  ((size_t)0)
#define OWK  ((size_t)4194304)
#define OWV  ((size_t)8388608)
#define OWO  ((size_t)12582912)
#define ORW1 ((size_t)16777216)
#define ORW2 ((size_t)25165824)
#define ODW  ((size_t)33554432)
#define OMW1 ((size_t)37748736)
#define OMW2 ((size_t)54525952)
#define WTOT ((size_t)71303168)
__device__ __align__(128) __half g_wh[WTOT];

// ---------------- helpers ----------------------------------------------------
__device__ __forceinline__ uint32_t smem_u32(const void* p) {
    uint32_t a;
    asm("{ .reg .u64 t; cvta.to.shared.u64 t, %1; cvt.u32.u64 %0, t; }" : "=r"(a) : "l"(p));
    return a;
}
__device__ __forceinline__ uint32_t packh2(float a, float b) {
    __half2 p;
    p.x = __float2half(a); p.y = __float2half(b);
    return *(uint32_t*)&p;
}

#define MMA16816H(d, a, b) \
    asm volatile("mma.sync.aligned.m16n8k16.row.col.f32.f16.f16.f32 " \
        "{%0,%1,%2,%3}, {%4,%5,%6,%7}, {%8,%9}, {%0,%1,%2,%3};" \
        : "+f"((d)[0]), "+f"((d)[1]), "+f"((d)[2]), "+f"((d)[3]) \
        : "r"((a)[0]), "r"((a)[1]), "r"((a)[2]), "r"((a)[3]), "r"((b)[0]), "r"((b)[1]))

#define LDMX4(d, addr) \
    asm volatile("ldmatrix.sync.aligned.m8n8.x4.shared.b16 {%0,%1,%2,%3}, [%4];" \
        : "=r"((d)[0]), "=r"((d)[1]), "=r"((d)[2]), "=r"((d)[3]) : "r"(addr))

__device__ __forceinline__ void cp16(uint32_t dst, const void* src) {
    asm volatile("cp.async.cg.shared.global [%0], [%1], 16;" :: "r"(dst), "l"(src));
}
#define CP_COMMIT() asm volatile("cp.async.commit_group;" ::: "memory")
#define CP_WAIT1()  asm volatile("cp.async.wait_group 1;" ::: "memory")

__device__ __forceinline__ float gelu1(float v) {
    return 0.5f * v * (1.0f + erff(v * 0.70710678118654752f));
}

// ================= HMMA GEMM (fp16 1-pass): 128x256 tile, 512 thr, KC=64 =====
#define LDE 72
#define AME (128*LDE)                  // 9216 elems
#define BME (256*LDE)                  // 18432 elems
#define STAGE_B ((AME + BME)*2)        // 55296 bytes
#define TG_SMEM (2*STAGE_B)            // 110592 bytes

template<bool GELU, bool BIAS, bool RES, bool OUT_F16>
__global__ __launch_bounds__(512, 1)
void tbgemm(const __half* __restrict__ Ah, const __half* __restrict__ Bh,
            const float* __restrict__ bias, const float* __restrict__ res,
            float* __restrict__ Cf, __half* __restrict__ Ch,
            int M, int N, int K)
{
    extern __shared__ __half sm[];
    const int tid  = threadIdx.x;
    const int lane = tid & 31;
    const int warp = tid >> 5;
    const int wm = warp & 3;
    const int wn = warp >> 2;
    const int m0 = blockIdx.y * 128;
    const int n0 = blockIdx.x * 256;
    const int g  = lane >> 2;
    const int t  = lane & 3;
    const uint32_t sbase = smem_u32(sm);
    const int jq = lane >> 3;
    const int jr = lane & 7;

    float acc[2][8][4];
    #pragma unroll
    for (int m = 0; m < 2; m++)
        #pragma unroll
        for (int n = 0; n < 8; n++)
            #pragma unroll
            for (int e = 0; e < 4; e++) acc[m][n][e] = 0.f;

    auto issue = [&](int c, int buf) {
        const int k0 = c << 6;
        const uint32_t b0 = sbase + (uint32_t)buf * STAGE_B;
        #pragma unroll
        for (int i = 0; i < 2; i++) {
            int v = i * 512 + tid;
            int r = v >> 3, q = v & 7;
            uint32_t so = (uint32_t)(r * LDE + q * 8) * 2;
            size_t ga = (size_t)(m0 + r) * K + k0 + q * 8;
            cp16(b0 + so, Ah + ga);
        }
        #pragma unroll
        for (int i = 0; i < 4; i++) {
            int v = i * 512 + tid;
            int r = v >> 3, q = v & 7;
            uint32_t so = (uint32_t)(r * LDE + q * 8) * 2;
            size_t gb = (size_t)(n0 + r) * K + k0 + q * 8;
            cp16(b0 + AME*2 + so, Bh + gb);
        }
        CP_COMMIT();
    };

    const int nc = K >> 6;
    issue(0, 0);
    if (nc > 1) issue(1, 1); else CP_COMMIT();

    for (int c = 0; c < nc; c++) {
        const int buf = c & 1;
        CP_WAIT1();
        __syncthreads();

        const uint32_t A_h = sbase + (uint32_t)buf * STAGE_B;
        const uint32_t B_h = A_h + AME*2;

        #pragma unroll
        for (int kk = 0; kk < 64; kk += 16) {
            uint32_t ah[2][4];
            #pragma unroll
            for (int m = 0; m < 2; m++) {
                int row = wm * 32 + m * 16 + (jq & 1) * 8 + jr;
                uint32_t off = (uint32_t)(row * LDE + kk + (jq >> 1) * 8) * 2;
                LDMX4(ah[m], A_h + off);
            }
            #pragma unroll
            for (int np = 0; np < 4; np++) {
                int nrow = wn * 64 + np * 16 + (jq >> 1) * 8 + jr;
                uint32_t boff = (uint32_t)(nrow * LDE + kk + (jq & 1) * 8) * 2;
                uint32_t bh[4];
                LDMX4(bh, B_h + boff);
                #pragma unroll
                for (int m = 0; m < 2; m++) {
                    MMA16816H(acc[m][2*np],   ah[m], &bh[0]);
                    MMA16816H(acc[m][2*np+1], ah[m], &bh[2]);
                }
            }
        }
        __syncthreads();
        if (c + 2 < nc) issue(c + 2, buf); else CP_COMMIT();
    }

    #pragma unroll
    for (int m = 0; m < 2; m++) {
        #pragma unroll
        for (int n = 0; n < 8; n++) {
            int col = n0 + wn * 64 + n * 8 + t * 2;
            #pragma unroll
            for (int half = 0; half < 2; half++) {
                int row = m0 + wm * 32 + m * 16 + g + half * 8;
                float v0 = acc[m][n][half * 2 + 0];
                float v1 = acc[m][n][half * 2 + 1];
                if (BIAS) { v0 += bias[col]; v1 += bias[col + 1]; }
                if (GELU) { v0 = gelu1(v0); v1 = gelu1(v1); }
                size_t off = (size_t)row * N + col;
                if (RES) {
                    float2 r2 = *(const float2*)&res[off];
                    v0 += r2.x; v1 += r2.y;
                }
                if (OUT_F16) {
                    __half2 hp;
                    hp.x = __float2half(v0); hp.y = __float2half(v1);
                    *(__half2*)&Ch[off] = hp;
                } else {
                    *(float2*)&Cf[off] = make_float2(v0, v1);
                }
            }
        }
    }
}

// ================= fused HMMA flash attention (fp16 single) ==================
#define LQ 136                         // Q/K smem row pad (128 d + 8)
#define LV 72                          // V^T smem row pad (64 keys + 8)
#define FQH 0
#define FST0 (128*LQ)                  // 17408
#define FKH 0
#define FVH (64*LQ)                    // 8704
#define FSTG (FVH + 128*LV)            // 17920 elems per stage
#define FA_SMEM ((FST0 + 2*FSTG)*2)    // 106496 bytes

__global__ __launch_bounds__(256)
void flash_attn(const __half* __restrict__ Qh, const __half* __restrict__ Kh,
                const __half* __restrict__ Vth,
                const int* __restrict__ mask,
                __half* __restrict__ Oh)
{
    extern __shared__ __half fsm[];
    const int tid  = threadIdx.x;
    const int lane = tid & 31;
    const int warp = tid >> 5;
    const int g  = lane >> 2;
    const int t  = lane & 3;
    const int jq = lane >> 3;
    const int jr = lane & 7;
    const uint32_t sb = smem_u32(fsm);
    const int z = blockIdx.y, b = z >> 4, h = z & 15;
    const int q0 = blockIdx.x * 128;
    const size_t qrow0 = (size_t)b * 2048 + q0;

    {
        #pragma unroll
        for (int i = 0; i < 8; i++) {
            int v = i * 256 + tid;
            int r = v >> 4, q = v & 15;
            uint32_t so = (uint32_t)(r * LQ + q * 8) * 2;
            size_t gq = (qrow0 + r) * 2048 + h * 128 + q * 8;
            cp16(sb + (FQH)*2 + so, Qh + gq);
        }
        CP_COMMIT();
    }

    auto issue_kv = [&](int kt, int s) {
        const uint32_t b0 = sb + (uint32_t)(FST0 + s * FSTG) * 2;
        #pragma unroll
        for (int i = 0; i < 4; i++) {
            int v = i * 256 + tid;
            int r = v >> 4, q = v & 15;
            uint32_t so = (uint32_t)(r * LQ + q * 8) * 2;
            size_t gk = ((size_t)b * 2048 + kt * 64 + r) * 2048 + h * 128 + q * 8;
            cp16(b0 + (FKH)*2 + so, Kh + gk);
        }
        #pragma unroll
        for (int i = 0; i < 4; i++) {
            int v = i * 256 + tid;
            int d = v >> 3, q = v & 7;
            uint32_t so = (uint32_t)(d * LV + q * 8) * 2;
            size_t gv = ((size_t)z * 128 + d) * 2048 + kt * 64 + q * 8;
            cp16(b0 + (FVH)*2 + so, Vth + gv);
        }
        CP_COMMIT();
    };

    issue_kv(0, 0);
    issue_kv(1, 1);

    const int q0w = warp * 16;
    float accO[16][4];
    #pragma unroll
    for (int n = 0; n < 16; n++)
        #pragma unroll
        for (int e = 0; e < 4; e++) accO[n][e] = 0.f;
    float m0v = -1e30f, m1v = -1e30f, l0v = 0.f, l1v = 0.f;

    for (int kt = 0; kt < 32; kt++) {
        CP_WAIT1();
        __syncthreads();
        const int s = kt & 1;
        const uint32_t K_h = sb + (uint32_t)(FST0 + s * FSTG + FKH) * 2;
        const uint32_t V_h = sb + (uint32_t)(FST0 + s * FSTG + FVH) * 2;

        // ---- S = Q @ K^T (single fp16) ----
        float sc[8][4];
        #pragma unroll
        for (int n = 0; n < 8; n++)
            #pragma unroll
            for (int e = 0; e < 4; e++) sc[n][e] = 0.f;
        #pragma unroll
        for (int kc = 0; kc < 8; kc++) {
            int arow = q0w + (jq & 1) * 8 + jr;
            uint32_t aoff = (uint32_t)(arow * LQ + kc * 16 + (jq >> 1) * 8) * 2;
            uint32_t qh_[4];
            LDMX4(qh_, sb + FQH*2 + aoff);
            #pragma unroll
            for (int ng = 0; ng < 4; ng++) {
                int krow = ng * 16 + (jq >> 1) * 8 + jr;
                uint32_t boff = (uint32_t)(krow * LQ + kc * 16 + (jq & 1) * 8) * 2;
                uint32_t kh_[4];
                LDMX4(kh_, K_h + boff);
                MMA16816H(sc[2*ng],   qh_, &kh_[0]);
                MMA16816H(sc[2*ng+1], qh_, &kh_[2]);
            }
        }

        // ---- mask + online softmax ----
        const int kb = b * 2048 + kt * 64;
        #pragma unroll
        for (int j = 0; j < 8; j++) {
            if (mask[kb + 8*j + 2*t]     == 0) { sc[j][0] = -1e30f; sc[j][2] = -1e30f; }
            if (mask[kb + 8*j + 2*t + 1] == 0) { sc[j][1] = -1e30f; sc[j][3] = -1e30f; }
        }
        float rm0 = -1e30f, rm1 = -1e30f;
        #pragma unroll
        for (int j = 0; j < 8; j++) {
            rm0 = fmaxf(rm0, fmaxf(sc[j][0], sc[j][1]));
            rm1 = fmaxf(rm1, fmaxf(sc[j][2], sc[j][3]));
        }
        rm0 = fmaxf(rm0, __shfl_xor_sync(0xffffffffu, rm0, 1));
        rm0 = fmaxf(rm0, __shfl_xor_sync(0xffffffffu, rm0, 2));
        rm1 = fmaxf(rm1, __shfl_xor_sync(0xffffffffu, rm1, 1));
        rm1 = fmaxf(rm1, __shfl_xor_sync(0xffffffffu, rm1, 2));
        float mn0 = fmaxf(m0v, rm0), mn1 = fmaxf(m1v, rm1);
        float c0 = __expf(m0v - mn0), c1 = __expf(m1v - mn1);
        float p[8][4], rs0 = 0.f, rs1 = 0.f;
        #pragma unroll
        for (int j = 0; j < 8; j++) {
            p[j][0] = __expf(sc[j][0] - mn0);
            p[j][1] = __expf(sc[j][1] - mn0);
            p[j][2] = __expf(sc[j][2] - mn1);
            p[j][3] = __expf(sc[j][3] - mn1);
            rs0 += p[j][0] + p[j][1];
            rs1 += p[j][2] + p[j][3];
        }
        rs0 += __shfl_xor_sync(0xffffffffu, rs0, 1);
        rs0 += __shfl_xor_sync(0xffffffffu, rs0, 2);
        rs1 += __shfl_xor_sync(0xffffffffu, rs1, 1);
        rs1 += __shfl_xor_sync(0xffffffffu, rs1, 2);
        l0v = l0v * c0 + rs0;  m0v = mn0;
        l1v = l1v * c1 + rs1;  m1v = mn1;
        #pragma unroll
        for (int n = 0; n < 16; n++) {
            accO[n][0] *= c0; accO[n][1] *= c0;
            accO[n][2] *= c1; accO[n][3] *= c1;
        }

        // ---- O += P @ V^T (single fp16 P) ----
        #pragma unroll
        for (int kc = 0; kc < 4; kc++) {
            uint32_t a_h[4];
            #pragma unroll
            for (int q = 0; q < 2; q++) {
                a_h[2*q+0] = packh2(p[2*kc+q][0], p[2*kc+q][1]);
                a_h[2*q+1] = packh2(p[2*kc+q][2], p[2*kc+q][3]);
            }
            #pragma unroll
            for (int ng = 0; ng < 8; ng++) {
                int drow = ng * 16 + (jq >> 1) * 8 + jr;
                uint32_t boff = (uint32_t)(drow * LV + kc * 16 + (jq & 1) * 8) * 2;
                uint32_t vh_[4];
                LDMX4(vh_, V_h + boff);
                MMA16816H(accO[2*ng],   a_h, &vh_[0]);
                MMA16816H(accO[2*ng+1], a_h, &vh_[2]);
            }
        }

        __syncthreads();
        if (kt + 2 < 32) issue_kv(kt + 2, s); else CP_COMMIT();
    }

    float inv0 = 1.0f / l0v, inv1 = 1.0f / l1v;
    const size_t r0 = qrow0 + q0w + g;
    const size_t r1 = r0 + 8;
    #pragma unroll
    for (int n = 0; n < 16; n++) {
        int col = h * 128 + n * 8 + t * 2;
        __half2 hp0, hp1;
        hp0.x = __float2half(accO[n][0] * inv0);
        hp0.y = __float2half(accO[n][1] * inv0);
        hp1.x = __float2half(accO[n][2] * inv1);
        hp1.y = __float2half(accO[n][3] * inv1);
        *(__half2*)&Oh[r0*2048 + col] = hp0;
        *(__half2*)&Oh[r1*2048 + col] = hp1;
    }
}

// ---------------- transpose + fp16 cast: W[K,N] -> Th[N,K] ------------------
__global__ __launch_bounds__(256)
void transpose_half(const float* __restrict__ W, int K, int N,
                    __half* __restrict__ Th)
{
    __shared__ float tile[32][33];
    const int tx = threadIdx.x, ty = threadIdx.y;
    const int n0 = blockIdx.x * 32, k0 = blockIdx.y * 32;
    #pragma unroll
    for (int i = 0; i < 4; i++)
        tile[ty + 8*i][tx] = W[(size_t)(k0 + ty + 8*i) * N + n0 + tx];
    __syncthreads();
    #pragma unroll
    for (int i = 0; i < 4; i++) {
        float v = tile[tx][ty + 8*i];
        Th[(size_t)(n0 + ty + 8*i) * K + k0 + tx] = __float2half(v);
    }
}

// ---------------- qk prep: qkv fp32 -> Q(scaled) fp16, K fp16 ---------------
__global__ __launch_bounds__(256)
void qk_prep(const float* __restrict__ qkv,
             __half* __restrict__ qh, __half* __restrict__ kh)
{
    const float scale = 0.088388347648318447f;
    size_t e = ((size_t)blockIdx.x * 256 + threadIdx.x) * 4;
    int row = (int)(e >> 12);
    int col = (int)(e & 4095);
    float4 v = *(const float4*)&qkv[(size_t)row * 6144 + col];
    __half hb[4];
    if (col < 2048) {
        hb[0] = __float2half(v.x*scale); hb[1] = __float2half(v.y*scale);
        hb[2] = __float2half(v.z*scale); hb[3] = __float2half(v.w*scale);
        *(uint2*)&qh[(size_t)row*2048 + col] = *(uint2*)hb;
    } else {
        hb[0] = __float2half(v.x); hb[1] = __float2half(v.y);
        hb[2] = __float2half(v.z); hb[3] = __float2half(v.w);
        *(uint2*)&kh[(size_t)row*2048 + col - 2048] = *(uint2*)hb;
    }
}

// ---------------- v prep: transpose V per (b,h) -> [dim][keys] fp16 ---------
__global__ __launch_bounds__(256)
void v_prep(const float* __restrict__ qkv, __half* __restrict__ vth)
{
    __shared__ float tile[32][33];
    const int tx = threadIdx.x, ty = threadIdx.y;
    const int z = blockIdx.z, b = z >> 4, h = z & 15;
    const int key0 = blockIdx.x * 32, d0 = blockIdx.y * 32;
    #pragma unroll
    for (int i = 0; i < 4; i++) {
        int key = key0 + ty + 8*i;
        tile[ty + 8*i][tx] = qkv[(size_t)(b*2048 + key)*6144 + 4096 + h*128 + d0 + tx];
    }
    __syncthreads();
    #pragma unroll
    for (int i = 0; i < 4; i++) {
        int d = d0 + ty + 8*i;
        float v = tile[tx][ty + 8*i];
        vth[((size_t)z*128 + d)*2048 + key0 + tx] = __float2half(v);
    }
}

// ---------------- LayerNorm: out = LN(A [+ Ad]) * g + b ; + fp16 cast -------
__global__ __launch_bounds__(256)
void ln_kernel(const float* __restrict__ A, const float* __restrict__ Ad,
               const float* __restrict__ g, const float* __restrict__ bb,
               float* __restrict__ out, __half* __restrict__ oh)
{
    const int row = blockIdx.x, t = threadIdx.x;
    const float* a = A + (size_t)row * D_;
    float4 v[2];
    float s = 0.f, ss = 0.f;
    #pragma unroll
    for (int i = 0; i < 2; i++) {
        int idx = (i*256 + t) * 4;
        float4 x = *(const float4*)&a[idx];
        if (Ad) {
            float4 y = *(const float4*)&Ad[(size_t)row*D_ + idx];
            x.x += y.x; x.y += y.y; x.z += y.z; x.w += y.w;
        }
        v[i] = x;
        s  += x.x + x.y + x.z + x.w;
        ss += x.x*x.x + x.y*x.y + x.z*x.z + x.w*x.w;
    }
    #pragma unroll
    for (int off = 16; off; off >>= 1) {
        s  += __shfl_xor_sync(0xffffffffu, s,  off);
        ss += __shfl_xor_sync(0xffffffffu, ss, off);
    }
    __shared__ float sb[8], ssb[8];
    if ((t & 31) == 0) { sb[t>>5] = s; ssb[t>>5] = ss; }
    __syncthreads();
    float st = 0.f, sst = 0.f;
    #pragma unroll
    for (int i = 0; i < 8; i++) { st += sb[i]; sst += ssb[i]; }
    float mean = st * (1.f / D_);
    float var  = sst * (1.f / D_) - mean * mean;
    float rstd = rsqrtf(var + 1e-5f);
    #pragma unroll
    for (int i = 0; i < 2; i++) {
        int idx = (i*256 + t) * 4;
        float4 gg  = *(const float4*)&g[idx];
        float4 bbv = *(const float4*)&bb[idx];
        float4 x = v[i], o;
        o.x = (x.x - mean)*rstd*gg.x + bbv.x;
        o.y = (x.y - mean)*rstd*gg.y + bbv.y;
        o.z = (x.z - mean)*rstd*gg.z + bbv.z;
        o.w = (x.w - mean)*rstd*gg.w + bbv.w;
        if (out) *(float4*)&out[(size_t)row*D_ + idx] = o;
        __half hb[4];
        hb[0] = __float2half(o.x); hb[1] = __float2half(o.y);
        hb[2] = __float2half(o.z); hb[3] = __float2half(o.w);
        *(uint2*)&oh[(size_t)row*D_ + idx] = *(uint2*)hb;
    }
}

// ---------------- persona vector (2-stage, deterministic) -------------------
__global__ __launch_bounds__(256)
void pers_part(const float* __restrict__ pemb, const int* __restrict__ trait,
               const float* __restrict__ dw, float* __restrict__ part)
{
    int j = blockIdx.x * 256 + threadIdx.x;
    int seg = blockIdx.y;
    int tix = trait[0];
    const float* pe = pemb + (size_t)tix * D_;
    float acc = 0.f;
    int i0 = seg * 64;
    #pragma unroll 8
    for (int i = i0; i < i0 + 64; ++i)
        acc = fmaf(pe[i], dw[(size_t)(D_ + i) * D_ + j], acc);
    part[(size_t)seg * D_ + j] = acc;
}
__global__ __launch_bounds__(256)
void pers_reduce(const float* __restrict__ part, const float* __restrict__ db,
                 float* __restrict__ out)
{
    int j = blockIdx.x * 256 + threadIdx.x;
    float s = db[j];
    #pragma unroll
    for (int k = 0; k < 32; ++k) s += part[(size_t)k * D_ + j];
    out[j] = s;
}

// ---------------- launch ----------------------------------------------------
extern "C" void kernel_launch(void* const* d_in, const int* in_sizes, int n_in,
                              void* d_out, int out_size)
{
    const float* x     = (const float*)d_in[0];
    const int*   mask  = (const int*)  d_in[1];
    const int*   trait = (const int*)  d_in[2];
    const float* wq    = (const float*)d_in[3];
    const float* wk    = (const float*)d_in[4];
    const float* wv    = (const float*)d_in[5];
    const float* wo    = (const float*)d_in[6];
    const float* g1    = (const float*)d_in[7];
    const float* b1    = (const float*)d_in[8];
    const float* g2    = (const float*)d_in[9];
    const float* b2    = (const float*)d_in[10];
    const float* rw1   = (const float*)d_in[11];
    const float* rb1   = (const float*)d_in[12];
    const float* rw2   = (const float*)d_in[13];
    const float* rb2   = (const float*)d_in[14];
    const float* rg    = (const float*)d_in[15];
    const float* rb    = (const float*)d_in[16];
    const float* pemb  = (const float*)d_in[17];
    const float* dw    = (const float*)d_in[18];
    const float* db    = (const float*)d_in[19];
    const float* wgam  = (const float*)d_in[20];
    const float* wbet  = (const float*)d_in[21];
    const float* mw1   = (const float*)d_in[22];
    const float* mb1   = (const float*)d_in[23];
    const float* mw2   = (const float*)d_in[24];
    const float* mb2   = (const float*)d_in[25];
    float* out = (float*)d_out;

    static float *pqkv=0,*px2=0,*pr=0,*ph2=0,*ph3=0,*ppers=0,*pppart=0;
    static __half *pah=0,*pth=0,*pwh=0;
    static __half *pqsh=0,*pksh=0,*pvth=0;
    static bool inited = false;
    if (!inited) {
        cudaGetSymbolAddress((void**)&pqkv, g_qkv);
        cudaGetSymbolAddress((void**)&px2, g_x2);
        cudaGetSymbolAddress((void**)&pr,  g_r);
        cudaGetSymbolAddress((void**)&ph2, g_h2);
        cudaGetSymbolAddress((void**)&ph3, g_h3);
        cudaGetSymbolAddress((void**)&ppers, g_pers);
        cudaGetSymbolAddress((void**)&pppart, g_ppart);
        cudaGetSymbolAddress((void**)&pah, g_ah);
        cudaGetSymbolAddress((void**)&pth, g_th);
        cudaGetSymbolAddress((void**)&pwh, g_wh);
        cudaGetSymbolAddress((void**)&pqsh, g_qsh);
        cudaGetSymbolAddress((void**)&pksh, g_ksh);
        cudaGetSymbolAddress((void**)&pvth, g_vth);
        cudaFuncSetAttribute(tbgemm<false,false,false,false>, cudaFuncAttributeMaxDynamicSharedMemorySize, TG_SMEM);
        cudaFuncSetAttribute(tbgemm<false,false,true,false>,  cudaFuncAttributeMaxDynamicSharedMemorySize, TG_SMEM);
        cudaFuncSetAttribute(tbgemm<true,true,false,true>,    cudaFuncAttributeMaxDynamicSharedMemorySize, TG_SMEM);
        cudaFuncSetAttribute(tbgemm<false,true,false,false>,  cudaFuncAttributeMaxDynamicSharedMemorySize, TG_SMEM);
        cudaFuncSetAttribute(tbgemm<false,true,true,false>,   cudaFuncAttributeMaxDynamicSharedMemorySize, TG_SMEM);
        cudaFuncSetAttribute(flash_attn, cudaFuncAttributeMaxDynamicSharedMemorySize, FA_SMEM);
        inited = true;
    }

    const dim3 blk(256);
    const dim3 blk512(512);
    const dim3 tb(32, 8);

    // ---- weight prep (fp16 single-level) ----
    transpose_half<<<dim3(64, 64),  tb>>>(wq,  2048, 2048, pwh+OWQ);
    transpose_half<<<dim3(64, 64),  tb>>>(wk,  2048, 2048, pwh+OWK);
    transpose_half<<<dim3(64, 64),  tb>>>(wv,  2048, 2048, pwh+OWV);
    transpose_half<<<dim3(64, 64),  tb>>>(wo,  2048, 2048, pwh+OWO);
    transpose_half<<<dim3(128, 64), tb>>>(rw1, 2048, 4096, pwh+ORW1);
    transpose_half<<<dim3(64, 128), tb>>>(rw2, 4096, 2048, pwh+ORW2);
    transpose_half<<<dim3(64, 64),  tb>>>(dw,  2048, 2048, pwh+ODW);
    transpose_half<<<dim3(256, 64), tb>>>(mw1, 2048, 8192, pwh+OMW1);
    transpose_half<<<dim3(64, 256), tb>>>(mw2, 8192, 2048, pwh+OMW2);
    pers_part<<<dim3(D_/256, 32), blk>>>(pemb, trait, dw, pppart);
    pers_reduce<<<D_/256, blk>>>(pppart, db, ppers);

    // 1) h = LN1(x) -> fp16
    ln_kernel<<<M_, blk>>>(x, nullptr, g1, b1, nullptr, pah);
    // 2) qkv = h @ [wq|wk|wv]
    tbgemm<false,false,false,false><<<dim3(24,32), blk512, TG_SMEM>>>(
        pah, pwh+OWQ, nullptr,nullptr, pqkv,nullptr, M_, 3*D_, D_);
    // 3) attention prep (fp16)
    qk_prep<<<16384, blk>>>(pqkv, pqsh, pksh);
    v_prep<<<dim3(64, 4, 32), tb>>>(pqkv, pvth);
    // 4) fused flash attention -> pah (fp16)
    flash_attn<<<dim3(16, 32), blk, FA_SMEM>>>(
        pqsh, pksh, pvth, mask, pah);
    // 5) x2 = x + attn_out @ wo
    tbgemm<false,false,true,false><<<dim3(8,32), blk512, TG_SMEM>>>(
        pah, pwh+OWO, nullptr,x, px2,nullptr, M_, D_, D_);
    // 6) h2 = LN2(x2)
    ln_kernel<<<M_, blk>>>(px2, nullptr, g2, b2, ph2, pah);
    // 7) t = gelu(h2 @ rw1 + rb1)
    tbgemm<true,true,false,true><<<dim3(16,32), blk512, TG_SMEM>>>(
        pah, pwh+ORW1, rb1,nullptr, nullptr,pth, M_, 2*D_, D_);
    // 8) r = t @ rw2 + rb2
    tbgemm<false,true,false,false><<<dim3(8,32), blk512, TG_SMEM>>>(
        pth, pwh+ORW2, rb2,nullptr, pr,nullptr, M_, D_, 2*D_);
    // 9) h3 = LN(h2 + r)
    ln_kernel<<<M_, blk>>>(ph2, pr, rg, rb, ph3, pah);
    // 10) dec = h3 @ dw[:D] + pers
    tbgemm<false,true,false,false><<<dim3(8,32), blk512, TG_SMEM>>>(
        pah, pwh+ODW, ppers,nullptr, pqkv,nullptr, M_, D_, D_);
    // 11) h4 = LN(h3 + dec)
    ln_kernel<<<M_, blk>>>(ph3, pqkv, wgam, wbet, nullptr, pah);
    // 12) t = gelu(h4 @ mw1 + mb1)
    tbgemm<true,true,false,true><<<dim3(32,32), blk512, TG_SMEM>>>(
        pah, pwh+OMW1, mb1,nullptr, nullptr,pth, M_, 4*D_, D_);
    // 13) out = x2 + t @ mw2 + mb2
    tbgemm<false,true,true,false><<<dim3(8,32), blk512, TG_SMEM>>>(
        pth, pwh+OMW2, mb2,px2, out,nullptr, M_, D_, 4*D_);
}